// round 1
// baseline (speedup 1.0000x reference)
#include <cuda_runtime.h>
#include <cstdint>
#include <cstdio>

#define NROIS 1000
#define CCH   256
#define DFEAT (CCH * 49)   // 12544

// ---------------- scratch (no allocation allowed) ----------------
__device__ float g_x[NROIS * DFEAT];     // pooled features, row-major 1000 x 12544
__device__ float g_fc1[NROIS * 1024];
__device__ float g_fc2[NROIS * 1024];

// ---------------- ROI align + 2x2 max pool -----------------------
// One block per ROI, one thread per channel.
__global__ void roi_align_kernel(const float* __restrict__ f2, const float* __restrict__ f3,
                                 const float* __restrict__ f4, const float* __restrict__ f5,
                                 const float* __restrict__ rois, float* __restrict__ xout)
{
    const int r = blockIdx.x;
    const int c = threadIdx.x;

    __shared__ int   s_y0[14], s_y1[14], s_x0[14], s_x1[14];
    __shared__ float s_ly[14], s_lx[14];

    const float ry1 = rois[r * 4 + 0];
    const float rx1 = rois[r * 4 + 1];
    const float ry2 = rois[r * 4 + 2];
    const float rx2 = rois[r * 4 + 3];

    const float h = ry2 - ry1 + 1.0f;
    const float w = rx2 - rx1 + 1.0f;
    float lv = floorf(logf(sqrtf(h * w) / 224.0f) / 0.693147f + 4.0f);
    lv = fminf(fmaxf(lv, 2.0f), 5.0f);
    const int lvl = (int)lv;

    int H; const float* f;
    if (lvl == 2)      { H = 256; f = f2; }
    else if (lvl == 3) { H = 128; f = f3; }
    else if (lvl == 4) { H = 64;  f = f4; }
    else               { H = 32;  f = f5; }

    const float fm = (float)(H - 1);
    const float gy1 = ry1 * fm / 1023.0f;
    const float gx1 = rx1 * fm / 1023.0f;
    const float gy2 = ry2 * fm / 1023.0f;
    const float gx2 = rx2 * fm / 1023.0f;
    const float hs = (gy2 - gy1) / 14.0f;
    const float ws = (gx2 - gx1) / 14.0f;

    if (c < 14) {
        const float cy = ((float)c + 0.5f) * hs + gy1;
        const float fl = floorf(cy);
        s_y0[c] = (int)fl;
        s_y1[c] = (int)ceilf(cy);
        s_ly[c] = cy - fl;
    } else if (c < 28) {
        const int j = c - 14;
        const float cx = ((float)j + 0.5f) * ws + gx1;
        const float fl = floorf(cx);
        s_x0[j] = (int)fl;
        s_x1[j] = (int)ceilf(cx);
        s_lx[j] = cx - fl;
    }
    __syncthreads();

    const float* __restrict__ fc = f + (size_t)c * H * H;
    float* __restrict__ out = xout + (size_t)r * DFEAT + c * 49;

    for (int py = 0; py < 7; ++py) {
        for (int px = 0; px < 7; ++px) {
            float m = -3.0e38f;
            #pragma unroll
            for (int a = 0; a < 2; ++a) {
                const int sy = 2 * py + a;
                const int y0 = s_y0[sy];
                const int y1i = s_y1[sy];
                const float ly = s_ly[sy];
                #pragma unroll
                for (int b = 0; b < 2; ++b) {
                    const int sx = 2 * px + b;
                    const int x0 = s_x0[sx];
                    const int x1i = s_x1[sx];
                    const float lx = s_lx[sx];
                    const float v00 = fc[y0  * H + x0];
                    const float v10 = fc[y1i * H + x0];
                    const float v01 = fc[y0  * H + x1i];
                    const float v11 = fc[y1i * H + x1i];
                    const float v = v00 * (1.0f - ly) * (1.0f - lx)
                                  + v10 * ly         * (1.0f - lx)
                                  + v01 * (1.0f - ly) * lx
                                  + v11 * ly          * lx;
                    m = fmaxf(m, v);
                }
            }
            out[py * 7 + px] = m;
        }
    }
}

// ---------------- fp32 GEMM with fma.rn.f32x2 ---------------------
// C[M,N] = A[M,K] @ B[K,N] + bias (+ optional relu)
// 128x64 tile, BK=16, 128 threads, 8x8 microtile per thread (packed f32x2).
#define BM 128
#define BN 64
#define BK 16

__device__ __forceinline__ unsigned long long pk2(float lo, float hi) {
    unsigned long long r;
    asm("mov.b64 %0, {%1, %2};" : "=l"(r) : "f"(lo), "f"(hi));
    return r;
}
__device__ __forceinline__ void fma2(unsigned long long& acc, unsigned long long a, unsigned long long b) {
    asm("fma.rn.f32x2 %0, %1, %2, %0;" : "+l"(acc) : "l"(a), "l"(b));
}
__device__ __forceinline__ float2 upk(unsigned long long v) {
    float2 r;
    asm("mov.b64 {%0, %1}, %2;" : "=f"(r.x), "=f"(r.y) : "l"(v));
    return r;
}

__global__ __launch_bounds__(128) void sgemm_bias_act(
    const float* __restrict__ A, const float* __restrict__ B,
    const float* __restrict__ bias, float* __restrict__ C,
    int M, int N, int K, int relu)
{
    __shared__ float As[2][BK][BM];   // 16 KB
    __shared__ float Bs[2][BK][BN];   // 8 KB

    const int tid = threadIdx.x;
    const int tm = tid & 15;   // 16 row-groups
    const int tn = tid >> 4;   // 8 col-groups
    const int rowBase = blockIdx.x * BM;
    const int colBase = blockIdx.y * BN;

    const int arow = rowBase + tid;
    const bool aok = (arow < M);
    const float* __restrict__ Ap = A + (size_t)arow * K;

    unsigned long long acc[4][8];
    #pragma unroll
    for (int i = 0; i < 4; ++i)
        #pragma unroll
        for (int j = 0; j < 8; ++j) acc[i][j] = 0ULL;

    float4 aReg[4];
    float  bReg[8];

    auto loadG = [&](int kt) {
        const int kb = kt * BK;
        #pragma unroll
        for (int i = 0; i < 4; ++i) {
            if (aok) aReg[i] = *reinterpret_cast<const float4*>(Ap + kb + i * 4);
            else     aReg[i] = make_float4(0.f, 0.f, 0.f, 0.f);
        }
        #pragma unroll
        for (int i = 0; i < 8; ++i) {
            const int idx = i * 128 + tid;
            const int k = idx >> 6;       // 0..15
            const int n = idx & 63;       // 0..63
            const int gn = colBase + n;
            bReg[i] = (gn < N) ? B[(size_t)(kb + k) * N + gn] : 0.0f;
        }
    };
    auto storeS = [&](int bufw) {
        #pragma unroll
        for (int i = 0; i < 4; ++i) {
            As[bufw][i * 4 + 0][tid] = aReg[i].x;
            As[bufw][i * 4 + 1][tid] = aReg[i].y;
            As[bufw][i * 4 + 2][tid] = aReg[i].z;
            As[bufw][i * 4 + 3][tid] = aReg[i].w;
        }
        #pragma unroll
        for (int i = 0; i < 8; ++i) {
            const int idx = i * 128 + tid;
            Bs[bufw][idx >> 6][idx & 63] = bReg[i];
        }
    };

    const int nt = K / BK;   // K is always a multiple of 16 here
    loadG(0);
    storeS(0);
    __syncthreads();

    int buf = 0;
    for (int kt = 0; kt < nt; ++kt) {
        const bool hasNext = (kt + 1 < nt);
        if (hasNext) loadG(kt + 1);

        #pragma unroll
        for (int kk = 0; kk < BK; ++kk) {
            const float4 a0 = *reinterpret_cast<const float4*>(&As[buf][kk][tm * 8]);
            const float4 a1 = *reinterpret_cast<const float4*>(&As[buf][kk][tm * 8 + 4]);
            const float4 b0 = *reinterpret_cast<const float4*>(&Bs[buf][kk][tn * 8]);
            const float4 b1 = *reinterpret_cast<const float4*>(&Bs[buf][kk][tn * 8 + 4]);
            unsigned long long av[4];
            av[0] = pk2(a0.x, a0.y);
            av[1] = pk2(a0.z, a0.w);
            av[2] = pk2(a1.x, a1.y);
            av[3] = pk2(a1.z, a1.w);
            const float bv[8] = {b0.x, b0.y, b0.z, b0.w, b1.x, b1.y, b1.z, b1.w};
            #pragma unroll
            for (int j = 0; j < 8; ++j) {
                const unsigned long long bb = pk2(bv[j], bv[j]);
                #pragma unroll
                for (int i = 0; i < 4; ++i) fma2(acc[i][j], av[i], bb);
            }
        }

        if (hasNext) storeS(buf ^ 1);
        __syncthreads();
        buf ^= 1;
    }

    // epilogue: bias, optional relu, guarded stores
    #pragma unroll
    for (int j = 0; j < 8; ++j) {
        const int col = colBase + tn * 8 + j;
        if (col >= N) continue;
        const float bsv = bias[col];
        #pragma unroll
        for (int i = 0; i < 4; ++i) {
            const float2 v = upk(acc[i][j]);
            const int r0 = rowBase + tm * 8 + 2 * i;
            float v0 = v.x + bsv;
            float v1 = v.y + bsv;
            if (relu) { v0 = fmaxf(v0, 0.0f); v1 = fmaxf(v1, 0.0f); }
            if (r0 < M)     C[(size_t)r0 * N + col]       = v0;
            if (r0 + 1 < M) C[(size_t)(r0 + 1) * N + col] = v1;
        }
    }
}

// ---------------- launch ------------------------------------------
extern "C" void kernel_launch(void* const* d_in, const int* in_sizes, int n_in,
                              void* d_out, int out_size)
{
    const float* f2   = (const float*)d_in[0];
    const float* f3   = (const float*)d_in[1];
    const float* f4   = (const float*)d_in[2];
    const float* f5   = (const float*)d_in[3];
    const float* rois = (const float*)d_in[4];
    // d_in[5] = img_size (fixed 1024x1024, folded into constants)
    const float* W1   = (const float*)d_in[6];
    const float* b1   = (const float*)d_in[7];
    const float* W2   = (const float*)d_in[8];
    const float* b2   = (const float*)d_in[9];
    const float* Wloc = (const float*)d_in[10];
    const float* bloc = (const float*)d_in[11];
    const float* Wsc  = (const float*)d_in[12];
    const float* bsc  = (const float*)d_in[13];

    float* out     = (float*)d_out;
    float* out_loc = out;                              // 1000 x 324
    float* out_sc  = out + (size_t)NROIS * 324;        // 1000 x 81

    float *xp, *fc1p, *fc2p;
    cudaGetSymbolAddress((void**)&xp,   g_x);
    cudaGetSymbolAddress((void**)&fc1p, g_fc1);
    cudaGetSymbolAddress((void**)&fc2p, g_fc2);

    roi_align_kernel<<<NROIS, 256>>>(f2, f3, f4, f5, rois, xp);

    dim3 g1((NROIS + BM - 1) / BM, 1024 / BN);                 // 8 x 16
    sgemm_bias_act<<<g1, 128>>>(xp,   W1, b1, fc1p, NROIS, 1024, DFEAT, 1);
    sgemm_bias_act<<<g1, 128>>>(fc1p, W2, b2, fc2p, NROIS, 1024, 1024, 1);

    dim3 g3((NROIS + BM - 1) / BM, (324 + BN - 1) / BN);       // 8 x 6
    sgemm_bias_act<<<g3, 128>>>(fc2p, Wloc, bloc, out_loc, NROIS, 324, 1024, 0);

    dim3 g4((NROIS + BM - 1) / BM, (81 + BN - 1) / BN);        // 8 x 2
    sgemm_bias_act<<<g4, 128>>>(fc2p, Wsc, bsc, out_sc, NROIS, 81, 1024, 0);
}

// round 3
// speedup vs baseline: 2.3207x; 2.3207x over previous
#include <cuda_runtime.h>
#include <cuda_bf16.h>
#include <cstdint>

typedef __nv_bfloat16 bf16;

#define NROIS 1000
#define DFEAT 12544
#define MPAD  1024

// ---------------- persistent scratch (zero-init; padded rows never written) ----
__device__ bf16 g_xh [MPAD * DFEAT];
__device__ bf16 g_xl [MPAD * DFEAT];
__device__ bf16 g_w1h[1024 * DFEAT];
__device__ bf16 g_w1l[1024 * DFEAT];
__device__ bf16 g_w2h[1024 * 1024];
__device__ bf16 g_w2l[1024 * 1024];
__device__ bf16 g_whh[512 * 1024];
__device__ bf16 g_whl[512 * 1024];
__device__ bf16 g_f1h[MPAD * 1024];
__device__ bf16 g_f1l[MPAD * 1024];
__device__ bf16 g_f2h[MPAD * 1024];
__device__ bf16 g_f2l[MPAD * 1024];
__device__ float g_bcomb[512];

// ---------------- helpers ------------------------------------------------------
__device__ __forceinline__ uint32_t s2u(const void* p) {
    uint32_t a;
    asm("{ .reg .u64 t; cvta.to.shared.u64 t, %1; cvt.u32.u64 %0, t; }" : "=r"(a) : "l"(p));
    return a;
}
__device__ __forceinline__ void cp16(uint32_t s, const void* g) {
    asm volatile("cp.async.cg.shared.global [%0], [%1], 16;" :: "r"(s), "l"(g) : "memory");
}
__device__ __forceinline__ void cp_commit() {
    asm volatile("cp.async.commit_group;" ::: "memory");
}
__device__ __forceinline__ void cp_wait0() {
    asm volatile("cp.async.wait_group 0;" ::: "memory");
}
__device__ __forceinline__ void ldsm4(uint32_t* r, uint32_t a) {
    asm volatile("ldmatrix.sync.aligned.m8n8.x4.shared.b16 {%0,%1,%2,%3}, [%4];"
                 : "=r"(r[0]), "=r"(r[1]), "=r"(r[2]), "=r"(r[3]) : "r"(a));
}
__device__ __forceinline__ void mma16816(float* c, const uint32_t* a, const uint32_t* b) {
    asm volatile(
        "mma.sync.aligned.m16n8k16.row.col.f32.bf16.bf16.f32 "
        "{%0,%1,%2,%3}, {%4,%5,%6,%7}, {%8,%9}, {%0,%1,%2,%3};"
        : "+f"(c[0]), "+f"(c[1]), "+f"(c[2]), "+f"(c[3])
        : "r"(a[0]), "r"(a[1]), "r"(a[2]), "r"(a[3]), "r"(b[0]), "r"(b[1]));
}
__device__ __forceinline__ void split2(float v, bf16& h, bf16& l) {
    h = __float2bfloat16(v);
    l = __float2bfloat16(v - __bfloat162float(h));
}

// ---------------- ROI align + 2x2 max pool + hi/lo split ----------------------
__global__ void roi_align_kernel(const float* __restrict__ f2, const float* __restrict__ f3,
                                 const float* __restrict__ f4, const float* __restrict__ f5,
                                 const float* __restrict__ rois,
                                 bf16* __restrict__ xh, bf16* __restrict__ xl)
{
    const int r = blockIdx.x;
    const int c = threadIdx.x;

    __shared__ int   s_y0[14], s_y1[14], s_x0[14], s_x1[14];
    __shared__ float s_ly[14], s_lx[14];

    const float ry1 = rois[r * 4 + 0];
    const float rx1 = rois[r * 4 + 1];
    const float ry2 = rois[r * 4 + 2];
    const float rx2 = rois[r * 4 + 3];

    const float h = ry2 - ry1 + 1.0f;
    const float w = rx2 - rx1 + 1.0f;
    float lv = floorf(logf(sqrtf(h * w) / 224.0f) / 0.693147f + 4.0f);
    lv = fminf(fmaxf(lv, 2.0f), 5.0f);
    const int lvl = (int)lv;

    int H; const float* f;
    if (lvl == 2)      { H = 256; f = f2; }
    else if (lvl == 3) { H = 128; f = f3; }
    else if (lvl == 4) { H = 64;  f = f4; }
    else               { H = 32;  f = f5; }

    const float fm = (float)(H - 1);
    const float gy1 = ry1 * fm / 1023.0f;
    const float gx1 = rx1 * fm / 1023.0f;
    const float gy2 = ry2 * fm / 1023.0f;
    const float gx2 = rx2 * fm / 1023.0f;
    const float hs = (gy2 - gy1) / 14.0f;
    const float ws = (gx2 - gx1) / 14.0f;

    if (c < 14) {
        const float cy = ((float)c + 0.5f) * hs + gy1;
        const float fl = floorf(cy);
        s_y0[c] = (int)fl;
        s_y1[c] = (int)ceilf(cy);
        s_ly[c] = cy - fl;
    } else if (c < 28) {
        const int j = c - 14;
        const float cx = ((float)j + 0.5f) * ws + gx1;
        const float fl = floorf(cx);
        s_x0[j] = (int)fl;
        s_x1[j] = (int)ceilf(cx);
        s_lx[j] = cx - fl;
    }
    __syncthreads();

    const float* __restrict__ fc = f + (size_t)c * H * H;
    const size_t ob = (size_t)r * DFEAT + c * 49;

    for (int py = 0; py < 7; ++py) {
        for (int px = 0; px < 7; ++px) {
            float m = -3.0e38f;
            #pragma unroll
            for (int a = 0; a < 2; ++a) {
                const int sy = 2 * py + a;
                const int y0 = s_y0[sy];
                const int y1i = s_y1[sy];
                const float ly = s_ly[sy];
                #pragma unroll
                for (int b = 0; b < 2; ++b) {
                    const int sx = 2 * px + b;
                    const int x0 = s_x0[sx];
                    const int x1i = s_x1[sx];
                    const float lx = s_lx[sx];
                    const float v00 = fc[y0  * H + x0];
                    const float v10 = fc[y1i * H + x0];
                    const float v01 = fc[y0  * H + x1i];
                    const float v11 = fc[y1i * H + x1i];
                    const float v = v00 * (1.0f - ly) * (1.0f - lx)
                                  + v10 * ly          * (1.0f - lx)
                                  + v01 * (1.0f - ly) * lx
                                  + v11 * ly          * lx;
                    m = fmaxf(m, v);
                }
            }
            bf16 hh, ll;
            split2(m, hh, ll);
            xh[ob + py * 7 + px] = hh;
            xl[ob + py * 7 + px] = ll;
        }
    }
}

// ---------------- weight transpose + hi/lo split ------------------------------
__global__ void tsplit(const float* __restrict__ W, int K, int N,
                       bf16* __restrict__ oH, bf16* __restrict__ oL)
{
    __shared__ float t[32][33];
    const int k0 = blockIdx.x * 32, n0 = blockIdx.y * 32;
    const int tx = threadIdx.x, ty = threadIdx.y;  // 32 x 8
    #pragma unroll
    for (int r = 0; r < 4; ++r) {
        const int k = k0 + ty + r * 8;
        t[ty + r * 8][tx] = W[(size_t)k * N + n0 + tx];
    }
    __syncthreads();
    #pragma unroll
    for (int r = 0; r < 4; ++r) {
        const int n = n0 + ty + r * 8;
        const float v = t[tx][ty + r * 8];
        bf16 h, l;
        split2(v, h, l);
        oH[(size_t)n * K + k0 + tx] = h;
        oL[(size_t)n * K + k0 + tx] = l;
    }
}

__global__ void tsplit_heads(const float* __restrict__ Wloc, const float* __restrict__ Wsc,
                             bf16* __restrict__ oH, bf16* __restrict__ oL)
{
    __shared__ float t[32][33];
    const int K = 1024;
    const int k0 = blockIdx.x * 32, n0 = blockIdx.y * 32;
    const int tx = threadIdx.x, ty = threadIdx.y;
    #pragma unroll
    for (int r = 0; r < 4; ++r) {
        const int k = k0 + ty + r * 8;
        const int n = n0 + tx;
        float v = 0.0f;
        if (n < 324)      v = Wloc[(size_t)k * 324 + n];
        else if (n < 405) v = Wsc[(size_t)k * 81 + (n - 324)];
        t[ty + r * 8][tx] = v;
    }
    __syncthreads();
    #pragma unroll
    for (int r = 0; r < 4; ++r) {
        const int n = n0 + ty + r * 8;
        if (n < 448) {
            const float v = t[tx][ty + r * 8];
            bf16 h, l;
            split2(v, h, l);
            oH[(size_t)n * K + k0 + tx] = h;
            oL[(size_t)n * K + k0 + tx] = l;
        }
    }
}

__global__ void bias_comb(const float* __restrict__ bloc, const float* __restrict__ bsc,
                          float* __restrict__ o)
{
    const int i = threadIdx.x;
    if (i < 512) o[i] = (i < 324) ? bloc[i] : ((i < 405) ? bsc[i - 324] : 0.0f);
}

// ---------------- HMMA GEMM: C[128][64] tile = A @ B^T, 3-term bf16 split -----
// A: [M][K] K-major bf16 hi/lo. B: [N][K] K-major bf16 hi/lo.
// SMEM per buffer (24 KB): Ah[128][32] @0, Al @8192, Bh[64][32] @16384, Bl @20480.
// 64B rows, chunk swizzle: chunk ^= (row>>1)&3  (conflict-free for cp.async + ldmatrix)
#define GBK 32
#define BUF_SZ 24576
#define GEMM_SMEM (2 * BUF_SZ)

__global__ __launch_bounds__(256) void gemm_mma(
    const bf16* __restrict__ Ah, const bf16* __restrict__ Al,
    const bf16* __restrict__ Bh, const bf16* __restrict__ Bl,
    const float* __restrict__ bias, int K, int mode,
    bf16* __restrict__ outH, bf16* __restrict__ outL,
    float* __restrict__ outLoc, float* __restrict__ outSc, int outW)
{
    extern __shared__ char smem[];
    const uint32_t smU = s2u(smem);
    const int t   = threadIdx.x;
    const int l   = t & 31;
    const int wid = t >> 5;
    const int wm  = (wid & 1) * 64;   // warp M offset (2 warps over 128)
    const int wn  = (wid >> 1) * 16;  // warp N offset (4 warps over 64)
    const int rowBase = blockIdx.x * 128;
    const int colBase = blockIdx.y * 64;
    const size_t K2 = (size_t)K * 2;   // bytes per row

    // cp.async geometry
    const int caRow = t >> 2;          // 0..63
    const int caC   = t & 3;
    const uint32_t sSel  = (caRow >> 1) & 3;
    const uint32_t sOff0 = caRow * 64 + ((caC ^ sSel) << 4);
    const uint32_t sOff1 = sOff0 + 4096;   // rows 64..127 (A only)

    const char* pAh  = (const char*)(Ah + (size_t)(rowBase + caRow) * K) + caC * 16;
    const char* pAh2 = pAh + 64 * K2;
    const char* pAl  = (const char*)(Al + (size_t)(rowBase + caRow) * K) + caC * 16;
    const char* pAl2 = pAl + 64 * K2;
    const char* pBh  = (const char*)(Bh + (size_t)(colBase + caRow) * K) + caC * 16;
    const char* pBl  = (const char*)(Bl + (size_t)(colBase + caRow) * K) + caC * 16;

    float acc[4][2][4];
    #pragma unroll
    for (int mb = 0; mb < 4; ++mb)
        #pragma unroll
        for (int nb = 0; nb < 2; ++nb)
            #pragma unroll
            for (int i = 0; i < 4; ++i) acc[mb][nb][i] = 0.0f;

    // ldmatrix geometry
    const uint32_t aRowAddr = (wm + (l & 15)) * 64;
    const uint32_t aSel = ((l & 15) >> 1) & 3;
    const uint32_t aCk0 = (l >> 4);                     // 0/1
    const uint32_t bRow = wn + ((l >> 4) << 3) + (l & 7);
    const uint32_t bRowAddr = bRow * 64;
    const uint32_t bSel = ((l & 7) >> 1) & 3;
    const uint32_t bCk0 = (l >> 3) & 1;

    const int nt = K / GBK;

    auto issue = [&](int kt) {
        const uint32_t bu = smU + (kt & 1) * BUF_SZ;
        const size_t kb2 = (size_t)kt * 64;
        cp16(bu + 0     + sOff0, pAh  + kb2);
        cp16(bu + 0     + sOff1, pAh2 + kb2);
        cp16(bu + 8192  + sOff0, pAl  + kb2);
        cp16(bu + 8192  + sOff1, pAl2 + kb2);
        cp16(bu + 16384 + sOff0, pBh  + kb2);
        cp16(bu + 20480 + sOff0, pBl  + kb2);
        cp_commit();
    };

    issue(0);

    for (int kt = 0; kt < nt; ++kt) {
        cp_wait0();
        __syncthreads();
        if (kt + 1 < nt) issue(kt + 1);

        const uint32_t bu = smU + (kt & 1) * BUF_SZ;
        const uint32_t aB = bu + aRowAddr;
        const uint32_t bB = bu + 16384 + bRowAddr;

        #pragma unroll
        for (int ks = 0; ks < 2; ++ks) {
            const uint32_t aOff = (((aCk0 + 2 * ks) ^ aSel) << 4);
            const uint32_t bOff = (((bCk0 + 2 * ks) ^ bSel) << 4);

            uint32_t ah[4][4], al[4][4], bh[4], bl[4];
            #pragma unroll
            for (int mb = 0; mb < 4; ++mb) {
                ldsm4(ah[mb], aB + mb * 1024 + aOff);
                ldsm4(al[mb], aB + 8192 + mb * 1024 + aOff);
            }
            ldsm4(bh, bB + bOff);
            ldsm4(bl, bB + 4096 + bOff);

            #pragma unroll
            for (int mb = 0; mb < 4; ++mb)
                #pragma unroll
                for (int nb = 0; nb < 2; ++nb)
                    mma16816(acc[mb][nb], ah[mb], &bh[2 * nb]);
            #pragma unroll
            for (int mb = 0; mb < 4; ++mb)
                #pragma unroll
                for (int nb = 0; nb < 2; ++nb)
                    mma16816(acc[mb][nb], al[mb], &bh[2 * nb]);
            #pragma unroll
            for (int mb = 0; mb < 4; ++mb)
                #pragma unroll
                for (int nb = 0; nb < 2; ++nb)
                    mma16816(acc[mb][nb], ah[mb], &bl[2 * nb]);
        }
    }

    // epilogue
    const int q = l >> 2, idx = l & 3;
    #pragma unroll
    for (int mb = 0; mb < 4; ++mb) {
        const int r0 = rowBase + wm + mb * 16 + q;
        const int r1 = r0 + 8;
        #pragma unroll
        for (int nb = 0; nb < 2; ++nb) {
            const int col = colBase + wn + nb * 8 + 2 * idx;
            if (mode == 0) {
                const float bs0 = bias[col], bs1 = bias[col + 1];
                float v00 = fmaxf(acc[mb][nb][0] + bs0, 0.0f);
                float v01 = fmaxf(acc[mb][nb][1] + bs1, 0.0f);
                float v10 = fmaxf(acc[mb][nb][2] + bs0, 0.0f);
                float v11 = fmaxf(acc[mb][nb][3] + bs1, 0.0f);
                bf16 h00, l00, h01, l01, h10, l10, h11, l11;
                split2(v00, h00, l00); split2(v01, h01, l01);
                split2(v10, h10, l10); split2(v11, h11, l11);
                __nv_bfloat162 p;
                p.x = h00; p.y = h01;
                *(__nv_bfloat162*)(outH + (size_t)r0 * outW + col) = p;
                p.x = l00; p.y = l01;
                *(__nv_bfloat162*)(outL + (size_t)r0 * outW + col) = p;
                p.x = h10; p.y = h11;
                *(__nv_bfloat162*)(outH + (size_t)r1 * outW + col) = p;
                p.x = l10; p.y = l11;
                *(__nv_bfloat162*)(outL + (size_t)r1 * outW + col) = p;
            } else {
                #pragma unroll
                for (int e = 0; e < 4; ++e) {
                    const int rr = (e < 2) ? r0 : r1;
                    const int cc = col + (e & 1);
                    if (rr < NROIS) {
                        const float v = acc[mb][nb][e] + bias[cc];
                        if (cc < 324)      outLoc[(size_t)rr * 324 + cc] = v;
                        else if (cc < 405) outSc[(size_t)rr * 81 + (cc - 324)] = v;
                    }
                }
            }
        }
    }
}

// ---------------- launch ------------------------------------------------------
extern "C" void kernel_launch(void* const* d_in, const int* in_sizes, int n_in,
                              void* d_out, int out_size)
{
    const float* f2   = (const float*)d_in[0];
    const float* f3   = (const float*)d_in[1];
    const float* f4   = (const float*)d_in[2];
    const float* f5   = (const float*)d_in[3];
    const float* rois = (const float*)d_in[4];
    const float* W1   = (const float*)d_in[6];
    const float* b1   = (const float*)d_in[7];
    const float* W2   = (const float*)d_in[8];
    const float* b2   = (const float*)d_in[9];
    const float* Wloc = (const float*)d_in[10];
    const float* bloc = (const float*)d_in[11];
    const float* Wsc  = (const float*)d_in[12];
    const float* bsc  = (const float*)d_in[13];

    float* out_loc = (float*)d_out;                       // 1000 x 324
    float* out_sc  = (float*)d_out + (size_t)NROIS * 324; // 1000 x 81

    bf16 *xh, *xl, *w1h, *w1l, *w2h, *w2l, *whh, *whl, *f1h, *f1l, *f2h_, *f2l_;
    float* bcomb;
    cudaGetSymbolAddress((void**)&xh,   g_xh);
    cudaGetSymbolAddress((void**)&xl,   g_xl);
    cudaGetSymbolAddress((void**)&w1h,  g_w1h);
    cudaGetSymbolAddress((void**)&w1l,  g_w1l);
    cudaGetSymbolAddress((void**)&w2h,  g_w2h);
    cudaGetSymbolAddress((void**)&w2l,  g_w2l);
    cudaGetSymbolAddress((void**)&whh,  g_whh);
    cudaGetSymbolAddress((void**)&whl,  g_whl);
    cudaGetSymbolAddress((void**)&f1h,  g_f1h);
    cudaGetSymbolAddress((void**)&f1l,  g_f1l);
    cudaGetSymbolAddress((void**)&f2h_, g_f2h);
    cudaGetSymbolAddress((void**)&f2l_, g_f2l);
    cudaGetSymbolAddress((void**)&bcomb, g_bcomb);

    cudaFuncSetAttribute(gemm_mma, cudaFuncAttributeMaxDynamicSharedMemorySize, GEMM_SMEM);

    bias_comb<<<1, 512>>>(bloc, bsc, bcomb);
    tsplit<<<dim3(DFEAT / 32, 1024 / 32), dim3(32, 8)>>>(W1, DFEAT, 1024, w1h, w1l);
    tsplit<<<dim3(1024 / 32, 1024 / 32), dim3(32, 8)>>>(W2, 1024, 1024, w2h, w2l);
    tsplit_heads<<<dim3(1024 / 32, 14), dim3(32, 8)>>>(Wloc, Wsc, whh, whl);
    roi_align_kernel<<<NROIS, 256>>>(f2, f3, f4, f5, rois, xh, xl);

    gemm_mma<<<dim3(8, 16), 256, GEMM_SMEM>>>(xh, xl, w1h, w1l, b1, DFEAT, 0,
                                              f1h, f1l, nullptr, nullptr, 1024);
    gemm_mma<<<dim3(8, 16), 256, GEMM_SMEM>>>(f1h, f1l, w2h, w2l, b2, 1024, 0,
                                              f2h_, f2l_, nullptr, nullptr, 1024);
    gemm_mma<<<dim3(8, 7), 256, GEMM_SMEM>>>(f2h_, f2l_, whh, whl, bcomb, 1024, 1,
                                             nullptr, nullptr, out_loc, out_sc, 0);
}

// round 4
// speedup vs baseline: 5.0691x; 2.1843x over previous
#include <cuda_runtime.h>
#include <cuda_bf16.h>
#include <cstdint>

typedef __nv_bfloat16 bf16;

#define NROIS 1000
#define DFEAT 12544
#define MPAD  1024

// ---------------- persistent scratch (zero-init) -------------------------------
__device__ bf16 g_xh [MPAD * DFEAT];
__device__ bf16 g_xl [MPAD * DFEAT];
__device__ bf16 g_w1h[DFEAT * 1024];   // [K][N] layout now
__device__ bf16 g_w1l[DFEAT * 1024];
__device__ bf16 g_w2h[1024 * 1024];
__device__ bf16 g_w2l[1024 * 1024];
__device__ bf16 g_whh[1024 * 512];     // combined heads [K=1024][N=512 padded]
__device__ bf16 g_whl[1024 * 512];
__device__ bf16 g_f1h[MPAD * 1024];
__device__ bf16 g_f1l[MPAD * 1024];
__device__ bf16 g_f2h[MPAD * 1024];
__device__ bf16 g_f2l[MPAD * 1024];
__device__ float g_bcomb[512];
// transposed feature maps [H][W][C] fp32
__device__ float g_ft2[256 * 256 * 256];
__device__ float g_ft3[128 * 128 * 256];
__device__ float g_ft4[64 * 64 * 256];
__device__ float g_ft5[32 * 32 * 256];

// ---------------- helpers ------------------------------------------------------
__device__ __forceinline__ uint32_t s2u(const void* p) {
    uint32_t a;
    asm("{ .reg .u64 t; cvta.to.shared.u64 t, %1; cvt.u32.u64 %0, t; }" : "=r"(a) : "l"(p));
    return a;
}
__device__ __forceinline__ void cp16(uint32_t s, const void* g) {
    asm volatile("cp.async.cg.shared.global [%0], [%1], 16;" :: "r"(s), "l"(g) : "memory");
}
__device__ __forceinline__ void cp_commit() {
    asm volatile("cp.async.commit_group;" ::: "memory");
}
__device__ __forceinline__ void cp_wait1() {
    asm volatile("cp.async.wait_group 1;" ::: "memory");
}
__device__ __forceinline__ void ldsm4(uint32_t* r, uint32_t a) {
    asm volatile("ldmatrix.sync.aligned.m8n8.x4.shared.b16 {%0,%1,%2,%3}, [%4];"
                 : "=r"(r[0]), "=r"(r[1]), "=r"(r[2]), "=r"(r[3]) : "r"(a));
}
__device__ __forceinline__ void ldsm4t(uint32_t* r, uint32_t a) {
    asm volatile("ldmatrix.sync.aligned.m8n8.x4.trans.shared.b16 {%0,%1,%2,%3}, [%4];"
                 : "=r"(r[0]), "=r"(r[1]), "=r"(r[2]), "=r"(r[3]) : "r"(a));
}
__device__ __forceinline__ void mma16816(float* c, const uint32_t* a, const uint32_t* b) {
    asm volatile(
        "mma.sync.aligned.m16n8k16.row.col.f32.bf16.bf16.f32 "
        "{%0,%1,%2,%3}, {%4,%5,%6,%7}, {%8,%9}, {%0,%1,%2,%3};"
        : "+f"(c[0]), "+f"(c[1]), "+f"(c[2]), "+f"(c[3])
        : "r"(a[0]), "r"(a[1]), "r"(a[2]), "r"(a[3]), "r"(b[0]), "r"(b[1]));
}
__device__ __forceinline__ void split2(float v, bf16& h, bf16& l) {
    h = __float2bfloat16(v);
    l = __float2bfloat16(v - __bfloat162float(h));
}

// ---------------- feature transpose [C][H][W] -> [H][W][C] ---------------------
__global__ void ftrans(const float* __restrict__ f, float* __restrict__ ft, int H)
{
    __shared__ float t[32][33];
    const int W = H;
    const int w0 = blockIdx.x * 32, h = blockIdx.y, c0 = blockIdx.z * 32;
    const int tx = threadIdx.x, ty = threadIdx.y;
    #pragma unroll
    for (int r = 0; r < 4; ++r) {
        const int c = c0 + ty + r * 8;
        t[ty + r * 8][tx] = f[((size_t)c * H + h) * W + w0 + tx];
    }
    __syncthreads();
    #pragma unroll
    for (int r = 0; r < 4; ++r) {
        const int w = w0 + ty + r * 8;
        ft[((size_t)h * W + w) * 256 + c0 + tx] = t[tx][ty + r * 8];
    }
}

// ---------------- ROI align on channel-last feats ------------------------------
__global__ void roi_align2(const float* __restrict__ ft2, const float* __restrict__ ft3,
                           const float* __restrict__ ft4, const float* __restrict__ ft5,
                           const float* __restrict__ rois,
                           bf16* __restrict__ xh, bf16* __restrict__ xl)
{
    extern __shared__ float s[];   // 12544 floats
    const int r = blockIdx.x;
    const int c = threadIdx.x;

    __shared__ int   s_y0[14], s_y1[14], s_x0[14], s_x1[14];
    __shared__ float s_ly[14], s_lx[14];

    const float ry1 = rois[r * 4 + 0];
    const float rx1 = rois[r * 4 + 1];
    const float ry2 = rois[r * 4 + 2];
    const float rx2 = rois[r * 4 + 3];

    const float hh = ry2 - ry1 + 1.0f;
    const float ww = rx2 - rx1 + 1.0f;
    float lv = floorf(logf(sqrtf(hh * ww) / 224.0f) / 0.693147f + 4.0f);
    lv = fminf(fmaxf(lv, 2.0f), 5.0f);
    const int lvl = (int)lv;

    int H; const float* ft;
    if (lvl == 2)      { H = 256; ft = ft2; }
    else if (lvl == 3) { H = 128; ft = ft3; }
    else if (lvl == 4) { H = 64;  ft = ft4; }
    else               { H = 32;  ft = ft5; }
    const int W = H;

    const float fm = (float)(H - 1);
    const float gy1 = ry1 * fm / 1023.0f;
    const float gx1 = rx1 * fm / 1023.0f;
    const float gy2 = ry2 * fm / 1023.0f;
    const float gx2 = rx2 * fm / 1023.0f;
    const float hs = (gy2 - gy1) / 14.0f;
    const float ws = (gx2 - gx1) / 14.0f;

    if (c < 14) {
        const float cy = ((float)c + 0.5f) * hs + gy1;
        const float fl = floorf(cy);
        s_y0[c] = (int)fl;
        s_y1[c] = (int)ceilf(cy);
        s_ly[c] = cy - fl;
    } else if (c < 28) {
        const int j = c - 14;
        const float cx = ((float)j + 0.5f) * ws + gx1;
        const float fl = floorf(cx);
        s_x0[j] = (int)fl;
        s_x1[j] = (int)ceilf(cx);
        s_lx[j] = cx - fl;
    }
    __syncthreads();

    const float* __restrict__ fb = ft + c;

    for (int py = 0; py < 7; ++py) {
        float m[7];
        #pragma unroll
        for (int i = 0; i < 7; ++i) m[i] = -3.0e38f;
        #pragma unroll
        for (int a = 0; a < 2; ++a) {
            const int sy = 2 * py + a;
            const float ly = s_ly[sy];
            const float oly = 1.0f - ly;
            const float* __restrict__ r0 = fb + (size_t)(s_y0[sy] * W) * 256;
            const float* __restrict__ r1 = fb + (size_t)(s_y1[sy] * W) * 256;
            #pragma unroll
            for (int sx = 0; sx < 14; ++sx) {
                const int x0 = s_x0[sx] * 256;
                const int x1 = s_x1[sx] * 256;
                const float lx = s_lx[sx];
                const float olx = 1.0f - lx;
                const float v00 = r0[x0];
                const float v01 = r0[x1];
                const float v10 = r1[x0];
                const float v11 = r1[x1];
                const float v = v00 * oly * olx + v10 * ly * olx
                              + v01 * oly * lx  + v11 * ly * lx;
                m[sx >> 1] = fmaxf(m[sx >> 1], v);
            }
        }
        #pragma unroll
        for (int px = 0; px < 7; ++px)
            s[c * 49 + py * 7 + px] = m[px];
    }
    __syncthreads();

    const size_t ob = (size_t)r * DFEAT;
    for (int i = c * 2; i < DFEAT; i += 512) {
        const float v0 = s[i], v1 = s[i + 1];
        bf16 h0, l0, h1, l1;
        split2(v0, h0, l0);
        split2(v1, h1, l1);
        __nv_bfloat162 p;
        p.x = h0; p.y = h1;
        *(__nv_bfloat162*)(xh + ob + i) = p;
        p.x = l0; p.y = l1;
        *(__nv_bfloat162*)(xl + ob + i) = p;
    }
}

// ---------------- streaming fp32 -> bf16 hi/lo convert (same layout) -----------
__global__ void csplit(const float4* __restrict__ W4, int n4,
                       bf16* __restrict__ oH, bf16* __restrict__ oL)
{
    const int i = blockIdx.x * blockDim.x + threadIdx.x;
    if (i < n4) {
        const float4 v = W4[i];
        bf16 hx, lx, hy, ly, hz, lz, hw, lw;
        split2(v.x, hx, lx); split2(v.y, hy, ly);
        split2(v.z, hz, lz); split2(v.w, hw, lw);
        __nv_bfloat162 p;
        __nv_bfloat162* H2 = (__nv_bfloat162*)oH;
        __nv_bfloat162* L2 = (__nv_bfloat162*)oL;
        p.x = hx; p.y = hy; H2[2 * i]     = p;
        p.x = hz; p.y = hw; H2[2 * i + 1] = p;
        p.x = lx; p.y = ly; L2[2 * i]     = p;
        p.x = lz; p.y = lw; L2[2 * i + 1] = p;
    }
}

__global__ void theads(const float* __restrict__ Wloc, const float* __restrict__ Wsc,
                       bf16* __restrict__ oH, bf16* __restrict__ oL)
{
    const int idx = blockIdx.x * 256 + threadIdx.x;
    if (idx < 1024 * 512) {
        const int k = idx >> 9, n = idx & 511;
        float v = 0.0f;
        if (n < 324)      v = Wloc[k * 324 + n];
        else if (n < 405) v = Wsc[k * 81 + (n - 324)];
        bf16 h, l;
        split2(v, h, l);
        oH[idx] = h;
        oL[idx] = l;
    }
}

__global__ void bias_comb(const float* __restrict__ bloc, const float* __restrict__ bsc,
                          float* __restrict__ o)
{
    const int i = threadIdx.x;
    if (i < 512) o[i] = (i < 324) ? bloc[i] : ((i < 405) ? bsc[i - 324] : 0.0f);
}

// ---------------- HMMA GEMM, 3-stage pipeline, B from [K][N] via ldmatrix.trans
// A: [M][K] bf16 hi/lo (K-major). B: [K][N] bf16 hi/lo (N-major).
// Buffer 24KB: Ah[128][32]@0, Al@8192, Bh[32][64]@16384, Bl@20480.
#define GBK 32
#define BUF_SZ 24576
#define STG 3
#define GEMM_SMEM (STG * BUF_SZ)

__global__ __launch_bounds__(256) void gemm_mma(
    const bf16* __restrict__ Ah, const bf16* __restrict__ Al,
    const bf16* __restrict__ Bh, const bf16* __restrict__ Bl,
    const float* __restrict__ bias, int K, int N, int mode,
    bf16* __restrict__ outH, bf16* __restrict__ outL,
    float* __restrict__ outLoc, float* __restrict__ outSc, int outW)
{
    extern __shared__ char smem[];
    const uint32_t smU = s2u(smem);
    const int t   = threadIdx.x;
    const int l   = t & 31;
    const int wid = t >> 5;
    const int wm  = (wid & 1) * 64;
    const int wn  = (wid >> 1) * 16;
    const int rowBase = blockIdx.x * 128;
    const int colBase = blockIdx.y * 64;
    const size_t K2 = (size_t)K * 2;

    // A cp.async geometry
    const int caRow = t >> 2;
    const int caC   = t & 3;
    const uint32_t sSel  = (caRow >> 1) & 3;
    const uint32_t sOff0 = caRow * 64 + ((caC ^ sSel) << 4);
    const uint32_t sOff1 = sOff0 + 4096;
    const char* pAh  = (const char*)(Ah + (size_t)(rowBase + caRow) * K) + caC * 16;
    const char* pAh2 = pAh + 64 * K2;
    const char* pAl  = (const char*)(Al + (size_t)(rowBase + caRow) * K) + caC * 16;
    const char* pAl2 = pAl + 64 * K2;

    // B cp.async geometry: tile [32 k][64 n], 128B rows, chunk ^= row&7
    const int cbRow = t >> 3;         // 0..31 (k within tile)
    const int cbC   = t & 7;
    const uint32_t sOffB = cbRow * 128 + (((uint32_t)(cbC ^ (cbRow & 7))) << 4);
    const char* pBh = (const char*)(Bh + (size_t)cbRow * N + colBase) + cbC * 16;
    const char* pBl = (const char*)(Bl + (size_t)cbRow * N + colBase) + cbC * 16;
    const size_t bStep = (size_t)GBK * N * 2;   // bytes per k-tile

    float acc[4][2][4];
    #pragma unroll
    for (int mb = 0; mb < 4; ++mb)
        #pragma unroll
        for (int nb = 0; nb < 2; ++nb)
            #pragma unroll
            for (int i = 0; i < 4; ++i) acc[mb][nb][i] = 0.0f;

    // A ldmatrix geometry
    const uint32_t aRowAddr = (wm + (l & 15)) * 64;
    const uint32_t aSel = ((l & 15) >> 1) & 3;
    const uint32_t aCk0 = (l >> 4);
    // B ldmatrix.trans geometry
    const uint32_t bLane = l & 15;
    const uint32_t bNg   = (uint32_t)(l >> 4);
    const uint32_t bChunkBase = ((uint32_t)wn >> 3) + bNg;

    const int nt = K / GBK;

    auto issue = [&](int kt) {
        const uint32_t bu = smU + (kt % STG) * BUF_SZ;
        const size_t ka = (size_t)kt * 64;
        const size_t kb = (size_t)kt * bStep;
        cp16(bu + 0     + sOff0, pAh  + ka);
        cp16(bu + 0     + sOff1, pAh2 + ka);
        cp16(bu + 8192  + sOff0, pAl  + ka);
        cp16(bu + 8192  + sOff1, pAl2 + ka);
        cp16(bu + 16384 + sOffB, pBh + kb);
        cp16(bu + 20480 + sOffB, pBl + kb);
        cp_commit();
    };

    issue(0);
    if (nt > 1) issue(1); else cp_commit();   // keep group count consistent

    for (int kt = 0; kt < nt; ++kt) {
        cp_wait1();
        __syncthreads();
        if (kt + 2 < nt) issue(kt + 2);
        else { cp_commit(); }                  // dummy group keeps wait1 semantics

        const uint32_t bu = smU + (kt % STG) * BUF_SZ;
        const uint32_t aB = bu + aRowAddr;

        #pragma unroll
        for (int ks = 0; ks < 2; ++ks) {
            const uint32_t aOff = (((aCk0 + 2 * ks) ^ aSel) << 4);
            const uint32_t rowB = ks * 16 + bLane;
            const uint32_t bOff = rowB * 128 + ((bChunkBase ^ (rowB & 7)) << 4);

            uint32_t ah[4][4], al[4][4], bh[4], bl[4];
            #pragma unroll
            for (int mb = 0; mb < 4; ++mb) {
                ldsm4(ah[mb], aB + mb * 1024 + aOff);
                ldsm4(al[mb], aB + 8192 + mb * 1024 + aOff);
            }
            ldsm4t(bh, bu + 16384 + bOff);
            ldsm4t(bl, bu + 20480 + bOff);

            #pragma unroll
            for (int mb = 0; mb < 4; ++mb)
                #pragma unroll
                for (int nb = 0; nb < 2; ++nb)
                    mma16816(acc[mb][nb], ah[mb], &bh[2 * nb]);
            #pragma unroll
            for (int mb = 0; mb < 4; ++mb)
                #pragma unroll
                for (int nb = 0; nb < 2; ++nb)
                    mma16816(acc[mb][nb], al[mb], &bh[2 * nb]);
            #pragma unroll
            for (int mb = 0; mb < 4; ++mb)
                #pragma unroll
                for (int nb = 0; nb < 2; ++nb)
                    mma16816(acc[mb][nb], ah[mb], &bl[2 * nb]);
        }
    }

    // epilogue
    const int q = l >> 2, idx = l & 3;
    #pragma unroll
    for (int mb = 0; mb < 4; ++mb) {
        const int r0 = rowBase + wm + mb * 16 + q;
        const int r1 = r0 + 8;
        #pragma unroll
        for (int nb = 0; nb < 2; ++nb) {
            const int col = colBase + wn + nb * 8 + 2 * idx;
            if (mode == 0) {
                const float bs0 = bias[col], bs1 = bias[col + 1];
                float v00 = fmaxf(acc[mb][nb][0] + bs0, 0.0f);
                float v01 = fmaxf(acc[mb][nb][1] + bs1, 0.0f);
                float v10 = fmaxf(acc[mb][nb][2] + bs0, 0.0f);
                float v11 = fmaxf(acc[mb][nb][3] + bs1, 0.0f);
                bf16 h00, l00, h01, l01, h10, l10, h11, l11;
                split2(v00, h00, l00); split2(v01, h01, l01);
                split2(v10, h10, l10); split2(v11, h11, l11);
                __nv_bfloat162 p;
                p.x = h00; p.y = h01;
                *(__nv_bfloat162*)(outH + (size_t)r0 * outW + col) = p;
                p.x = l00; p.y = l01;
                *(__nv_bfloat162*)(outL + (size_t)r0 * outW + col) = p;
                p.x = h10; p.y = h11;
                *(__nv_bfloat162*)(outH + (size_t)r1 * outW + col) = p;
                p.x = l10; p.y = l11;
                *(__nv_bfloat162*)(outL + (size_t)r1 * outW + col) = p;
            } else {
                #pragma unroll
                for (int e = 0; e < 4; ++e) {
                    const int rr = (e < 2) ? r0 : r1;
                    const int cc = col + (e & 1);
                    if (rr < NROIS) {
                        const float v = acc[mb][nb][e] + bias[cc];
                        if (cc < 324)      outLoc[(size_t)rr * 324 + cc] = v;
                        else if (cc < 405) outSc[(size_t)rr * 81 + (cc - 324)] = v;
                    }
                }
            }
        }
    }
}

// ---------------- launch ------------------------------------------------------
extern "C" void kernel_launch(void* const* d_in, const int* in_sizes, int n_in,
                              void* d_out, int out_size)
{
    const float* f2   = (const float*)d_in[0];
    const float* f3   = (const float*)d_in[1];
    const float* f4   = (const float*)d_in[2];
    const float* f5   = (const float*)d_in[3];
    const float* rois = (const float*)d_in[4];
    const float* W1   = (const float*)d_in[6];
    const float* b1   = (const float*)d_in[7];
    const float* W2   = (const float*)d_in[8];
    const float* b2   = (const float*)d_in[9];
    const float* Wloc = (const float*)d_in[10];
    const float* bloc = (const float*)d_in[11];
    const float* Wsc  = (const float*)d_in[12];
    const float* bsc  = (const float*)d_in[13];

    float* out_loc = (float*)d_out;
    float* out_sc  = (float*)d_out + (size_t)NROIS * 324;

    bf16 *xh, *xl, *w1h, *w1l, *w2h, *w2l, *whh, *whl, *f1h, *f1l, *f2h_, *f2l_;
    float *bcomb, *ft2, *ft3, *ft4, *ft5;
    cudaGetSymbolAddress((void**)&xh,   g_xh);
    cudaGetSymbolAddress((void**)&xl,   g_xl);
    cudaGetSymbolAddress((void**)&w1h,  g_w1h);
    cudaGetSymbolAddress((void**)&w1l,  g_w1l);
    cudaGetSymbolAddress((void**)&w2h,  g_w2h);
    cudaGetSymbolAddress((void**)&w2l,  g_w2l);
    cudaGetSymbolAddress((void**)&whh,  g_whh);
    cudaGetSymbolAddress((void**)&whl,  g_whl);
    cudaGetSymbolAddress((void**)&f1h,  g_f1h);
    cudaGetSymbolAddress((void**)&f1l,  g_f1l);
    cudaGetSymbolAddress((void**)&f2h_, g_f2h);
    cudaGetSymbolAddress((void**)&f2l_, g_f2l);
    cudaGetSymbolAddress((void**)&bcomb, g_bcomb);
    cudaGetSymbolAddress((void**)&ft2,  g_ft2);
    cudaGetSymbolAddress((void**)&ft3,  g_ft3);
    cudaGetSymbolAddress((void**)&ft4,  g_ft4);
    cudaGetSymbolAddress((void**)&ft5,  g_ft5);

    cudaFuncSetAttribute(gemm_mma, cudaFuncAttributeMaxDynamicSharedMemorySize, GEMM_SMEM);
    cudaFuncSetAttribute(roi_align2, cudaFuncAttributeMaxDynamicSharedMemorySize, DFEAT * 4);

    bias_comb<<<1, 512>>>(bloc, bsc, bcomb);
    {
        const int n4a = DFEAT * 1024 / 4;
        csplit<<<(n4a + 255) / 256, 256>>>((const float4*)W1, n4a, w1h, w1l);
        const int n4b = 1024 * 1024 / 4;
        csplit<<<(n4b + 255) / 256, 256>>>((const float4*)W2, n4b, w2h, w2l);
        theads<<<(1024 * 512 + 255) / 256, 256>>>(Wloc, Wsc, whh, whl);
    }
    ftrans<<<dim3(256 / 32, 256, 8), dim3(32, 8)>>>(f2, ft2, 256);
    ftrans<<<dim3(128 / 32, 128, 8), dim3(32, 8)>>>(f3, ft3, 128);
    ftrans<<<dim3(64 / 32, 64, 8),   dim3(32, 8)>>>(f4, ft4, 64);
    ftrans<<<dim3(32 / 32, 32, 8),   dim3(32, 8)>>>(f5, ft5, 32);

    roi_align2<<<NROIS, 256, DFEAT * 4>>>(ft2, ft3, ft4, ft5, rois, xh, xl);

    gemm_mma<<<dim3(8, 16), 256, GEMM_SMEM>>>(xh, xl, w1h, w1l, b1, DFEAT, 1024, 0,
                                              f1h, f1l, nullptr, nullptr, 1024);
    gemm_mma<<<dim3(8, 16), 256, GEMM_SMEM>>>(f1h, f1l, w2h, w2l, b2, 1024, 1024, 0,
                                              f2h_, f2l_, nullptr, nullptr, 1024);
    gemm_mma<<<dim3(8, 7), 256, GEMM_SMEM>>>(f2h_, f2l_, whh, whl, bcomb, 1024, 512, 1,
                                             nullptr, nullptr, out_loc, out_sc, 0);
}

// round 5
// speedup vs baseline: 5.1015x; 1.0064x over previous
#include <cuda_runtime.h>
#include <cuda_bf16.h>
#include <cstdint>

typedef __nv_bfloat16 bf16;

#define NROIS 1000
#define DFEAT 12544
#define MPAD  1024

// ---------------- persistent scratch (zero-init) -------------------------------
__device__ bf16 g_xh [MPAD * DFEAT];
__device__ bf16 g_xl [MPAD * DFEAT];
__device__ bf16 g_w1h[DFEAT * 1024];   // [K][N]
__device__ bf16 g_w1l[DFEAT * 1024];
__device__ bf16 g_w2h[1024 * 1024];
__device__ bf16 g_w2l[1024 * 1024];
__device__ bf16 g_whh[1024 * 512];     // combined heads [K=1024][N=512 padded]
__device__ bf16 g_whl[1024 * 512];
__device__ bf16 g_f1h[MPAD * 1024];
__device__ bf16 g_f1l[MPAD * 1024];
__device__ bf16 g_f2h[MPAD * 1024];
__device__ bf16 g_f2l[MPAD * 1024];
__device__ float g_bcomb[512];
// transposed feature maps [H][W][C] fp32
__device__ float g_ft2[256 * 256 * 256];
__device__ float g_ft3[128 * 128 * 256];
__device__ float g_ft4[64 * 64 * 256];
__device__ float g_ft5[32 * 32 * 256];

// ---------------- helpers ------------------------------------------------------
__device__ __forceinline__ uint32_t s2u(const void* p) {
    uint32_t a;
    asm("{ .reg .u64 t; cvta.to.shared.u64 t, %1; cvt.u32.u64 %0, t; }" : "=r"(a) : "l"(p));
    return a;
}
__device__ __forceinline__ void cp16(uint32_t s, const void* g) {
    asm volatile("cp.async.cg.shared.global [%0], [%1], 16;" :: "r"(s), "l"(g) : "memory");
}
__device__ __forceinline__ void cp_commit() {
    asm volatile("cp.async.commit_group;" ::: "memory");
}
__device__ __forceinline__ void cp_wait2() {
    asm volatile("cp.async.wait_group 2;" ::: "memory");
}
__device__ __forceinline__ void ldsm4(uint32_t* r, uint32_t a) {
    asm volatile("ldmatrix.sync.aligned.m8n8.x4.shared.b16 {%0,%1,%2,%3}, [%4];"
                 : "=r"(r[0]), "=r"(r[1]), "=r"(r[2]), "=r"(r[3]) : "r"(a));
}
__device__ __forceinline__ void ldsm4t(uint32_t* r, uint32_t a) {
    asm volatile("ldmatrix.sync.aligned.m8n8.x4.trans.shared.b16 {%0,%1,%2,%3}, [%4];"
                 : "=r"(r[0]), "=r"(r[1]), "=r"(r[2]), "=r"(r[3]) : "r"(a));
}
__device__ __forceinline__ void mma16816(float* c, const uint32_t* a, const uint32_t* b) {
    asm volatile(
        "mma.sync.aligned.m16n8k16.row.col.f32.bf16.bf16.f32 "
        "{%0,%1,%2,%3}, {%4,%5,%6,%7}, {%8,%9}, {%0,%1,%2,%3};"
        : "+f"(c[0]), "+f"(c[1]), "+f"(c[2]), "+f"(c[3])
        : "r"(a[0]), "r"(a[1]), "r"(a[2]), "r"(a[3]), "r"(b[0]), "r"(b[1]));
}
__device__ __forceinline__ void split2(float v, bf16& h, bf16& l) {
    h = __float2bfloat16(v);
    l = __float2bfloat16(v - __bfloat162float(h));
}

// ---------------- fused prep: W1/W2 hi-lo split, heads pack, bias pack ---------
#define NB_W1 12544           // (DFEAT*1024/4)/256
#define NB_W2 1024            // (1024*1024/4)/256
#define NB_HD 2048            // (1024*512)/256
__global__ void prep_all(const float4* __restrict__ W1, const float4* __restrict__ W2,
                         const float* __restrict__ Wloc, const float* __restrict__ Wsc,
                         const float* __restrict__ bloc, const float* __restrict__ bsc,
                         bf16* __restrict__ w1h, bf16* __restrict__ w1l,
                         bf16* __restrict__ w2h, bf16* __restrict__ w2l,
                         bf16* __restrict__ whh, bf16* __restrict__ whl,
                         float* __restrict__ bcomb)
{
    const int b = blockIdx.x;
    const int tid = threadIdx.x;
    if (b < NB_W1 + NB_W2) {
        const bool isW1 = (b < NB_W1);
        const int i = (isW1 ? b : b - NB_W1) * 256 + tid;
        const float4 v = isW1 ? W1[i] : W2[i];
        bf16 hx, lx, hy, ly, hz, lz, hw, lw;
        split2(v.x, hx, lx); split2(v.y, hy, ly);
        split2(v.z, hz, lz); split2(v.w, hw, lw);
        __nv_bfloat162* H2 = (__nv_bfloat162*)(isW1 ? w1h : w2h);
        __nv_bfloat162* L2 = (__nv_bfloat162*)(isW1 ? w1l : w2l);
        __nv_bfloat162 p;
        p.x = hx; p.y = hy; H2[2 * i]     = p;
        p.x = hz; p.y = hw; H2[2 * i + 1] = p;
        p.x = lx; p.y = ly; L2[2 * i]     = p;
        p.x = lz; p.y = lw; L2[2 * i + 1] = p;
    } else if (b < NB_W1 + NB_W2 + NB_HD) {
        const int idx = (b - NB_W1 - NB_W2) * 256 + tid;
        const int k = idx >> 9, n = idx & 511;
        float v = 0.0f;
        if (n < 324)      v = Wloc[k * 324 + n];
        else if (n < 405) v = Wsc[k * 81 + (n - 324)];
        bf16 h, l;
        split2(v, h, l);
        whh[idx] = h;
        whl[idx] = l;
    } else {
        for (int i = tid; i < 512; i += 256)
            bcomb[i] = (i < 324) ? bloc[i] : ((i < 405) ? bsc[i - 324] : 0.0f);
    }
}

// ---------------- fused feature transpose [C][H][W] -> [H][W][C] ---------------
#define FT_NB2 16384   // 8*256*8
#define FT_NB3 4096    // 4*128*8
#define FT_NB4 1024    // 2*64*8
#define FT_NB5 256     // 1*32*8
__global__ void ftrans_all(const float* __restrict__ f2, const float* __restrict__ f3,
                           const float* __restrict__ f4, const float* __restrict__ f5,
                           float* __restrict__ t2o, float* __restrict__ t3o,
                           float* __restrict__ t4o, float* __restrict__ t5o)
{
    __shared__ float t[32][33];
    int b = blockIdx.x;
    const float* f; float* ft; int H;
    if (b < FT_NB2)                         { f = f2; ft = t2o; H = 256; }
    else if (b < FT_NB2 + FT_NB3)           { b -= FT_NB2; f = f3; ft = t3o; H = 128; }
    else if (b < FT_NB2 + FT_NB3 + FT_NB4)  { b -= FT_NB2 + FT_NB3; f = f4; ft = t4o; H = 64; }
    else                                    { b -= FT_NB2 + FT_NB3 + FT_NB4; f = f5; ft = t5o; H = 32; }
    const int W = H;
    const int wT = H >> 5;
    const int w0 = (b % wT) * 32;
    const int h  = (b / wT) % H;
    const int c0 = (b / (wT * H)) * 32;
    const int tx = threadIdx.x, ty = threadIdx.y;
    #pragma unroll
    for (int r = 0; r < 4; ++r) {
        const int c = c0 + ty + r * 8;
        t[ty + r * 8][tx] = f[((size_t)c * H + h) * W + w0 + tx];
    }
    __syncthreads();
    #pragma unroll
    for (int r = 0; r < 4; ++r) {
        const int w = w0 + ty + r * 8;
        ft[((size_t)h * W + w) * 256 + c0 + tx] = t[tx][ty + r * 8];
    }
}

// ---------------- ROI align on channel-last feats ------------------------------
__global__ void roi_align2(const float* __restrict__ ft2, const float* __restrict__ ft3,
                           const float* __restrict__ ft4, const float* __restrict__ ft5,
                           const float* __restrict__ rois,
                           bf16* __restrict__ xh, bf16* __restrict__ xl)
{
    extern __shared__ float s[];   // 12544 floats
    const int r = blockIdx.x;
    const int c = threadIdx.x;

    __shared__ int   s_y0[14], s_y1[14], s_x0[14], s_x1[14];
    __shared__ float s_ly[14], s_lx[14];

    const float ry1 = rois[r * 4 + 0];
    const float rx1 = rois[r * 4 + 1];
    const float ry2 = rois[r * 4 + 2];
    const float rx2 = rois[r * 4 + 3];

    const float hh = ry2 - ry1 + 1.0f;
    const float ww = rx2 - rx1 + 1.0f;
    float lv = floorf(logf(sqrtf(hh * ww) / 224.0f) / 0.693147f + 4.0f);
    lv = fminf(fmaxf(lv, 2.0f), 5.0f);
    const int lvl = (int)lv;

    int H; const float* ft;
    if (lvl == 2)      { H = 256; ft = ft2; }
    else if (lvl == 3) { H = 128; ft = ft3; }
    else if (lvl == 4) { H = 64;  ft = ft4; }
    else               { H = 32;  ft = ft5; }
    const int W = H;

    const float fm = (float)(H - 1);
    const float gy1 = ry1 * fm / 1023.0f;
    const float gx1 = rx1 * fm / 1023.0f;
    const float gy2 = ry2 * fm / 1023.0f;
    const float gx2 = rx2 * fm / 1023.0f;
    const float hs = (gy2 - gy1) / 14.0f;
    const float ws = (gx2 - gx1) / 14.0f;

    if (c < 14) {
        const float cy = ((float)c + 0.5f) * hs + gy1;
        const float fl = floorf(cy);
        s_y0[c] = (int)fl;
        s_y1[c] = (int)ceilf(cy);
        s_ly[c] = cy - fl;
    } else if (c < 28) {
        const int j = c - 14;
        const float cx = ((float)j + 0.5f) * ws + gx1;
        const float fl = floorf(cx);
        s_x0[j] = (int)fl;
        s_x1[j] = (int)ceilf(cx);
        s_lx[j] = cx - fl;
    }
    __syncthreads();

    const float* __restrict__ fb = ft + c;

    for (int py = 0; py < 7; ++py) {
        float m[7];
        #pragma unroll
        for (int i = 0; i < 7; ++i) m[i] = -3.0e38f;
        #pragma unroll
        for (int a = 0; a < 2; ++a) {
            const int sy = 2 * py + a;
            const float ly = s_ly[sy];
            const float oly = 1.0f - ly;
            const float* __restrict__ r0 = fb + (size_t)(s_y0[sy] * W) * 256;
            const float* __restrict__ r1 = fb + (size_t)(s_y1[sy] * W) * 256;
            #pragma unroll
            for (int sx = 0; sx < 14; ++sx) {
                const int x0 = s_x0[sx] * 256;
                const int x1 = s_x1[sx] * 256;
                const float lx = s_lx[sx];
                const float olx = 1.0f - lx;
                const float v00 = r0[x0];
                const float v01 = r0[x1];
                const float v10 = r1[x0];
                const float v11 = r1[x1];
                const float v = v00 * oly * olx + v10 * ly * olx
                              + v01 * oly * lx  + v11 * ly * lx;
                m[sx >> 1] = fmaxf(m[sx >> 1], v);
            }
        }
        #pragma unroll
        for (int px = 0; px < 7; ++px)
            s[c * 49 + py * 7 + px] = m[px];
    }
    __syncthreads();

    const size_t ob = (size_t)r * DFEAT;
    for (int i = c * 2; i < DFEAT; i += 512) {
        const float v0 = s[i], v1 = s[i + 1];
        bf16 h0, l0, h1, l1;
        split2(v0, h0, l0);
        split2(v1, h1, l1);
        __nv_bfloat162 p;
        p.x = h0; p.y = h1;
        *(__nv_bfloat162*)(xh + ob + i) = p;
        p.x = l0; p.y = l1;
        *(__nv_bfloat162*)(xl + ob + i) = p;
    }
}

// ---------------- HMMA GEMM, 4-stage cp.async pipeline -------------------------
// A: [M][K] bf16 hi/lo (K-major). B: [K][N] bf16 hi/lo (N-major).
// Buffer 24KB: Ah[128][32]@0, Al@8192, Bh[32][64]@16384, Bl@20480.
#define GBK 32
#define BUF_SZ 24576
#define STG 4
#define GEMM_SMEM (STG * BUF_SZ)

__global__ __launch_bounds__(256) void gemm_mma(
    const bf16* __restrict__ Ah, const bf16* __restrict__ Al,
    const bf16* __restrict__ Bh, const bf16* __restrict__ Bl,
    const float* __restrict__ bias, int K, int N, int mode,
    bf16* __restrict__ outH, bf16* __restrict__ outL,
    float* __restrict__ outLoc, float* __restrict__ outSc, int outW)
{
    extern __shared__ char smem[];
    const uint32_t smU = s2u(smem);
    const int t   = threadIdx.x;
    const int l   = t & 31;
    const int wid = t >> 5;
    const int wm  = (wid & 1) * 64;
    const int wn  = (wid >> 1) * 16;
    const int rowBase = blockIdx.x * 128;
    const int colBase = blockIdx.y * 64;
    const size_t K2 = (size_t)K * 2;

    // A cp.async geometry
    const int caRow = t >> 2;
    const int caC   = t & 3;
    const uint32_t sSel  = (caRow >> 1) & 3;
    const uint32_t sOff0 = caRow * 64 + ((caC ^ sSel) << 4);
    const uint32_t sOff1 = sOff0 + 4096;
    const char* pAh  = (const char*)(Ah + (size_t)(rowBase + caRow) * K) + caC * 16;
    const char* pAh2 = pAh + 64 * K2;
    const char* pAl  = (const char*)(Al + (size_t)(rowBase + caRow) * K) + caC * 16;
    const char* pAl2 = pAl + 64 * K2;

    // B cp.async geometry: tile [32 k][64 n], 128B rows, chunk ^= row&7
    const int cbRow = t >> 3;
    const int cbC   = t & 7;
    const uint32_t sOffB = cbRow * 128 + (((uint32_t)(cbC ^ (cbRow & 7))) << 4);
    const char* pBh = (const char*)(Bh + (size_t)cbRow * N + colBase) + cbC * 16;
    const char* pBl = (const char*)(Bl + (size_t)cbRow * N + colBase) + cbC * 16;
    const size_t bStep = (size_t)GBK * N * 2;

    float acc[4][2][4];
    #pragma unroll
    for (int mb = 0; mb < 4; ++mb)
        #pragma unroll
        for (int nb = 0; nb < 2; ++nb)
            #pragma unroll
            for (int i = 0; i < 4; ++i) acc[mb][nb][i] = 0.0f;

    // A ldmatrix geometry
    const uint32_t aRowAddr = (wm + (l & 15)) * 64;
    const uint32_t aSel = ((l & 15) >> 1) & 3;
    const uint32_t aCk0 = (l >> 4);
    // B ldmatrix.trans geometry
    const uint32_t bLane = l & 15;
    const uint32_t bNg   = (uint32_t)(l >> 4);
    const uint32_t bChunkBase = ((uint32_t)wn >> 3) + bNg;

    const int nt = K / GBK;

    auto issue = [&](int kt) {
        const uint32_t bu = smU + (kt % STG) * BUF_SZ;
        const size_t ka = (size_t)kt * 64;
        const size_t kb = (size_t)kt * bStep;
        cp16(bu + 0     + sOff0, pAh  + ka);
        cp16(bu + 0     + sOff1, pAh2 + ka);
        cp16(bu + 8192  + sOff0, pAl  + ka);
        cp16(bu + 8192  + sOff1, pAl2 + ka);
        cp16(bu + 16384 + sOffB, pBh + kb);
        cp16(bu + 20480 + sOffB, pBl + kb);
        cp_commit();
    };

    issue(0);
    if (nt > 1) issue(1); else cp_commit();
    if (nt > 2) issue(2); else cp_commit();

    for (int kt = 0; kt < nt; ++kt) {
        cp_wait2();
        __syncthreads();
        if (kt + 3 < nt) issue(kt + 3);
        else cp_commit();

        const uint32_t bu = smU + (kt % STG) * BUF_SZ;
        const uint32_t aB = bu + aRowAddr;

        #pragma unroll
        for (int ks = 0; ks < 2; ++ks) {
            const uint32_t aOff = (((aCk0 + 2 * ks) ^ aSel) << 4);
            const uint32_t rowB = ks * 16 + bLane;
            const uint32_t bOff = rowB * 128 + ((bChunkBase ^ (rowB & 7)) << 4);

            uint32_t ah[4][4], al[4][4], bh[4], bl[4];
            #pragma unroll
            for (int mb = 0; mb < 4; ++mb) {
                ldsm4(ah[mb], aB + mb * 1024 + aOff);
                ldsm4(al[mb], aB + 8192 + mb * 1024 + aOff);
            }
            ldsm4t(bh, bu + 16384 + bOff);
            ldsm4t(bl, bu + 20480 + bOff);

            #pragma unroll
            for (int mb = 0; mb < 4; ++mb)
                #pragma unroll
                for (int nb = 0; nb < 2; ++nb)
                    mma16816(acc[mb][nb], ah[mb], &bh[2 * nb]);
            #pragma unroll
            for (int mb = 0; mb < 4; ++mb)
                #pragma unroll
                for (int nb = 0; nb < 2; ++nb)
                    mma16816(acc[mb][nb], al[mb], &bh[2 * nb]);
            #pragma unroll
            for (int mb = 0; mb < 4; ++mb)
                #pragma unroll
                for (int nb = 0; nb < 2; ++nb)
                    mma16816(acc[mb][nb], ah[mb], &bl[2 * nb]);
        }
    }

    // epilogue
    const int q = l >> 2, idx = l & 3;
    #pragma unroll
    for (int mb = 0; mb < 4; ++mb) {
        const int r0 = rowBase + wm + mb * 16 + q;
        const int r1 = r0 + 8;
        #pragma unroll
        for (int nb = 0; nb < 2; ++nb) {
            const int col = colBase + wn + nb * 8 + 2 * idx;
            if (mode == 0) {
                const float bs0 = bias[col], bs1 = bias[col + 1];
                float v00 = fmaxf(acc[mb][nb][0] + bs0, 0.0f);
                float v01 = fmaxf(acc[mb][nb][1] + bs1, 0.0f);
                float v10 = fmaxf(acc[mb][nb][2] + bs0, 0.0f);
                float v11 = fmaxf(acc[mb][nb][3] + bs1, 0.0f);
                bf16 h00, l00, h01, l01, h10, l10, h11, l11;
                split2(v00, h00, l00); split2(v01, h01, l01);
                split2(v10, h10, l10); split2(v11, h11, l11);
                __nv_bfloat162 p;
                p.x = h00; p.y = h01;
                *(__nv_bfloat162*)(outH + (size_t)r0 * outW + col) = p;
                p.x = l00; p.y = l01;
                *(__nv_bfloat162*)(outL + (size_t)r0 * outW + col) = p;
                p.x = h10; p.y = h11;
                *(__nv_bfloat162*)(outH + (size_t)r1 * outW + col) = p;
                p.x = l10; p.y = l11;
                *(__nv_bfloat162*)(outL + (size_t)r1 * outW + col) = p;
            } else {
                #pragma unroll
                for (int e = 0; e < 4; ++e) {
                    const int rr = (e < 2) ? r0 : r1;
                    const int cc = col + (e & 1);
                    if (rr < NROIS) {
                        const float v = acc[mb][nb][e] + bias[cc];
                        if (cc < 324)      outLoc[(size_t)rr * 324 + cc] = v;
                        else if (cc < 405) outSc[(size_t)rr * 81 + (cc - 324)] = v;
                    }
                }
            }
        }
    }
}

// ---------------- launch ------------------------------------------------------
extern "C" void kernel_launch(void* const* d_in, const int* in_sizes, int n_in,
                              void* d_out, int out_size)
{
    const float* f2   = (const float*)d_in[0];
    const float* f3   = (const float*)d_in[1];
    const float* f4   = (const float*)d_in[2];
    const float* f5   = (const float*)d_in[3];
    const float* rois = (const float*)d_in[4];
    const float* W1   = (const float*)d_in[6];
    const float* b1   = (const float*)d_in[7];
    const float* W2   = (const float*)d_in[8];
    const float* b2   = (const float*)d_in[9];
    const float* Wloc = (const float*)d_in[10];
    const float* bloc = (const float*)d_in[11];
    const float* Wsc  = (const float*)d_in[12];
    const float* bsc  = (const float*)d_in[13];

    float* out_loc = (float*)d_out;
    float* out_sc  = (float*)d_out + (size_t)NROIS * 324;

    bf16 *xh, *xl, *w1h, *w1l, *w2h, *w2l, *whh, *whl, *f1h, *f1l, *f2h_, *f2l_;
    float *bcomb, *ft2, *ft3, *ft4, *ft5;
    cudaGetSymbolAddress((void**)&xh,   g_xh);
    cudaGetSymbolAddress((void**)&xl,   g_xl);
    cudaGetSymbolAddress((void**)&w1h,  g_w1h);
    cudaGetSymbolAddress((void**)&w1l,  g_w1l);
    cudaGetSymbolAddress((void**)&w2h,  g_w2h);
    cudaGetSymbolAddress((void**)&w2l,  g_w2l);
    cudaGetSymbolAddress((void**)&whh,  g_whh);
    cudaGetSymbolAddress((void**)&whl,  g_whl);
    cudaGetSymbolAddress((void**)&f1h,  g_f1h);
    cudaGetSymbolAddress((void**)&f1l,  g_f1l);
    cudaGetSymbolAddress((void**)&f2h_, g_f2h);
    cudaGetSymbolAddress((void**)&f2l_, g_f2l);
    cudaGetSymbolAddress((void**)&bcomb, g_bcomb);
    cudaGetSymbolAddress((void**)&ft2,  g_ft2);
    cudaGetSymbolAddress((void**)&ft3,  g_ft3);
    cudaGetSymbolAddress((void**)&ft4,  g_ft4);
    cudaGetSymbolAddress((void**)&ft5,  g_ft5);

    cudaFuncSetAttribute(gemm_mma, cudaFuncAttributeMaxDynamicSharedMemorySize, GEMM_SMEM);
    cudaFuncSetAttribute(roi_align2, cudaFuncAttributeMaxDynamicSharedMemorySize, DFEAT * 4);

    // launch 1: fused prep
    prep_all<<<NB_W1 + NB_W2 + NB_HD + 1, 256>>>((const float4*)W1, (const float4*)W2,
                                                 Wloc, Wsc, bloc, bsc,
                                                 w1h, w1l, w2h, w2l, whh, whl, bcomb);
    // launch 2: fused feature transpose
    ftrans_all<<<FT_NB2 + FT_NB3 + FT_NB4 + FT_NB5, dim3(32, 8)>>>(f2, f3, f4, f5,
                                                                   ft2, ft3, ft4, ft5);
    // launch 3: ROI align
    roi_align2<<<NROIS, 256, DFEAT * 4>>>(ft2, ft3, ft4, ft5, rois, xh, xl);

    // launch 4 (profiled): big GEMM
    gemm_mma<<<dim3(8, 16), 256, GEMM_SMEM>>>(xh, xl, w1h, w1l, b1, DFEAT, 1024, 0,
                                              f1h, f1l, nullptr, nullptr, 1024);
    // launch 5
    gemm_mma<<<dim3(8, 16), 256, GEMM_SMEM>>>(f1h, f1l, w2h, w2l, b2, 1024, 1024, 0,
                                              f2h_, f2l_, nullptr, nullptr, 1024);
    // launch 6
    gemm_mma<<<dim3(8, 7), 256, GEMM_SMEM>>>(f2h_, f2l_, whh, whl, bcomb, 1024, 512, 1,
                                             nullptr, nullptr, out_loc, out_sc, 0);
}

// round 6
// speedup vs baseline: 5.7154x; 1.1203x over previous
#include <cuda_runtime.h>
#include <cuda_bf16.h>
#include <cstdint>

typedef __nv_bfloat16 bf16;

#define NROIS 1000
#define DFEAT 12544
#define MPAD  1024

// ---------------- persistent scratch (zero-init) -------------------------------
__device__ bf16 g_xh [MPAD * DFEAT];
__device__ bf16 g_xl [MPAD * DFEAT];
__device__ bf16 g_w1h[DFEAT * 1024];   // [K][N]
__device__ bf16 g_w1l[DFEAT * 1024];
__device__ bf16 g_w2h[1024 * 1024];
__device__ bf16 g_w2l[1024 * 1024];
__device__ bf16 g_whh[1024 * 512];     // combined heads [K=1024][N=512 padded]
__device__ bf16 g_whl[1024 * 512];
__device__ bf16 g_f1h[MPAD * 1024];
__device__ bf16 g_f1l[MPAD * 1024];
__device__ bf16 g_f2h[MPAD * 1024];
__device__ bf16 g_f2l[MPAD * 1024];
__device__ float g_bcomb[512];
// transposed feature maps [H][W][C] fp32
__device__ float g_ft2[256 * 256 * 256];
__device__ float g_ft3[128 * 128 * 256];
__device__ float g_ft4[64 * 64 * 256];
__device__ float g_ft5[32 * 32 * 256];

// ---------------- helpers ------------------------------------------------------
__device__ __forceinline__ uint32_t s2u(const void* p) {
    uint32_t a;
    asm("{ .reg .u64 t; cvta.to.shared.u64 t, %1; cvt.u32.u64 %0, t; }" : "=r"(a) : "l"(p));
    return a;
}
__device__ __forceinline__ void cp16(uint32_t s, const void* g) {
    asm volatile("cp.async.cg.shared.global [%0], [%1], 16;" :: "r"(s), "l"(g) : "memory");
}
__device__ __forceinline__ void cp_commit() {
    asm volatile("cp.async.commit_group;" ::: "memory");
}
__device__ __forceinline__ void cp_wait2() {
    asm volatile("cp.async.wait_group 2;" ::: "memory");
}
__device__ __forceinline__ void ldsm4(uint32_t* r, uint32_t a) {
    asm volatile("ldmatrix.sync.aligned.m8n8.x4.shared.b16 {%0,%1,%2,%3}, [%4];"
                 : "=r"(r[0]), "=r"(r[1]), "=r"(r[2]), "=r"(r[3]) : "r"(a));
}
__device__ __forceinline__ void ldsm4t(uint32_t* r, uint32_t a) {
    asm volatile("ldmatrix.sync.aligned.m8n8.x4.trans.shared.b16 {%0,%1,%2,%3}, [%4];"
                 : "=r"(r[0]), "=r"(r[1]), "=r"(r[2]), "=r"(r[3]) : "r"(a));
}
__device__ __forceinline__ void mma16816(float* c, const uint32_t* a, const uint32_t* b) {
    asm volatile(
        "mma.sync.aligned.m16n8k16.row.col.f32.bf16.bf16.f32 "
        "{%0,%1,%2,%3}, {%4,%5,%6,%7}, {%8,%9}, {%0,%1,%2,%3};"
        : "+f"(c[0]), "+f"(c[1]), "+f"(c[2]), "+f"(c[3])
        : "r"(a[0]), "r"(a[1]), "r"(a[2]), "r"(a[3]), "r"(b[0]), "r"(b[1]));
}
__device__ __forceinline__ void split2(float v, bf16& h, bf16& l) {
    h = __float2bfloat16(v);
    l = __float2bfloat16(v - __bfloat162float(h));
}

// ---------------- fused prep: W1/W2 hi-lo split, heads pack, bias pack ---------
#define NB_W1 12544
#define NB_W2 1024
#define NB_HD 2048
__global__ void prep_all(const float4* __restrict__ W1, const float4* __restrict__ W2,
                         const float* __restrict__ Wloc, const float* __restrict__ Wsc,
                         const float* __restrict__ bloc, const float* __restrict__ bsc,
                         bf16* __restrict__ w1h, bf16* __restrict__ w1l,
                         bf16* __restrict__ w2h, bf16* __restrict__ w2l,
                         bf16* __restrict__ whh, bf16* __restrict__ whl,
                         float* __restrict__ bcomb)
{
    const int b = blockIdx.x;
    const int tid = threadIdx.x;
    if (b < NB_W1 + NB_W2) {
        const bool isW1 = (b < NB_W1);
        const int i = (isW1 ? b : b - NB_W1) * 256 + tid;
        const float4 v = isW1 ? W1[i] : W2[i];
        bf16 hx, lx, hy, ly, hz, lz, hw, lw;
        split2(v.x, hx, lx); split2(v.y, hy, ly);
        split2(v.z, hz, lz); split2(v.w, hw, lw);
        __nv_bfloat162* H2 = (__nv_bfloat162*)(isW1 ? w1h : w2h);
        __nv_bfloat162* L2 = (__nv_bfloat162*)(isW1 ? w1l : w2l);
        __nv_bfloat162 p;
        p.x = hx; p.y = hy; H2[2 * i]     = p;
        p.x = hz; p.y = hw; H2[2 * i + 1] = p;
        p.x = lx; p.y = ly; L2[2 * i]     = p;
        p.x = lz; p.y = lw; L2[2 * i + 1] = p;
    } else if (b < NB_W1 + NB_W2 + NB_HD) {
        const int idx = (b - NB_W1 - NB_W2) * 256 + tid;
        const int k = idx >> 9, n = idx & 511;
        float v = 0.0f;
        if (n < 324)      v = Wloc[k * 324 + n];
        else if (n < 405) v = Wsc[k * 81 + (n - 324)];
        bf16 h, l;
        split2(v, h, l);
        whh[idx] = h;
        whl[idx] = l;
    } else {
        for (int i = tid; i < 512; i += 256)
            bcomb[i] = (i < 324) ? bloc[i] : ((i < 405) ? bsc[i - 324] : 0.0f);
    }
}

// ---------------- fused feature transpose [C][H][W] -> [H][W][C] ---------------
#define FT_NB2 16384
#define FT_NB3 4096
#define FT_NB4 1024
#define FT_NB5 256
__global__ void ftrans_all(const float* __restrict__ f2, const float* __restrict__ f3,
                           const float* __restrict__ f4, const float* __restrict__ f5,
                           float* __restrict__ t2o, float* __restrict__ t3o,
                           float* __restrict__ t4o, float* __restrict__ t5o)
{
    __shared__ float t[32][33];
    int b = blockIdx.x;
    const float* f; float* ft; int H;
    if (b < FT_NB2)                         { f = f2; ft = t2o; H = 256; }
    else if (b < FT_NB2 + FT_NB3)           { b -= FT_NB2; f = f3; ft = t3o; H = 128; }
    else if (b < FT_NB2 + FT_NB3 + FT_NB4)  { b -= FT_NB2 + FT_NB3; f = f4; ft = t4o; H = 64; }
    else                                    { b -= FT_NB2 + FT_NB3 + FT_NB4; f = f5; ft = t5o; H = 32; }
    const int W = H;
    const int wT = H >> 5;
    const int w0 = (b % wT) * 32;
    const int h  = (b / wT) % H;
    const int c0 = (b / (wT * H)) * 32;
    const int tx = threadIdx.x, ty = threadIdx.y;
    #pragma unroll
    for (int r = 0; r < 4; ++r) {
        const int c = c0 + ty + r * 8;
        t[ty + r * 8][tx] = f[((size_t)c * H + h) * W + w0 + tx];
    }
    __syncthreads();
    #pragma unroll
    for (int r = 0; r < 4; ++r) {
        const int w = w0 + ty + r * 8;
        ft[((size_t)h * W + w) * 256 + c0 + tx] = t[tx][ty + r * 8];
    }
}

// ---------------- ROI align, float4 gather (4 channels/thread) -----------------
// 128 threads: cg = tid&63 (channels 4cg..4cg+3), half = tid>>6 (py split 0-3 / 4-6)
__global__ void roi_align3(const float* __restrict__ ft2, const float* __restrict__ ft3,
                           const float* __restrict__ ft4, const float* __restrict__ ft5,
                           const float* __restrict__ rois,
                           bf16* __restrict__ xh, bf16* __restrict__ xl)
{
    extern __shared__ float s[];   // 12544 floats
    const int r = blockIdx.x;
    const int tid = threadIdx.x;
    const int cg = tid & 63;
    const int half = tid >> 6;

    __shared__ int   s_y0[14], s_y1[14], s_x0[14], s_x1[14];
    __shared__ float s_ly[14], s_lx[14];

    const float ry1 = rois[r * 4 + 0];
    const float rx1 = rois[r * 4 + 1];
    const float ry2 = rois[r * 4 + 2];
    const float rx2 = rois[r * 4 + 3];

    const float hh = ry2 - ry1 + 1.0f;
    const float ww = rx2 - rx1 + 1.0f;
    float lv = floorf(logf(sqrtf(hh * ww) / 224.0f) / 0.693147f + 4.0f);
    lv = fminf(fmaxf(lv, 2.0f), 5.0f);
    const int lvl = (int)lv;

    int H; const float* ft;
    if (lvl == 2)      { H = 256; ft = ft2; }
    else if (lvl == 3) { H = 128; ft = ft3; }
    else if (lvl == 4) { H = 64;  ft = ft4; }
    else               { H = 32;  ft = ft5; }
    const int W = H;

    const float fm = (float)(H - 1);
    const float gy1 = ry1 * fm / 1023.0f;
    const float gx1 = rx1 * fm / 1023.0f;
    const float gy2 = ry2 * fm / 1023.0f;
    const float gx2 = rx2 * fm / 1023.0f;
    const float hs = (gy2 - gy1) / 14.0f;
    const float ws = (gx2 - gx1) / 14.0f;

    if (tid < 14) {
        const float cy = ((float)tid + 0.5f) * hs + gy1;
        const float fl = floorf(cy);
        s_y0[tid] = (int)fl;
        s_y1[tid] = (int)ceilf(cy);
        s_ly[tid] = cy - fl;
    } else if (tid < 28) {
        const int j = tid - 14;
        const float cx = ((float)j + 0.5f) * ws + gx1;
        const float fl = floorf(cx);
        s_x0[j] = (int)fl;
        s_x1[j] = (int)ceilf(cx);
        s_lx[j] = cx - fl;
    }
    __syncthreads();

    const float4* __restrict__ fb = (const float4*)ft + cg;   // channel group base

    const int pyBeg = half ? 4 : 0;
    const int pyEnd = half ? 7 : 4;

    for (int py = pyBeg; py < pyEnd; ++py) {
        float4 m[7];
        #pragma unroll
        for (int i = 0; i < 7; ++i) m[i] = make_float4(-3.0e38f, -3.0e38f, -3.0e38f, -3.0e38f);
        #pragma unroll
        for (int a = 0; a < 2; ++a) {
            const int sy = 2 * py + a;
            const float ly = s_ly[sy];
            const float oly = 1.0f - ly;
            const float4* __restrict__ r0 = fb + (size_t)(s_y0[sy] * W) * 64;
            const float4* __restrict__ r1 = fb + (size_t)(s_y1[sy] * W) * 64;
            #pragma unroll
            for (int sx = 0; sx < 14; ++sx) {
                const int x0 = s_x0[sx] * 64;
                const int x1 = s_x1[sx] * 64;
                const float lx = s_lx[sx];
                const float olx = 1.0f - lx;
                const float w00 = oly * olx, w01 = oly * lx;
                const float w10 = ly * olx,  w11 = ly * lx;
                const float4 v00 = r0[x0];
                const float4 v01 = r0[x1];
                const float4 v10 = r1[x0];
                const float4 v11 = r1[x1];
                float4& mm = m[sx >> 1];
                mm.x = fmaxf(mm.x, v00.x * w00 + v10.x * w10 + v01.x * w01 + v11.x * w11);
                mm.y = fmaxf(mm.y, v00.y * w00 + v10.y * w10 + v01.y * w01 + v11.y * w11);
                mm.z = fmaxf(mm.z, v00.z * w00 + v10.z * w10 + v01.z * w01 + v11.z * w11);
                mm.w = fmaxf(mm.w, v00.w * w00 + v10.w * w10 + v01.w * w01 + v11.w * w11);
            }
        }
        #pragma unroll
        for (int px = 0; px < 7; ++px) {
            const int cell = py * 7 + px;
            s[(4 * cg + 0) * 49 + cell] = m[px].x;
            s[(4 * cg + 1) * 49 + cell] = m[px].y;
            s[(4 * cg + 2) * 49 + cell] = m[px].z;
            s[(4 * cg + 3) * 49 + cell] = m[px].w;
        }
    }
    __syncthreads();

    const size_t ob = (size_t)r * DFEAT;
    for (int i = tid * 2; i < DFEAT; i += 256) {
        const float v0 = s[i], v1 = s[i + 1];
        bf16 h0, l0, h1, l1;
        split2(v0, h0, l0);
        split2(v1, h1, l1);
        __nv_bfloat162 p;
        p.x = h0; p.y = h1;
        *(__nv_bfloat162*)(xh + ob + i) = p;
        p.x = l0; p.y = l1;
        *(__nv_bfloat162*)(xl + ob + i) = p;
    }
}

// ---------------- HMMA GEMM, 512 threads, 4-stage cp.async pipeline ------------
// A: [M][K] bf16 hi/lo (K-major). B: [K][N] bf16 hi/lo (N-major).
// Buffer 24KB: Ah[128][32]@0, Al@8192, Bh[32][64]@16384, Bl@20480.
#define GBK 32
#define BUF_SZ 24576
#define STG 4
#define GEMM_SMEM (STG * BUF_SZ)

__global__ __launch_bounds__(512) void gemm_mma(
    const bf16* __restrict__ Ah, const bf16* __restrict__ Al,
    const bf16* __restrict__ Bh, const bf16* __restrict__ Bl,
    const float* __restrict__ bias, int K, int N, int mode,
    bf16* __restrict__ outH, bf16* __restrict__ outL,
    float* __restrict__ outLoc, float* __restrict__ outSc, int outW)
{
    extern __shared__ char smem[];
    const uint32_t smU = s2u(smem);
    const int t   = threadIdx.x;
    const int l   = t & 31;
    const int wid = t >> 5;                 // 0..15
    const int wm  = (wid & 3) * 32;         // 4 warps over M=128
    const int wn  = (wid >> 2) * 16;        // 4 warps over N=64
    const int rowBase = blockIdx.x * 128;
    const int colBase = blockIdx.y * 64;

    // A cp.async geometry: 128 rows x 64B, 1 chunk per thread
    const int caRow = t >> 2;                // 0..127
    const int caC   = t & 3;
    const uint32_t sSel  = (caRow >> 1) & 3;
    const uint32_t sOffA = caRow * 64 + ((caC ^ sSel) << 4);
    const char* pAh = (const char*)(Ah + (size_t)(rowBase + caRow) * K) + caC * 16;
    const char* pAl = (const char*)(Al + (size_t)(rowBase + caRow) * K) + caC * 16;

    // B cp.async geometry: tile [32 k][64 n] = 4KB, threads<256 -> Bh, >=256 -> Bl
    const int tb = t & 255;
    const int cbRow = tb >> 3;
    const int cbC   = tb & 7;
    const uint32_t sOffB = cbRow * 128 + (((uint32_t)(cbC ^ (cbRow & 7))) << 4);
    const char* pB = (const char*)((t < 256 ? Bh : Bl) + (size_t)cbRow * N + colBase) + cbC * 16;
    const uint32_t bBufOff = (t < 256) ? 16384u : 20480u;
    const size_t bStep = (size_t)GBK * N * 2;

    float acc[2][2][4];
    #pragma unroll
    for (int mb = 0; mb < 2; ++mb)
        #pragma unroll
        for (int nb = 0; nb < 2; ++nb)
            #pragma unroll
            for (int i = 0; i < 4; ++i) acc[mb][nb][i] = 0.0f;

    // A ldmatrix geometry
    const uint32_t aRowAddr = (wm + (l & 15)) * 64;
    const uint32_t aSel = ((l & 15) >> 1) & 3;
    const uint32_t aCk0 = (l >> 4);
    // B ldmatrix.trans geometry
    const uint32_t bLane = l & 15;
    const uint32_t bNg   = (uint32_t)(l >> 4);
    const uint32_t bChunkBase = ((uint32_t)wn >> 3) + bNg;

    const int nt = K / GBK;

    auto issue = [&](int kt) {
        const uint32_t bu = smU + (kt % STG) * BUF_SZ;
        const size_t ka = (size_t)kt * 64;
        const size_t kb = (size_t)kt * bStep;
        cp16(bu + 0    + sOffA, pAh + ka);
        cp16(bu + 8192 + sOffA, pAl + ka);
        cp16(bu + bBufOff + sOffB, pB + kb);
        cp_commit();
    };

    issue(0);
    if (nt > 1) issue(1); else cp_commit();
    if (nt > 2) issue(2); else cp_commit();

    for (int kt = 0; kt < nt; ++kt) {
        cp_wait2();
        __syncthreads();
        if (kt + 3 < nt) issue(kt + 3);
        else cp_commit();

        const uint32_t bu = smU + (kt % STG) * BUF_SZ;
        const uint32_t aB = bu + aRowAddr;

        #pragma unroll
        for (int ks = 0; ks < 2; ++ks) {
            const uint32_t aOff = (((aCk0 + 2 * ks) ^ aSel) << 4);
            const uint32_t rowB = ks * 16 + bLane;
            const uint32_t bOff = rowB * 128 + ((bChunkBase ^ (rowB & 7)) << 4);

            uint32_t ah[2][4], al[2][4], bh[4], bl[4];
            #pragma unroll
            for (int mb = 0; mb < 2; ++mb) {
                ldsm4(ah[mb], aB + mb * 1024 + aOff);
                ldsm4(al[mb], aB + 8192 + mb * 1024 + aOff);
            }
            ldsm4t(bh, bu + 16384 + bOff);
            ldsm4t(bl, bu + 20480 + bOff);

            #pragma unroll
            for (int mb = 0; mb < 2; ++mb)
                #pragma unroll
                for (int nb = 0; nb < 2; ++nb)
                    mma16816(acc[mb][nb], ah[mb], &bh[2 * nb]);
            #pragma unroll
            for (int mb = 0; mb < 2; ++mb)
                #pragma unroll
                for (int nb = 0; nb < 2; ++nb)
                    mma16816(acc[mb][nb], al[mb], &bh[2 * nb]);
            #pragma unroll
            for (int mb = 0; mb < 2; ++mb)
                #pragma unroll
                for (int nb = 0; nb < 2; ++nb)
                    mma16816(acc[mb][nb], ah[mb], &bl[2 * nb]);
        }
    }

    // epilogue
    const int q = l >> 2, idx = l & 3;
    #pragma unroll
    for (int mb = 0; mb < 2; ++mb) {
        const int r0 = rowBase + wm + mb * 16 + q;
        const int r1 = r0 + 8;
        #pragma unroll
        for (int nb = 0; nb < 2; ++nb) {
            const int col = colBase + wn + nb * 8 + 2 * idx;
            if (mode == 0) {
                const float bs0 = bias[col], bs1 = bias[col + 1];
                float v00 = fmaxf(acc[mb][nb][0] + bs0, 0.0f);
                float v01 = fmaxf(acc[mb][nb][1] + bs1, 0.0f);
                float v10 = fmaxf(acc[mb][nb][2] + bs0, 0.0f);
                float v11 = fmaxf(acc[mb][nb][3] + bs1, 0.0f);
                bf16 h00, l00, h01, l01, h10, l10, h11, l11;
                split2(v00, h00, l00); split2(v01, h01, l01);
                split2(v10, h10, l10); split2(v11, h11, l11);
                __nv_bfloat162 p;
                p.x = h00; p.y = h01;
                *(__nv_bfloat162*)(outH + (size_t)r0 * outW + col) = p;
                p.x = l00; p.y = l01;
                *(__nv_bfloat162*)(outL + (size_t)r0 * outW + col) = p;
                p.x = h10; p.y = h11;
                *(__nv_bfloat162*)(outH + (size_t)r1 * outW + col) = p;
                p.x = l10; p.y = l11;
                *(__nv_bfloat162*)(outL + (size_t)r1 * outW + col) = p;
            } else {
                #pragma unroll
                for (int e = 0; e < 4; ++e) {
                    const int rr = (e < 2) ? r0 : r1;
                    const int cc = col + (e & 1);
                    if (rr < NROIS) {
                        const float v = acc[mb][nb][e] + bias[cc];
                        if (cc < 324)      outLoc[(size_t)rr * 324 + cc] = v;
                        else if (cc < 405) outSc[(size_t)rr * 81 + (cc - 324)] = v;
                    }
                }
            }
        }
    }
}

// ---------------- launch ------------------------------------------------------
extern "C" void kernel_launch(void* const* d_in, const int* in_sizes, int n_in,
                              void* d_out, int out_size)
{
    const float* f2   = (const float*)d_in[0];
    const float* f3   = (const float*)d_in[1];
    const float* f4   = (const float*)d_in[2];
    const float* f5   = (const float*)d_in[3];
    const float* rois = (const float*)d_in[4];
    const float* W1   = (const float*)d_in[6];
    const float* b1   = (const float*)d_in[7];
    const float* W2   = (const float*)d_in[8];
    const float* b2   = (const float*)d_in[9];
    const float* Wloc = (const float*)d_in[10];
    const float* bloc = (const float*)d_in[11];
    const float* Wsc  = (const float*)d_in[12];
    const float* bsc  = (const float*)d_in[13];

    float* out_loc = (float*)d_out;
    float* out_sc  = (float*)d_out + (size_t)NROIS * 324;

    bf16 *xh, *xl, *w1h, *w1l, *w2h, *w2l, *whh, *whl, *f1h, *f1l, *f2h_, *f2l_;
    float *bcomb, *ft2, *ft3, *ft4, *ft5;
    cudaGetSymbolAddress((void**)&xh,   g_xh);
    cudaGetSymbolAddress((void**)&xl,   g_xl);
    cudaGetSymbolAddress((void**)&w1h,  g_w1h);
    cudaGetSymbolAddress((void**)&w1l,  g_w1l);
    cudaGetSymbolAddress((void**)&w2h,  g_w2h);
    cudaGetSymbolAddress((void**)&w2l,  g_w2l);
    cudaGetSymbolAddress((void**)&whh,  g_whh);
    cudaGetSymbolAddress((void**)&whl,  g_whl);
    cudaGetSymbolAddress((void**)&f1h,  g_f1h);
    cudaGetSymbolAddress((void**)&f1l,  g_f1l);
    cudaGetSymbolAddress((void**)&f2h_, g_f2h);
    cudaGetSymbolAddress((void**)&f2l_, g_f2l);
    cudaGetSymbolAddress((void**)&bcomb, g_bcomb);
    cudaGetSymbolAddress((void**)&ft2,  g_ft2);
    cudaGetSymbolAddress((void**)&ft3,  g_ft3);
    cudaGetSymbolAddress((void**)&ft4,  g_ft4);
    cudaGetSymbolAddress((void**)&ft5,  g_ft5);

    cudaFuncSetAttribute(gemm_mma, cudaFuncAttributeMaxDynamicSharedMemorySize, GEMM_SMEM);
    cudaFuncSetAttribute(roi_align3, cudaFuncAttributeMaxDynamicSharedMemorySize, DFEAT * 4);

    // launch 1: fused prep
    prep_all<<<NB_W1 + NB_W2 + NB_HD + 1, 256>>>((const float4*)W1, (const float4*)W2,
                                                 Wloc, Wsc, bloc, bsc,
                                                 w1h, w1l, w2h, w2l, whh, whl, bcomb);
    // launch 2: fused feature transpose
    ftrans_all<<<FT_NB2 + FT_NB3 + FT_NB4 + FT_NB5, dim3(32, 8)>>>(f2, f3, f4, f5,
                                                                   ft2, ft3, ft4, ft5);
    // launch 3: ROI align
    roi_align3<<<NROIS, 128, DFEAT * 4>>>(ft2, ft3, ft4, ft5, rois, xh, xl);

    // launch 4 (profiled): big GEMM
    gemm_mma<<<dim3(8, 16), 512, GEMM_SMEM>>>(xh, xl, w1h, w1l, b1, DFEAT, 1024, 0,
                                              f1h, f1l, nullptr, nullptr, 1024);
    // launch 5
    gemm_mma<<<dim3(8, 16), 512, GEMM_SMEM>>>(f1h, f1l, w2h, w2l, b2, 1024, 1024, 0,
                                              f2h_, f2l_, nullptr, nullptr, 1024);
    // launch 6
    gemm_mma<<<dim3(8, 7), 512, GEMM_SMEM>>>(f2h_, f2l_, whh, whl, bcomb, 1024, 512, 1,
                                             nullptr, nullptr, out_loc, out_sc, 0);
}

// round 7
// speedup vs baseline: 6.0381x; 1.0565x over previous
#include <cuda_runtime.h>
#include <cuda_bf16.h>
#include <cstdint>

typedef __nv_bfloat16 bf16;

#define NROIS 1000
#define DFEAT 12544
#define MPAD  1024

// ---------------- persistent scratch (zero-init) -------------------------------
__device__ bf16 g_xh [MPAD * DFEAT];
__device__ bf16 g_xl [MPAD * DFEAT];
__device__ bf16 g_w1h[DFEAT * 1024];   // [K][N]
__device__ bf16 g_w1l[DFEAT * 1024];
__device__ bf16 g_w2h[1024 * 1024];
__device__ bf16 g_w2l[1024 * 1024];
__device__ bf16 g_whh[1024 * 512];     // combined heads [K=1024][N=512 padded]
__device__ bf16 g_whl[1024 * 512];
__device__ bf16 g_f1h[MPAD * 1024];
__device__ bf16 g_f1l[MPAD * 1024];
__device__ bf16 g_f2h[MPAD * 1024];
__device__ bf16 g_f2l[MPAD * 1024];
__device__ float g_bcomb[512];
// transposed feature maps [H][W][C] fp32
__device__ float g_ft2[256 * 256 * 256];
__device__ float g_ft3[128 * 128 * 256];
__device__ float g_ft4[64 * 64 * 256];
__device__ float g_ft5[32 * 32 * 256];

// ---------------- helpers ------------------------------------------------------
__device__ __forceinline__ uint32_t s2u(const void* p) {
    uint32_t a;
    asm("{ .reg .u64 t; cvta.to.shared.u64 t, %1; cvt.u32.u64 %0, t; }" : "=r"(a) : "l"(p));
    return a;
}
__device__ __forceinline__ void cp16(uint32_t s, const void* g) {
    asm volatile("cp.async.cg.shared.global [%0], [%1], 16;" :: "r"(s), "l"(g) : "memory");
}
__device__ __forceinline__ void cp_commit() {
    asm volatile("cp.async.commit_group;" ::: "memory");
}
__device__ __forceinline__ void cp_wait2() {
    asm volatile("cp.async.wait_group 2;" ::: "memory");
}
__device__ __forceinline__ void ldsm4(uint32_t* r, uint32_t a) {
    asm volatile("ldmatrix.sync.aligned.m8n8.x4.shared.b16 {%0,%1,%2,%3}, [%4];"
                 : "=r"(r[0]), "=r"(r[1]), "=r"(r[2]), "=r"(r[3]) : "r"(a));
}
__device__ __forceinline__ void ldsm4t(uint32_t* r, uint32_t a) {
    asm volatile("ldmatrix.sync.aligned.m8n8.x4.trans.shared.b16 {%0,%1,%2,%3}, [%4];"
                 : "=r"(r[0]), "=r"(r[1]), "=r"(r[2]), "=r"(r[3]) : "r"(a));
}
__device__ __forceinline__ void mma16816(float* c, const uint32_t* a, const uint32_t* b) {
    asm volatile(
        "mma.sync.aligned.m16n8k16.row.col.f32.bf16.bf16.f32 "
        "{%0,%1,%2,%3}, {%4,%5,%6,%7}, {%8,%9}, {%0,%1,%2,%3};"
        : "+f"(c[0]), "+f"(c[1]), "+f"(c[2]), "+f"(c[3])
        : "r"(a[0]), "r"(a[1]), "r"(a[2]), "r"(a[3]), "r"(b[0]), "r"(b[1]));
}
__device__ __forceinline__ void split2(float v, bf16& h, bf16& l) {
    h = __float2bfloat16(v);
    l = __float2bfloat16(v - __bfloat162float(h));
}

// ---------------- fused prep: W1/W2 hi-lo split, heads pack, bias pack ---------
#define NB_W1 12544
#define NB_W2 1024
#define NB_HD 2048
__global__ void prep_all(const float4* __restrict__ W1, const float4* __restrict__ W2,
                         const float* __restrict__ Wloc, const float* __restrict__ Wsc,
                         const float* __restrict__ bloc, const float* __restrict__ bsc,
                         bf16* __restrict__ w1h, bf16* __restrict__ w1l,
                         bf16* __restrict__ w2h, bf16* __restrict__ w2l,
                         bf16* __restrict__ whh, bf16* __restrict__ whl,
                         float* __restrict__ bcomb)
{
    const int b = blockIdx.x;
    const int tid = threadIdx.x;
    if (b < NB_W1 + NB_W2) {
        const bool isW1 = (b < NB_W1);
        const int i = (isW1 ? b : b - NB_W1) * 256 + tid;
        const float4 v = isW1 ? W1[i] : W2[i];
        bf16 hx, lx, hy, ly, hz, lz, hw, lw;
        split2(v.x, hx, lx); split2(v.y, hy, ly);
        split2(v.z, hz, lz); split2(v.w, hw, lw);
        __nv_bfloat162* H2 = (__nv_bfloat162*)(isW1 ? w1h : w2h);
        __nv_bfloat162* L2 = (__nv_bfloat162*)(isW1 ? w1l : w2l);
        __nv_bfloat162 p;
        p.x = hx; p.y = hy; H2[2 * i]     = p;
        p.x = hz; p.y = hw; H2[2 * i + 1] = p;
        p.x = lx; p.y = ly; L2[2 * i]     = p;
        p.x = lz; p.y = lw; L2[2 * i + 1] = p;
    } else if (b < NB_W1 + NB_W2 + NB_HD) {
        const int idx = (b - NB_W1 - NB_W2) * 256 + tid;
        const int k = idx >> 9, n = idx & 511;
        float v = 0.0f;
        if (n < 324)      v = Wloc[k * 324 + n];
        else if (n < 405) v = Wsc[k * 81 + (n - 324)];
        bf16 h, l;
        split2(v, h, l);
        whh[idx] = h;
        whl[idx] = l;
    } else {
        for (int i = tid; i < 512; i += 256)
            bcomb[i] = (i < 324) ? bloc[i] : ((i < 405) ? bsc[i - 324] : 0.0f);
    }
}

// ---------------- fused feature transpose [C][H][W] -> [H][W][C] ---------------
#define FT_NB2 16384
#define FT_NB3 4096
#define FT_NB4 1024
#define FT_NB5 256
__global__ void ftrans_all(const float* __restrict__ f2, const float* __restrict__ f3,
                           const float* __restrict__ f4, const float* __restrict__ f5,
                           float* __restrict__ t2o, float* __restrict__ t3o,
                           float* __restrict__ t4o, float* __restrict__ t5o)
{
    __shared__ float t[32][33];
    int b = blockIdx.x;
    const float* f; float* ft; int H;
    if (b < FT_NB2)                         { f = f2; ft = t2o; H = 256; }
    else if (b < FT_NB2 + FT_NB3)           { b -= FT_NB2; f = f3; ft = t3o; H = 128; }
    else if (b < FT_NB2 + FT_NB3 + FT_NB4)  { b -= FT_NB2 + FT_NB3; f = f4; ft = t4o; H = 64; }
    else                                    { b -= FT_NB2 + FT_NB3 + FT_NB4; f = f5; ft = t5o; H = 32; }
    const int W = H;
    const int wT = H >> 5;
    const int w0 = (b % wT) * 32;
    const int h  = (b / wT) % H;
    const int c0 = (b / (wT * H)) * 32;
    const int tx = threadIdx.x, ty = threadIdx.y;
    #pragma unroll
    for (int r = 0; r < 4; ++r) {
        const int c = c0 + ty + r * 8;
        t[ty + r * 8][tx] = f[((size_t)c * H + h) * W + w0 + tx];
    }
    __syncthreads();
    #pragma unroll
    for (int r = 0; r < 4; ++r) {
        const int w = w0 + ty + r * 8;
        ft[((size_t)h * W + w) * 256 + c0 + tx] = t[tx][ty + r * 8];
    }
}

// ---------------- ROI align, float4 gather (4 channels/thread) -----------------
__global__ void roi_align3(const float* __restrict__ ft2, const float* __restrict__ ft3,
                           const float* __restrict__ ft4, const float* __restrict__ ft5,
                           const float* __restrict__ rois,
                           bf16* __restrict__ xh, bf16* __restrict__ xl)
{
    extern __shared__ float s[];   // 12544 floats
    const int r = blockIdx.x;
    const int tid = threadIdx.x;
    const int cg = tid & 63;
    const int half = tid >> 6;

    __shared__ int   s_y0[14], s_y1[14], s_x0[14], s_x1[14];
    __shared__ float s_ly[14], s_lx[14];

    const float ry1 = rois[r * 4 + 0];
    const float rx1 = rois[r * 4 + 1];
    const float ry2 = rois[r * 4 + 2];
    const float rx2 = rois[r * 4 + 3];

    const float hh = ry2 - ry1 + 1.0f;
    const float ww = rx2 - rx1 + 1.0f;
    float lv = floorf(logf(sqrtf(hh * ww) / 224.0f) / 0.693147f + 4.0f);
    lv = fminf(fmaxf(lv, 2.0f), 5.0f);
    const int lvl = (int)lv;

    int H; const float* ft;
    if (lvl == 2)      { H = 256; ft = ft2; }
    else if (lvl == 3) { H = 128; ft = ft3; }
    else if (lvl == 4) { H = 64;  ft = ft4; }
    else               { H = 32;  ft = ft5; }
    const int W = H;

    const float fm = (float)(H - 1);
    const float gy1 = ry1 * fm / 1023.0f;
    const float gx1 = rx1 * fm / 1023.0f;
    const float gy2 = ry2 * fm / 1023.0f;
    const float gx2 = rx2 * fm / 1023.0f;
    const float hs = (gy2 - gy1) / 14.0f;
    const float ws = (gx2 - gx1) / 14.0f;

    if (tid < 14) {
        const float cy = ((float)tid + 0.5f) * hs + gy1;
        const float fl = floorf(cy);
        s_y0[tid] = (int)fl;
        s_y1[tid] = (int)ceilf(cy);
        s_ly[tid] = cy - fl;
    } else if (tid < 28) {
        const int j = tid - 14;
        const float cx = ((float)j + 0.5f) * ws + gx1;
        const float fl = floorf(cx);
        s_x0[j] = (int)fl;
        s_x1[j] = (int)ceilf(cx);
        s_lx[j] = cx - fl;
    }
    __syncthreads();

    const float4* __restrict__ fb = (const float4*)ft + cg;

    const int pyBeg = half ? 4 : 0;
    const int pyEnd = half ? 7 : 4;

    for (int py = pyBeg; py < pyEnd; ++py) {
        float4 m[7];
        #pragma unroll
        for (int i = 0; i < 7; ++i) m[i] = make_float4(-3.0e38f, -3.0e38f, -3.0e38f, -3.0e38f);
        #pragma unroll
        for (int a = 0; a < 2; ++a) {
            const int sy = 2 * py + a;
            const float ly = s_ly[sy];
            const float oly = 1.0f - ly;
            const float4* __restrict__ r0 = fb + (size_t)(s_y0[sy] * W) * 64;
            const float4* __restrict__ r1 = fb + (size_t)(s_y1[sy] * W) * 64;
            #pragma unroll
            for (int sx = 0; sx < 14; ++sx) {
                const int x0 = s_x0[sx] * 64;
                const int x1 = s_x1[sx] * 64;
                const float lx = s_lx[sx];
                const float olx = 1.0f - lx;
                const float w00 = oly * olx, w01 = oly * lx;
                const float w10 = ly * olx,  w11 = ly * lx;
                const float4 v00 = r0[x0];
                const float4 v01 = r0[x1];
                const float4 v10 = r1[x0];
                const float4 v11 = r1[x1];
                float4& mm = m[sx >> 1];
                mm.x = fmaxf(mm.x, v00.x * w00 + v10.x * w10 + v01.x * w01 + v11.x * w11);
                mm.y = fmaxf(mm.y, v00.y * w00 + v10.y * w10 + v01.y * w01 + v11.y * w11);
                mm.z = fmaxf(mm.z, v00.z * w00 + v10.z * w10 + v01.z * w01 + v11.z * w11);
                mm.w = fmaxf(mm.w, v00.w * w00 + v10.w * w10 + v01.w * w01 + v11.w * w11);
            }
        }
        #pragma unroll
        for (int px = 0; px < 7; ++px) {
            const int cell = py * 7 + px;
            s[(4 * cg + 0) * 49 + cell] = m[px].x;
            s[(4 * cg + 1) * 49 + cell] = m[px].y;
            s[(4 * cg + 2) * 49 + cell] = m[px].z;
            s[(4 * cg + 3) * 49 + cell] = m[px].w;
        }
    }
    __syncthreads();

    const size_t ob = (size_t)r * DFEAT;
    for (int i = tid * 2; i < DFEAT; i += 256) {
        const float v0 = s[i], v1 = s[i + 1];
        bf16 h0, l0, h1, l1;
        split2(v0, h0, l0);
        split2(v1, h1, l1);
        __nv_bfloat162 p;
        p.x = h0; p.y = h1;
        *(__nv_bfloat162*)(xh + ob + i) = p;
        p.x = l0; p.y = l1;
        *(__nv_bfloat162*)(xl + ob + i) = p;
    }
}

// ---------------- HMMA GEMM, 256 threads, warp tile 32x32, 4-stage pipeline ----
// A: [M][K] bf16 hi/lo (K-major). B: [K][N] bf16 hi/lo (N-major).
// Buffer 24KB: Ah[128][32]@0, Al@8192, Bh[32][64]@16384, Bl@20480.
#define GBK 32
#define BUF_SZ 24576
#define STG 4
#define GEMM_SMEM (STG * BUF_SZ)

__global__ __launch_bounds__(256) void gemm_mma(
    const bf16* __restrict__ Ah, const bf16* __restrict__ Al,
    const bf16* __restrict__ Bh, const bf16* __restrict__ Bl,
    const float* __restrict__ bias, int K, int N, int mode,
    bf16* __restrict__ outH, bf16* __restrict__ outL,
    float* __restrict__ outLoc, float* __restrict__ outSc, int outW)
{
    extern __shared__ char smem[];
    const uint32_t smU = s2u(smem);
    const int t   = threadIdx.x;
    const int l   = t & 31;
    const int wid = t >> 5;                 // 0..7
    const int wm  = (wid & 3) * 32;         // 4 warps over M=128
    const int wn  = (wid >> 2) * 32;        // 2 warps over N=64
    const int rowBase = blockIdx.x * 128;
    const int colBase = blockIdx.y * 64;
    const size_t K2 = (size_t)K * 2;

    // A cp.async geometry (256 threads, 2 chunks each for hi and lo)
    const int caRow = t >> 2;                // 0..63
    const int caC   = t & 3;
    const uint32_t sSel  = (caRow >> 1) & 3;
    const uint32_t sOff0 = caRow * 64 + ((caC ^ sSel) << 4);
    const uint32_t sOff1 = sOff0 + 4096;     // rows 64..127
    const char* pAh  = (const char*)(Ah + (size_t)(rowBase + caRow) * K) + caC * 16;
    const char* pAh2 = pAh + 64 * K2;
    const char* pAl  = (const char*)(Al + (size_t)(rowBase + caRow) * K) + caC * 16;
    const char* pAl2 = pAl + 64 * K2;

    // B cp.async geometry: tile [32 k][64 n], 128B rows, chunk ^= row&7
    const int cbRow = t >> 3;
    const int cbC   = t & 7;
    const uint32_t sOffB = cbRow * 128 + (((uint32_t)(cbC ^ (cbRow & 7))) << 4);
    const char* pBh = (const char*)(Bh + (size_t)cbRow * N + colBase) + cbC * 16;
    const char* pBl = (const char*)(Bl + (size_t)cbRow * N + colBase) + cbC * 16;
    const size_t bStep = (size_t)GBK * N * 2;

    float acc[2][4][4];
    #pragma unroll
    for (int mb = 0; mb < 2; ++mb)
        #pragma unroll
        for (int nb = 0; nb < 4; ++nb)
            #pragma unroll
            for (int i = 0; i < 4; ++i) acc[mb][nb][i] = 0.0f;

    // A ldmatrix geometry
    const uint32_t aRowAddr = (wm + (l & 15)) * 64;
    const uint32_t aSel = ((l & 15) >> 1) & 3;
    const uint32_t aCk0 = (l >> 4);
    // B ldmatrix.trans geometry (two 16-wide n-groups)
    const uint32_t bLane = l & 15;
    const uint32_t bNg   = (uint32_t)(l >> 4);
    const uint32_t bCk0  = ((uint32_t)wn >> 3) + bNg;      // group 0 chunks
    const uint32_t bCk1  = bCk0 + 2;                        // group 1 chunks

    const int nt = K / GBK;

    auto issue = [&](int kt) {
        const uint32_t bu = smU + (kt % STG) * BUF_SZ;
        const size_t ka = (size_t)kt * 64;
        const size_t kb = (size_t)kt * bStep;
        cp16(bu + 0     + sOff0, pAh  + ka);
        cp16(bu + 0     + sOff1, pAh2 + ka);
        cp16(bu + 8192  + sOff0, pAl  + ka);
        cp16(bu + 8192  + sOff1, pAl2 + ka);
        cp16(bu + 16384 + sOffB, pBh + kb);
        cp16(bu + 20480 + sOffB, pBl + kb);
        cp_commit();
    };

    issue(0);
    if (nt > 1) issue(1); else cp_commit();
    if (nt > 2) issue(2); else cp_commit();

    for (int kt = 0; kt < nt; ++kt) {
        cp_wait2();
        __syncthreads();
        if (kt + 3 < nt) issue(kt + 3);
        else cp_commit();

        const uint32_t bu = smU + (kt % STG) * BUF_SZ;
        const uint32_t aB = bu + aRowAddr;

        #pragma unroll
        for (int ks = 0; ks < 2; ++ks) {
            const uint32_t aOff = (((aCk0 + 2 * ks) ^ aSel) << 4);
            const uint32_t rowB = ks * 16 + bLane;
            const uint32_t rx = rowB & 7;
            const uint32_t bRow = rowB * 128;

            uint32_t ah[2][4], al[2][4], bh[2][4], bl[2][4];
            // 8 independent ldmatrix loads (MLP=8)
            ldsm4(ah[0], aB + aOff);
            ldsm4(ah[1], aB + 1024 + aOff);
            ldsm4(al[0], aB + 8192 + aOff);
            ldsm4(al[1], aB + 9216 + aOff);
            ldsm4t(bh[0], bu + 16384 + bRow + (((bCk0 ^ rx)) << 4));
            ldsm4t(bh[1], bu + 16384 + bRow + (((bCk1 ^ rx)) << 4));
            ldsm4t(bl[0], bu + 20480 + bRow + (((bCk0 ^ rx)) << 4));
            ldsm4t(bl[1], bu + 20480 + bRow + (((bCk1 ^ rx)) << 4));

            #pragma unroll
            for (int mb = 0; mb < 2; ++mb)
                #pragma unroll
                for (int nb = 0; nb < 4; ++nb)
                    mma16816(acc[mb][nb], ah[mb], &bh[nb >> 1][2 * (nb & 1)]);
            #pragma unroll
            for (int mb = 0; mb < 2; ++mb)
                #pragma unroll
                for (int nb = 0; nb < 4; ++nb)
                    mma16816(acc[mb][nb], al[mb], &bh[nb >> 1][2 * (nb & 1)]);
            #pragma unroll
            for (int mb = 0; mb < 2; ++mb)
                #pragma unroll
                for (int nb = 0; nb < 4; ++nb)
                    mma16816(acc[mb][nb], ah[mb], &bl[nb >> 1][2 * (nb & 1)]);
        }
    }

    // epilogue
    const int q = l >> 2, idx = l & 3;
    #pragma unroll
    for (int mb = 0; mb < 2; ++mb) {
        const int r0 = rowBase + wm + mb * 16 + q;
        const int r1 = r0 + 8;
        #pragma unroll
        for (int nb = 0; nb < 4; ++nb) {
            const int col = colBase + wn + nb * 8 + 2 * idx;
            if (mode == 0) {
                const float bs0 = bias[col], bs1 = bias[col + 1];
                float v00 = fmaxf(acc[mb][nb][0] + bs0, 0.0f);
                float v01 = fmaxf(acc[mb][nb][1] + bs1, 0.0f);
                float v10 = fmaxf(acc[mb][nb][2] + bs0, 0.0f);
                float v11 = fmaxf(acc[mb][nb][3] + bs1, 0.0f);
                bf16 h00, l00, h01, l01, h10, l10, h11, l11;
                split2(v00, h00, l00); split2(v01, h01, l01);
                split2(v10, h10, l10); split2(v11, h11, l11);
                __nv_bfloat162 p;
                p.x = h00; p.y = h01;
                *(__nv_bfloat162*)(outH + (size_t)r0 * outW + col) = p;
                p.x = l00; p.y = l01;
                *(__nv_bfloat162*)(outL + (size_t)r0 * outW + col) = p;
                p.x = h10; p.y = h11;
                *(__nv_bfloat162*)(outH + (size_t)r1 * outW + col) = p;
                p.x = l10; p.y = l11;
                *(__nv_bfloat162*)(outL + (size_t)r1 * outW + col) = p;
            } else {
                #pragma unroll
                for (int e = 0; e < 4; ++e) {
                    const int rr = (e < 2) ? r0 : r1;
                    const int cc = col + (e & 1);
                    if (rr < NROIS) {
                        const float v = acc[mb][nb][e] + bias[cc];
                        if (cc < 324)      outLoc[(size_t)rr * 324 + cc] = v;
                        else if (cc < 405) outSc[(size_t)rr * 81 + (cc - 324)] = v;
                    }
                }
            }
        }
    }
}

// ---------------- launch ------------------------------------------------------
extern "C" void kernel_launch(void* const* d_in, const int* in_sizes, int n_in,
                              void* d_out, int out_size)
{
    const float* f2   = (const float*)d_in[0];
    const float* f3   = (const float*)d_in[1];
    const float* f4   = (const float*)d_in[2];
    const float* f5   = (const float*)d_in[3];
    const float* rois = (const float*)d_in[4];
    const float* W1   = (const float*)d_in[6];
    const float* b1   = (const float*)d_in[7];
    const float* W2   = (const float*)d_in[8];
    const float* b2   = (const float*)d_in[9];
    const float* Wloc = (const float*)d_in[10];
    const float* bloc = (const float*)d_in[11];
    const float* Wsc  = (const float*)d_in[12];
    const float* bsc  = (const float*)d_in[13];

    float* out_loc = (float*)d_out;
    float* out_sc  = (float*)d_out + (size_t)NROIS * 324;

    bf16 *xh, *xl, *w1h, *w1l, *w2h, *w2l, *whh, *whl, *f1h, *f1l, *f2h_, *f2l_;
    float *bcomb, *ft2, *ft3, *ft4, *ft5;
    cudaGetSymbolAddress((void**)&xh,   g_xh);
    cudaGetSymbolAddress((void**)&xl,   g_xl);
    cudaGetSymbolAddress((void**)&w1h,  g_w1h);
    cudaGetSymbolAddress((void**)&w1l,  g_w1l);
    cudaGetSymbolAddress((void**)&w2h,  g_w2h);
    cudaGetSymbolAddress((void**)&w2l,  g_w2l);
    cudaGetSymbolAddress((void**)&whh,  g_whh);
    cudaGetSymbolAddress((void**)&whl,  g_whl);
    cudaGetSymbolAddress((void**)&f1h,  g_f1h);
    cudaGetSymbolAddress((void**)&f1l,  g_f1l);
    cudaGetSymbolAddress((void**)&f2h_, g_f2h);
    cudaGetSymbolAddress((void**)&f2l_, g_f2l);
    cudaGetSymbolAddress((void**)&bcomb, g_bcomb);
    cudaGetSymbolAddress((void**)&ft2,  g_ft2);
    cudaGetSymbolAddress((void**)&ft3,  g_ft3);
    cudaGetSymbolAddress((void**)&ft4,  g_ft4);
    cudaGetSymbolAddress((void**)&ft5,  g_ft5);

    cudaFuncSetAttribute(gemm_mma, cudaFuncAttributeMaxDynamicSharedMemorySize, GEMM_SMEM);
    cudaFuncSetAttribute(roi_align3, cudaFuncAttributeMaxDynamicSharedMemorySize, DFEAT * 4);

    // launch 1: fused prep
    prep_all<<<NB_W1 + NB_W2 + NB_HD + 1, 256>>>((const float4*)W1, (const float4*)W2,
                                                 Wloc, Wsc, bloc, bsc,
                                                 w1h, w1l, w2h, w2l, whh, whl, bcomb);
    // launch 2: fused feature transpose
    ftrans_all<<<FT_NB2 + FT_NB3 + FT_NB4 + FT_NB5, dim3(32, 8)>>>(f2, f3, f4, f5,
                                                                   ft2, ft3, ft4, ft5);
    // launch 3: ROI align
    roi_align3<<<NROIS, 128, DFEAT * 4>>>(ft2, ft3, ft4, ft5, rois, xh, xl);

    // launch 4 (profiled): big GEMM
    gemm_mma<<<dim3(8, 16), 256, GEMM_SMEM>>>(xh, xl, w1h, w1l, b1, DFEAT, 1024, 0,
                                              f1h, f1l, nullptr, nullptr, 1024);
    // launch 5
    gemm_mma<<<dim3(8, 16), 256, GEMM_SMEM>>>(f1h, f1l, w2h, w2l, b2, 1024, 1024, 0,
                                              f2h_, f2l_, nullptr, nullptr, 1024);
    // launch 6
    gemm_mma<<<dim3(8, 7), 256, GEMM_SMEM>>>(f2h_, f2l_, whh, whl, bcomb, 1024, 512, 1,
                                             nullptr, nullptr, out_loc, out_sc, 0);
}

// round 8
// speedup vs baseline: 7.0451x; 1.1668x over previous
#include <cuda_runtime.h>
#include <cuda_fp16.h>
#include <cstdint>

typedef __half fp16;

#define NROIS 1000
#define DFEAT 12544
#define MPAD  1024

// ---------------- persistent scratch (zero-init) -------------------------------
__device__ fp16 g_xh [MPAD * DFEAT];
__device__ fp16 g_xl [MPAD * DFEAT];
__device__ fp16 g_w1h[DFEAT * 1024];   // [K][N], single fp16
__device__ fp16 g_w2h[1024 * 1024];
__device__ fp16 g_whh[1024 * 512];     // combined heads [K=1024][N=512 padded]
__device__ fp16 g_f1h[MPAD * 1024];
__device__ fp16 g_f1l[MPAD * 1024];
__device__ fp16 g_f2h[MPAD * 1024];
__device__ fp16 g_f2l[MPAD * 1024];
__device__ float g_bcomb[512];
// transposed feature maps [H][W][C] fp32
__device__ float g_ft2[256 * 256 * 256];
__device__ float g_ft3[128 * 128 * 256];
__device__ float g_ft4[64 * 64 * 256];
__device__ float g_ft5[32 * 32 * 256];

// ---------------- helpers ------------------------------------------------------
__device__ __forceinline__ uint32_t s2u(const void* p) {
    uint32_t a;
    asm("{ .reg .u64 t; cvta.to.shared.u64 t, %1; cvt.u32.u64 %0, t; }" : "=r"(a) : "l"(p));
    return a;
}
__device__ __forceinline__ void cp16(uint32_t s, const void* g) {
    asm volatile("cp.async.cg.shared.global [%0], [%1], 16;" :: "r"(s), "l"(g) : "memory");
}
__device__ __forceinline__ void cp_commit() {
    asm volatile("cp.async.commit_group;" ::: "memory");
}
__device__ __forceinline__ void cp_wait2() {
    asm volatile("cp.async.wait_group 2;" ::: "memory");
}
__device__ __forceinline__ void ldsm4(uint32_t* r, uint32_t a) {
    asm volatile("ldmatrix.sync.aligned.m8n8.x4.shared.b16 {%0,%1,%2,%3}, [%4];"
                 : "=r"(r[0]), "=r"(r[1]), "=r"(r[2]), "=r"(r[3]) : "r"(a));
}
__device__ __forceinline__ void ldsm4t(uint32_t* r, uint32_t a) {
    asm volatile("ldmatrix.sync.aligned.m8n8.x4.trans.shared.b16 {%0,%1,%2,%3}, [%4];"
                 : "=r"(r[0]), "=r"(r[1]), "=r"(r[2]), "=r"(r[3]) : "r"(a));
}
__device__ __forceinline__ void mma16816(float* c, const uint32_t* a, const uint32_t* b) {
    asm volatile(
        "mma.sync.aligned.m16n8k16.row.col.f32.f16.f16.f32 "
        "{%0,%1,%2,%3}, {%4,%5,%6,%7}, {%8,%9}, {%0,%1,%2,%3};"
        : "+f"(c[0]), "+f"(c[1]), "+f"(c[2]), "+f"(c[3])
        : "r"(a[0]), "r"(a[1]), "r"(a[2]), "r"(a[3]), "r"(b[0]), "r"(b[1]));
}
__device__ __forceinline__ void split2h(float v, fp16& h, fp16& l) {
    h = __float2half_rn(v);
    l = __float2half_rn(v - __half2float(h));
}

// ---------------- fused prep: W1/W2 fp16 convert, heads pack, bias pack --------
#define NB_W1 12544
#define NB_W2 1024
#define NB_HD 2048
__global__ void prep_all(const float4* __restrict__ W1, const float4* __restrict__ W2,
                         const float* __restrict__ Wloc, const float* __restrict__ Wsc,
                         const float* __restrict__ bloc, const float* __restrict__ bsc,
                         fp16* __restrict__ w1h, fp16* __restrict__ w2h,
                         fp16* __restrict__ whh, float* __restrict__ bcomb)
{
    const int b = blockIdx.x;
    const int tid = threadIdx.x;
    if (b < NB_W1 + NB_W2) {
        const bool isW1 = (b < NB_W1);
        const int i = (isW1 ? b : b - NB_W1) * 256 + tid;
        const float4 v = isW1 ? W1[i] : W2[i];
        __half2* H2 = (__half2*)(isW1 ? w1h : w2h);
        H2[2 * i]     = __halves2half2(__float2half_rn(v.x), __float2half_rn(v.y));
        H2[2 * i + 1] = __halves2half2(__float2half_rn(v.z), __float2half_rn(v.w));
    } else if (b < NB_W1 + NB_W2 + NB_HD) {
        const int idx = (b - NB_W1 - NB_W2) * 256 + tid;
        const int k = idx >> 9, n = idx & 511;
        float v = 0.0f;
        if (n < 324)      v = Wloc[k * 324 + n];
        else if (n < 405) v = Wsc[k * 81 + (n - 324)];
        whh[idx] = __float2half_rn(v);
    } else {
        for (int i = tid; i < 512; i += 256)
            bcomb[i] = (i < 324) ? bloc[i] : ((i < 405) ? bsc[i - 324] : 0.0f);
    }
}

// ---------------- fused feature transpose [C][H][W] -> [H][W][C] ---------------
#define FT_NB2 16384
#define FT_NB3 4096
#define FT_NB4 1024
#define FT_NB5 256
__global__ void ftrans_all(const float* __restrict__ f2, const float* __restrict__ f3,
                           const float* __restrict__ f4, const float* __restrict__ f5,
                           float* __restrict__ t2o, float* __restrict__ t3o,
                           float* __restrict__ t4o, float* __restrict__ t5o)
{
    __shared__ float t[32][33];
    int b = blockIdx.x;
    const float* f; float* ft; int H;
    if (b < FT_NB2)                         { f = f2; ft = t2o; H = 256; }
    else if (b < FT_NB2 + FT_NB3)           { b -= FT_NB2; f = f3; ft = t3o; H = 128; }
    else if (b < FT_NB2 + FT_NB3 + FT_NB4)  { b -= FT_NB2 + FT_NB3; f = f4; ft = t4o; H = 64; }
    else                                    { b -= FT_NB2 + FT_NB3 + FT_NB4; f = f5; ft = t5o; H = 32; }
    const int W = H;
    const int wT = H >> 5;
    const int w0 = (b % wT) * 32;
    const int h  = (b / wT) % H;
    const int c0 = (b / (wT * H)) * 32;
    const int tx = threadIdx.x, ty = threadIdx.y;
    #pragma unroll
    for (int r = 0; r < 4; ++r) {
        const int c = c0 + ty + r * 8;
        t[ty + r * 8][tx] = f[((size_t)c * H + h) * W + w0 + tx];
    }
    __syncthreads();
    #pragma unroll
    for (int r = 0; r < 4; ++r) {
        const int w = w0 + ty + r * 8;
        ft[((size_t)h * W + w) * 256 + c0 + tx] = t[tx][ty + r * 8];
    }
}

// ---------------- ROI align, float4 gather (4 channels/thread) -----------------
__global__ void roi_align3(const float* __restrict__ ft2, const float* __restrict__ ft3,
                           const float* __restrict__ ft4, const float* __restrict__ ft5,
                           const float* __restrict__ rois,
                           fp16* __restrict__ xh, fp16* __restrict__ xl)
{
    extern __shared__ float s[];   // 12544 floats
    const int r = blockIdx.x;
    const int tid = threadIdx.x;
    const int cg = tid & 63;
    const int half = tid >> 6;

    __shared__ int   s_y0[14], s_y1[14], s_x0[14], s_x1[14];
    __shared__ float s_ly[14], s_lx[14];

    const float ry1 = rois[r * 4 + 0];
    const float rx1 = rois[r * 4 + 1];
    const float ry2 = rois[r * 4 + 2];
    const float rx2 = rois[r * 4 + 3];

    const float hh = ry2 - ry1 + 1.0f;
    const float ww = rx2 - rx1 + 1.0f;
    float lv = floorf(logf(sqrtf(hh * ww) / 224.0f) / 0.693147f + 4.0f);
    lv = fminf(fmaxf(lv, 2.0f), 5.0f);
    const int lvl = (int)lv;

    int H; const float* ft;
    if (lvl == 2)      { H = 256; ft = ft2; }
    else if (lvl == 3) { H = 128; ft = ft3; }
    else if (lvl == 4) { H = 64;  ft = ft4; }
    else               { H = 32;  ft = ft5; }
    const int W = H;

    const float fm = (float)(H - 1);
    const float gy1 = ry1 * fm / 1023.0f;
    const float gx1 = rx1 * fm / 1023.0f;
    const float gy2 = ry2 * fm / 1023.0f;
    const float gx2 = rx2 * fm / 1023.0f;
    const float hs = (gy2 - gy1) / 14.0f;
    const float ws = (gx2 - gx1) / 14.0f;

    if (tid < 14) {
        const float cy = ((float)tid + 0.5f) * hs + gy1;
        const float fl = floorf(cy);
        s_y0[tid] = (int)fl;
        s_y1[tid] = (int)ceilf(cy);
        s_ly[tid] = cy - fl;
    } else if (tid < 28) {
        const int j = tid - 14;
        const float cx = ((float)j + 0.5f) * ws + gx1;
        const float fl = floorf(cx);
        s_x0[j] = (int)fl;
        s_x1[j] = (int)ceilf(cx);
        s_lx[j] = cx - fl;
    }
    __syncthreads();

    const float4* __restrict__ fb = (const float4*)ft + cg;

    const int pyBeg = half ? 4 : 0;
    const int pyEnd = half ? 7 : 4;

    for (int py = pyBeg; py < pyEnd; ++py) {
        float4 m[7];
        #pragma unroll
        for (int i = 0; i < 7; ++i) m[i] = make_float4(-3.0e38f, -3.0e38f, -3.0e38f, -3.0e38f);
        #pragma unroll
        for (int a = 0; a < 2; ++a) {
            const int sy = 2 * py + a;
            const float ly = s_ly[sy];
            const float oly = 1.0f - ly;
            const float4* __restrict__ r0 = fb + (size_t)(s_y0[sy] * W) * 64;
            const float4* __restrict__ r1 = fb + (size_t)(s_y1[sy] * W) * 64;
            #pragma unroll
            for (int sx = 0; sx < 14; ++sx) {
                const int x0 = s_x0[sx] * 64;
                const int x1 = s_x1[sx] * 64;
                const float lx = s_lx[sx];
                const float olx = 1.0f - lx;
                const float w00 = oly * olx, w01 = oly * lx;
                const float w10 = ly * olx,  w11 = ly * lx;
                const float4 v00 = r0[x0];
                const float4 v01 = r0[x1];
                const float4 v10 = r1[x0];
                const float4 v11 = r1[x1];
                float4& mm = m[sx >> 1];
                mm.x = fmaxf(mm.x, v00.x * w00 + v10.x * w10 + v01.x * w01 + v11.x * w11);
                mm.y = fmaxf(mm.y, v00.y * w00 + v10.y * w10 + v01.y * w01 + v11.y * w11);
                mm.z = fmaxf(mm.z, v00.z * w00 + v10.z * w10 + v01.z * w01 + v11.z * w11);
                mm.w = fmaxf(mm.w, v00.w * w00 + v10.w * w10 + v01.w * w01 + v11.w * w11);
            }
        }
        #pragma unroll
        for (int px = 0; px < 7; ++px) {
            const int cell = py * 7 + px;
            s[(4 * cg + 0) * 49 + cell] = m[px].x;
            s[(4 * cg + 1) * 49 + cell] = m[px].y;
            s[(4 * cg + 2) * 49 + cell] = m[px].z;
            s[(4 * cg + 3) * 49 + cell] = m[px].w;
        }
    }
    __syncthreads();

    const size_t ob = (size_t)r * DFEAT;
    for (int i = tid * 2; i < DFEAT; i += 256) {
        const float v0 = s[i], v1 = s[i + 1];
        fp16 h0, l0, h1, l1;
        split2h(v0, h0, l0);
        split2h(v1, h1, l1);
        *(__half2*)(xh + ob + i) = __halves2half2(h0, h1);
        *(__half2*)(xl + ob + i) = __halves2half2(l0, l1);
    }
}

// ---------------- HMMA GEMM, 2-term fp16, 256 threads, 32x32 warp tiles --------
// A: [M][K] fp16 hi/lo (K-major). B: [K][N] fp16 (N-major, single).
// Buffer 20KB: Ah[128][32]@0, Al@8192, Bh[32][64]@16384.
#define GBK 32
#define BUF_SZ 20480
#define STG 4
#define GEMM_SMEM (STG * BUF_SZ)

__global__ __launch_bounds__(256) void gemm_mma(
    const fp16* __restrict__ Ah, const fp16* __restrict__ Al,
    const fp16* __restrict__ Bh,
    const float* __restrict__ bias, int K, int N, int mode,
    fp16* __restrict__ outH, fp16* __restrict__ outL,
    float* __restrict__ outLoc, float* __restrict__ outSc, int outW)
{
    extern __shared__ char smem[];
    const uint32_t smU = s2u(smem);
    const int t   = threadIdx.x;
    const int l   = t & 31;
    const int wid = t >> 5;                 // 0..7
    const int wm  = (wid & 3) * 32;         // 4 warps over M=128
    const int wn  = (wid >> 2) * 32;        // 2 warps over N=64
    const int rowBase = blockIdx.x * 128;
    const int colBase = blockIdx.y * 64;
    const size_t K2 = (size_t)K * 2;

    // A cp.async geometry
    const int caRow = t >> 2;                // 0..63
    const int caC   = t & 3;
    const uint32_t sSel  = (caRow >> 1) & 3;
    const uint32_t sOff0 = caRow * 64 + ((caC ^ sSel) << 4);
    const uint32_t sOff1 = sOff0 + 4096;     // rows 64..127
    const char* pAh  = (const char*)(Ah + (size_t)(rowBase + caRow) * K) + caC * 16;
    const char* pAh2 = pAh + 64 * K2;
    const char* pAl  = (const char*)(Al + (size_t)(rowBase + caRow) * K) + caC * 16;
    const char* pAl2 = pAl + 64 * K2;

    // B cp.async geometry: tile [32 k][64 n], 128B rows, chunk ^= row&7
    const int cbRow = t >> 3;
    const int cbC   = t & 7;
    const uint32_t sOffB = cbRow * 128 + (((uint32_t)(cbC ^ (cbRow & 7))) << 4);
    const char* pBh = (const char*)(Bh + (size_t)cbRow * N + colBase) + cbC * 16;
    const size_t bStep = (size_t)GBK * N * 2;

    float acc[2][4][4];
    #pragma unroll
    for (int mb = 0; mb < 2; ++mb)
        #pragma unroll
        for (int nb = 0; nb < 4; ++nb)
            #pragma unroll
            for (int i = 0; i < 4; ++i) acc[mb][nb][i] = 0.0f;

    // A ldmatrix geometry
    const uint32_t aRowAddr = (wm + (l & 15)) * 64;
    const uint32_t aSel = ((l & 15) >> 1) & 3;
    const uint32_t aCk0 = (l >> 4);
    // B ldmatrix.trans geometry (two 16-wide n-groups)
    const uint32_t bLane = l & 15;
    const uint32_t bNg   = (uint32_t)(l >> 4);
    const uint32_t bCk0  = ((uint32_t)wn >> 3) + bNg;
    const uint32_t bCk1  = bCk0 + 2;

    const int nt = K / GBK;

    auto issue = [&](int kt) {
        const uint32_t bu = smU + (kt % STG) * BUF_SZ;
        const size_t ka = (size_t)kt * 64;
        const size_t kb = (size_t)kt * bStep;
        cp16(bu + 0     + sOff0, pAh  + ka);
        cp16(bu + 0     + sOff1, pAh2 + ka);
        cp16(bu + 8192  + sOff0, pAl  + ka);
        cp16(bu + 8192  + sOff1, pAl2 + ka);
        cp16(bu + 16384 + sOffB, pBh + kb);
        cp_commit();
    };

    issue(0);
    if (nt > 1) issue(1); else cp_commit();
    if (nt > 2) issue(2); else cp_commit();

    for (int kt = 0; kt < nt; ++kt) {
        cp_wait2();
        __syncthreads();
        if (kt + 3 < nt) issue(kt + 3);
        else cp_commit();

        const uint32_t bu = smU + (kt % STG) * BUF_SZ;
        const uint32_t aB = bu + aRowAddr;

        #pragma unroll
        for (int ks = 0; ks < 2; ++ks) {
            const uint32_t aOff = (((aCk0 + 2 * ks) ^ aSel) << 4);
            const uint32_t rowB = ks * 16 + bLane;
            const uint32_t rx = rowB & 7;
            const uint32_t bRow = rowB * 128;

            uint32_t ah[2][4], al[2][4], bh[2][4];
            // 6 independent ldmatrix loads
            ldsm4(ah[0], aB + aOff);
            ldsm4(ah[1], aB + 1024 + aOff);
            ldsm4(al[0], aB + 8192 + aOff);
            ldsm4(al[1], aB + 9216 + aOff);
            ldsm4t(bh[0], bu + 16384 + bRow + (((bCk0 ^ rx)) << 4));
            ldsm4t(bh[1], bu + 16384 + bRow + (((bCk1 ^ rx)) << 4));

            #pragma unroll
            for (int mb = 0; mb < 2; ++mb)
                #pragma unroll
                for (int nb = 0; nb < 4; ++nb)
                    mma16816(acc[mb][nb], ah[mb], &bh[nb >> 1][2 * (nb & 1)]);
            #pragma unroll
            for (int mb = 0; mb < 2; ++mb)
                #pragma unroll
                for (int nb = 0; nb < 4; ++nb)
                    mma16816(acc[mb][nb], al[mb], &bh[nb >> 1][2 * (nb & 1)]);
        }
    }

    // epilogue
    const int q = l >> 2, idx = l & 3;
    #pragma unroll
    for (int mb = 0; mb < 2; ++mb) {
        const int r0 = rowBase + wm + mb * 16 + q;
        const int r1 = r0 + 8;
        #pragma unroll
        for (int nb = 0; nb < 4; ++nb) {
            const int col = colBase + wn + nb * 8 + 2 * idx;
            if (mode == 0) {
                const float bs0 = bias[col], bs1 = bias[col + 1];
                float v00 = fmaxf(acc[mb][nb][0] + bs0, 0.0f);
                float v01 = fmaxf(acc[mb][nb][1] + bs1, 0.0f);
                float v10 = fmaxf(acc[mb][nb][2] + bs0, 0.0f);
                float v11 = fmaxf(acc[mb][nb][3] + bs1, 0.0f);
                fp16 h00, l00, h01, l01, h10, l10, h11, l11;
                split2h(v00, h00, l00); split2h(v01, h01, l01);
                split2h(v10, h10, l10); split2h(v11, h11, l11);
                *(__half2*)(outH + (size_t)r0 * outW + col) = __halves2half2(h00, h01);
                *(__half2*)(outL + (size_t)r0 * outW + col) = __halves2half2(l00, l01);
                *(__half2*)(outH + (size_t)r1 * outW + col) = __halves2half2(h10, h11);
                *(__half2*)(outL + (size_t)r1 * outW + col) = __halves2half2(l10, l11);
            } else {
                #pragma unroll
                for (int e = 0; e < 4; ++e) {
                    const int rr = (e < 2) ? r0 : r1;
                    const int cc = col + (e & 1);
                    if (rr < NROIS) {
                        const float v = acc[mb][nb][e] + bias[cc];
                        if (cc < 324)      outLoc[(size_t)rr * 324 + cc] = v;
                        else if (cc < 405) outSc[(size_t)rr * 81 + (cc - 324)] = v;
                    }
                }
            }
        }
    }
}

// ---------------- launch ------------------------------------------------------
extern "C" void kernel_launch(void* const* d_in, const int* in_sizes, int n_in,
                              void* d_out, int out_size)
{
    const float* f2   = (const float*)d_in[0];
    const float* f3   = (const float*)d_in[1];
    const float* f4   = (const float*)d_in[2];
    const float* f5   = (const float*)d_in[3];
    const float* rois = (const float*)d_in[4];
    const float* W1   = (const float*)d_in[6];
    const float* b1   = (const float*)d_in[7];
    const float* W2   = (const float*)d_in[8];
    const float* b2   = (const float*)d_in[9];
    const float* Wloc = (const float*)d_in[10];
    const float* bloc = (const float*)d_in[11];
    const float* Wsc  = (const float*)d_in[12];
    const float* bsc  = (const float*)d_in[13];

    float* out_loc = (float*)d_out;
    float* out_sc  = (float*)d_out + (size_t)NROIS * 324;

    fp16 *xh, *xl, *w1h, *w2h, *whh, *f1h, *f1l, *f2h_, *f2l_;
    float *bcomb, *ft2, *ft3, *ft4, *ft5;
    cudaGetSymbolAddress((void**)&xh,   g_xh);
    cudaGetSymbolAddress((void**)&xl,   g_xl);
    cudaGetSymbolAddress((void**)&w1h,  g_w1h);
    cudaGetSymbolAddress((void**)&w2h,  g_w2h);
    cudaGetSymbolAddress((void**)&whh,  g_whh);
    cudaGetSymbolAddress((void**)&f1h,  g_f1h);
    cudaGetSymbolAddress((void**)&f1l,  g_f1l);
    cudaGetSymbolAddress((void**)&f2h_, g_f2h);
    cudaGetSymbolAddress((void**)&f2l_, g_f2l);
    cudaGetSymbolAddress((void**)&bcomb, g_bcomb);
    cudaGetSymbolAddress((void**)&ft2,  g_ft2);
    cudaGetSymbolAddress((void**)&ft3,  g_ft3);
    cudaGetSymbolAddress((void**)&ft4,  g_ft4);
    cudaGetSymbolAddress((void**)&ft5,  g_ft5);

    cudaFuncSetAttribute(gemm_mma, cudaFuncAttributeMaxDynamicSharedMemorySize, GEMM_SMEM);
    cudaFuncSetAttribute(roi_align3, cudaFuncAttributeMaxDynamicSharedMemorySize, DFEAT * 4);

    // launch 1: fused prep
    prep_all<<<NB_W1 + NB_W2 + NB_HD + 1, 256>>>((const float4*)W1, (const float4*)W2,
                                                 Wloc, Wsc, bloc, bsc,
                                                 w1h, w2h, whh, bcomb);
    // launch 2: fused feature transpose
    ftrans_all<<<FT_NB2 + FT_NB3 + FT_NB4 + FT_NB5, dim3(32, 8)>>>(f2, f3, f4, f5,
                                                                   ft2, ft3, ft4, ft5);
    // launch 3: ROI align
    roi_align3<<<NROIS, 128, DFEAT * 4>>>(ft2, ft3, ft4, ft5, rois, xh, xl);

    // launch 4 (profiled): big GEMM
    gemm_mma<<<dim3(8, 16), 256, GEMM_SMEM>>>(xh, xl, w1h, b1, DFEAT, 1024, 0,
                                              f1h, f1l, nullptr, nullptr, 1024);
    // launch 5
    gemm_mma<<<dim3(8, 16), 256, GEMM_SMEM>>>(f1h, f1l, w2h, b2, 1024, 1024, 0,
                                              f2h_, f2l_, nullptr, nullptr, 1024);
    // launch 6
    gemm_mma<<<dim3(8, 7), 256, GEMM_SMEM>>>(f2h_, f2l_, whh, bcomb, 1024, 512, 1,
                                             nullptr, nullptr, out_loc, out_sc, 0);
}

// round 9
// speedup vs baseline: 7.8228x; 1.1104x over previous
#include <cuda_runtime.h>
#include <cuda_fp16.h>
#include <cstdint>

typedef __half fp16;

#define NROIS 1000
#define DFEAT 12544
#define MPAD  1024

// ---------------- persistent scratch (zero-init) -------------------------------
__device__ fp16 g_xh [MPAD * DFEAT];
__device__ fp16 g_xl [MPAD * DFEAT];
__device__ fp16 g_w1h[DFEAT * 1024];   // [K][N], single fp16
__device__ fp16 g_w2h[1024 * 1024];
__device__ fp16 g_whh[1024 * 512];     // combined heads [K=1024][N=512 padded]
__device__ fp16 g_f1h[MPAD * 1024];
__device__ fp16 g_f1l[MPAD * 1024];
__device__ fp16 g_f2h[MPAD * 1024];
__device__ fp16 g_f2l[MPAD * 1024];
__device__ float g_bcomb[512];
// transposed feature maps [H][W][C] fp32
__device__ float g_ft2[256 * 256 * 256];
__device__ float g_ft3[128 * 128 * 256];
__device__ float g_ft4[64 * 64 * 256];
__device__ float g_ft5[32 * 32 * 256];

// ---------------- helpers ------------------------------------------------------
__device__ __forceinline__ uint32_t s2u(const void* p) {
    uint32_t a;
    asm("{ .reg .u64 t; cvta.to.shared.u64 t, %1; cvt.u32.u64 %0, t; }" : "=r"(a) : "l"(p));
    return a;
}
__device__ __forceinline__ void cp16(uint32_t s, const void* g) {
    asm volatile("cp.async.cg.shared.global [%0], [%1], 16;" :: "r"(s), "l"(g) : "memory");
}
__device__ __forceinline__ void cp_commit() {
    asm volatile("cp.async.commit_group;" ::: "memory");
}
__device__ __forceinline__ void cp_wait2() {
    asm volatile("cp.async.wait_group 2;" ::: "memory");
}
__device__ __forceinline__ void ldsm4(uint32_t* r, uint32_t a) {
    asm volatile("ldmatrix.sync.aligned.m8n8.x4.shared.b16 {%0,%1,%2,%3}, [%4];"
                 : "=r"(r[0]), "=r"(r[1]), "=r"(r[2]), "=r"(r[3]) : "r"(a));
}
__device__ __forceinline__ void ldsm4t(uint32_t* r, uint32_t a) {
    asm volatile("ldmatrix.sync.aligned.m8n8.x4.trans.shared.b16 {%0,%1,%2,%3}, [%4];"
                 : "=r"(r[0]), "=r"(r[1]), "=r"(r[2]), "=r"(r[3]) : "r"(a));
}
__device__ __forceinline__ void mma16816(float* c, const uint32_t* a, const uint32_t* b) {
    asm volatile(
        "mma.sync.aligned.m16n8k16.row.col.f32.f16.f16.f32 "
        "{%0,%1,%2,%3}, {%4,%5,%6,%7}, {%8,%9}, {%0,%1,%2,%3};"
        : "+f"(c[0]), "+f"(c[1]), "+f"(c[2]), "+f"(c[3])
        : "r"(a[0]), "r"(a[1]), "r"(a[2]), "r"(a[3]), "r"(b[0]), "r"(b[1]));
}
__device__ __forceinline__ void split2h(float v, fp16& h, fp16& l) {
    h = __float2half_rn(v);
    l = __float2half_rn(v - __half2float(h));
}

// ---------------- fused prep: W1/W2 fp16 convert, heads pack, bias pack --------
#define NB_W1 12544
#define NB_W2 1024
#define NB_HD 2048
__global__ void prep_all(const float4* __restrict__ W1, const float4* __restrict__ W2,
                         const float* __restrict__ Wloc, const float* __restrict__ Wsc,
                         const float* __restrict__ bloc, const float* __restrict__ bsc,
                         fp16* __restrict__ w1h, fp16* __restrict__ w2h,
                         fp16* __restrict__ whh, float* __restrict__ bcomb)
{
    const int b = blockIdx.x;
    const int tid = threadIdx.x;
    if (b < NB_W1 + NB_W2) {
        const bool isW1 = (b < NB_W1);
        const int i = (isW1 ? b : b - NB_W1) * 256 + tid;
        const float4 v = isW1 ? W1[i] : W2[i];
        __half2* H2 = (__half2*)(isW1 ? w1h : w2h);
        H2[2 * i]     = __halves2half2(__float2half_rn(v.x), __float2half_rn(v.y));
        H2[2 * i + 1] = __halves2half2(__float2half_rn(v.z), __float2half_rn(v.w));
    } else if (b < NB_W1 + NB_W2 + NB_HD) {
        const int idx = (b - NB_W1 - NB_W2) * 256 + tid;
        const int k = idx >> 9, n = idx & 511;
        float v = 0.0f;
        if (n < 324)      v = Wloc[k * 324 + n];
        else if (n < 405) v = Wsc[k * 81 + (n - 324)];
        whh[idx] = __float2half_rn(v);
    } else {
        for (int i = tid; i < 512; i += 256)
            bcomb[i] = (i < 324) ? bloc[i] : ((i < 405) ? bsc[i - 324] : 0.0f);
    }
}

// ---------------- fused feature transpose [C][H][W] -> [H][W][C] ---------------
#define FT_NB2 16384
#define FT_NB3 4096
#define FT_NB4 1024
#define FT_NB5 256
__global__ void ftrans_all(const float* __restrict__ f2, const float* __restrict__ f3,
                           const float* __restrict__ f4, const float* __restrict__ f5,
                           float* __restrict__ t2o, float* __restrict__ t3o,
                           float* __restrict__ t4o, float* __restrict__ t5o)
{
    __shared__ float t[32][33];
    int b = blockIdx.x;
    const float* f; float* ft; int H;
    if (b < FT_NB2)                         { f = f2; ft = t2o; H = 256; }
    else if (b < FT_NB2 + FT_NB3)           { b -= FT_NB2; f = f3; ft = t3o; H = 128; }
    else if (b < FT_NB2 + FT_NB3 + FT_NB4)  { b -= FT_NB2 + FT_NB3; f = f4; ft = t4o; H = 64; }
    else                                    { b -= FT_NB2 + FT_NB3 + FT_NB4; f = f5; ft = t5o; H = 32; }
    const int W = H;
    const int wT = H >> 5;
    const int w0 = (b % wT) * 32;
    const int h  = (b / wT) % H;
    const int c0 = (b / (wT * H)) * 32;
    const int tx = threadIdx.x, ty = threadIdx.y;
    #pragma unroll
    for (int r = 0; r < 4; ++r) {
        const int c = c0 + ty + r * 8;
        t[ty + r * 8][tx] = f[((size_t)c * H + h) * W + w0 + tx];
    }
    __syncthreads();
    #pragma unroll
    for (int r = 0; r < 4; ++r) {
        const int w = w0 + ty + r * 8;
        ft[((size_t)h * W + w) * 256 + c0 + tx] = t[tx][ty + r * 8];
    }
}

// ---------------- ROI align, float4 gather (4 channels/thread) -----------------
__global__ void roi_align3(const float* __restrict__ ft2, const float* __restrict__ ft3,
                           const float* __restrict__ ft4, const float* __restrict__ ft5,
                           const float* __restrict__ rois,
                           fp16* __restrict__ xh, fp16* __restrict__ xl)
{
    extern __shared__ float s[];   // 12544 floats
    const int r = blockIdx.x;
    const int tid = threadIdx.x;
    const int cg = tid & 63;
    const int half = tid >> 6;

    __shared__ int   s_y0[14], s_y1[14], s_x0[14], s_x1[14];
    __shared__ float s_ly[14], s_lx[14];

    const float ry1 = rois[r * 4 + 0];
    const float rx1 = rois[r * 4 + 1];
    const float ry2 = rois[r * 4 + 2];
    const float rx2 = rois[r * 4 + 3];

    const float hh = ry2 - ry1 + 1.0f;
    const float ww = rx2 - rx1 + 1.0f;
    float lv = floorf(logf(sqrtf(hh * ww) / 224.0f) / 0.693147f + 4.0f);
    lv = fminf(fmaxf(lv, 2.0f), 5.0f);
    const int lvl = (int)lv;

    int H; const float* ft;
    if (lvl == 2)      { H = 256; ft = ft2; }
    else if (lvl == 3) { H = 128; ft = ft3; }
    else if (lvl == 4) { H = 64;  ft = ft4; }
    else               { H = 32;  ft = ft5; }
    const int W = H;

    const float fm = (float)(H - 1);
    const float gy1 = ry1 * fm / 1023.0f;
    const float gx1 = rx1 * fm / 1023.0f;
    const float gy2 = ry2 * fm / 1023.0f;
    const float gx2 = rx2 * fm / 1023.0f;
    const float hs = (gy2 - gy1) / 14.0f;
    const float ws = (gx2 - gx1) / 14.0f;

    if (tid < 14) {
        const float cy = ((float)tid + 0.5f) * hs + gy1;
        const float fl = floorf(cy);
        s_y0[tid] = (int)fl;
        s_y1[tid] = (int)ceilf(cy);
        s_ly[tid] = cy - fl;
    } else if (tid < 28) {
        const int j = tid - 14;
        const float cx = ((float)j + 0.5f) * ws + gx1;
        const float fl = floorf(cx);
        s_x0[j] = (int)fl;
        s_x1[j] = (int)ceilf(cx);
        s_lx[j] = cx - fl;
    }
    __syncthreads();

    const float4* __restrict__ fb = (const float4*)ft + cg;

    const int pyBeg = half ? 4 : 0;
    const int pyEnd = half ? 7 : 4;

    for (int py = pyBeg; py < pyEnd; ++py) {
        float4 m[7];
        #pragma unroll
        for (int i = 0; i < 7; ++i) m[i] = make_float4(-3.0e38f, -3.0e38f, -3.0e38f, -3.0e38f);
        #pragma unroll
        for (int a = 0; a < 2; ++a) {
            const int sy = 2 * py + a;
            const float ly = s_ly[sy];
            const float oly = 1.0f - ly;
            const float4* __restrict__ r0 = fb + (size_t)(s_y0[sy] * W) * 64;
            const float4* __restrict__ r1 = fb + (size_t)(s_y1[sy] * W) * 64;
            #pragma unroll
            for (int sx = 0; sx < 14; ++sx) {
                const int x0 = s_x0[sx] * 64;
                const int x1 = s_x1[sx] * 64;
                const float lx = s_lx[sx];
                const float olx = 1.0f - lx;
                const float w00 = oly * olx, w01 = oly * lx;
                const float w10 = ly * olx,  w11 = ly * lx;
                const float4 v00 = r0[x0];
                const float4 v01 = r0[x1];
                const float4 v10 = r1[x0];
                const float4 v11 = r1[x1];
                float4& mm = m[sx >> 1];
                mm.x = fmaxf(mm.x, v00.x * w00 + v10.x * w10 + v01.x * w01 + v11.x * w11);
                mm.y = fmaxf(mm.y, v00.y * w00 + v10.y * w10 + v01.y * w01 + v11.y * w11);
                mm.z = fmaxf(mm.z, v00.z * w00 + v10.z * w10 + v01.z * w01 + v11.z * w11);
                mm.w = fmaxf(mm.w, v00.w * w00 + v10.w * w10 + v01.w * w01 + v11.w * w11);
            }
        }
        #pragma unroll
        for (int px = 0; px < 7; ++px) {
            const int cell = py * 7 + px;
            s[(4 * cg + 0) * 49 + cell] = m[px].x;
            s[(4 * cg + 1) * 49 + cell] = m[px].y;
            s[(4 * cg + 2) * 49 + cell] = m[px].z;
            s[(4 * cg + 3) * 49 + cell] = m[px].w;
        }
    }
    __syncthreads();

    const size_t ob = (size_t)r * DFEAT;
    for (int i = tid * 2; i < DFEAT; i += 256) {
        const float v0 = s[i], v1 = s[i + 1];
        fp16 h0, l0, h1, l1;
        split2h(v0, h0, l0);
        split2h(v1, h1, l1);
        *(__half2*)(xh + ob + i) = __halves2half2(h0, h1);
        *(__half2*)(xl + ob + i) = __halves2half2(l0, l1);
    }
}

// ---------------- HMMA GEMM, 2-term fp16, GBK=64, 256 threads ------------------
// A: [M][K] fp16 hi/lo (K-major). B: [K][N] fp16 (N-major, single).
// Stage 40KB: Ah[128][64]@0, Al@16384, Bh[64][64]@32768. 128B rows, chunk ^= row&7.
#define GBK 64
#define BUF_SZ 40960
#define STG 4
#define GEMM_SMEM (STG * BUF_SZ)

__global__ __launch_bounds__(256) void gemm_mma(
    const fp16* __restrict__ Ah, const fp16* __restrict__ Al,
    const fp16* __restrict__ Bh,
    const float* __restrict__ bias, int K, int N, int mode,
    fp16* __restrict__ outH, fp16* __restrict__ outL,
    float* __restrict__ outLoc, float* __restrict__ outSc, int outW)
{
    extern __shared__ char smem[];
    const uint32_t smU = s2u(smem);
    const int t   = threadIdx.x;
    const int l   = t & 31;
    const int wid = t >> 5;                 // 0..7
    const int wm  = (wid & 3) * 32;         // 4 warps over M=128
    const int wn  = (wid >> 2) * 32;        // 2 warps over N=64
    const int rowBase = blockIdx.x * 128;
    const int colBase = blockIdx.y * 64;
    const size_t K2 = (size_t)K * 2;

    // loader geometry: row = t>>3 (0..31, then +32 groups), chunk c = t&7
    const int ldRow = t >> 3;
    const int ldC   = t & 7;
    const uint32_t ldSel  = (uint32_t)(ldRow & 7);   // row+32 keeps low 3 bits
    const uint32_t sOff0  = ldRow * 128 + (((uint32_t)ldC ^ ldSel) << 4);

    // A global: rows rowBase+ldRow (+32,+64,+96), byte col = ldC*16 + kt*128
    const char* pAh = (const char*)(Ah + (size_t)(rowBase + ldRow) * K) + ldC * 16;
    const char* pAl = (const char*)(Al + (size_t)(rowBase + ldRow) * K) + ldC * 16;
    // B global: k rows kt*64 + ldRow (+32), byte col = colBase*2 + ldC*16
    const char* pB  = (const char*)(Bh + (size_t)ldRow * N + colBase) + ldC * 16;
    const size_t bStep = (size_t)GBK * N * 2;
    const size_t aRowStep32 = 32 * K2;
    const size_t bRowStep32 = 32 * (size_t)N * 2;

    float acc[2][4][4];
    #pragma unroll
    for (int mb = 0; mb < 2; ++mb)
        #pragma unroll
        for (int nb = 0; nb < 4; ++nb)
            #pragma unroll
            for (int i = 0; i < 4; ++i) acc[mb][nb][i] = 0.0f;

    // A ldmatrix geometry (rows = wm + (l&15), chunks = 2*ks + (l>>4))
    const uint32_t aRowAddr = (wm + (l & 15)) * 128;
    const uint32_t aSel = (uint32_t)((l & 15) & 7);
    const uint32_t aCk0 = (l >> 4);
    // B ldmatrix.trans geometry
    const uint32_t bLane = l & 15;
    const uint32_t bNg   = (uint32_t)(l >> 4);
    const uint32_t bCk0  = ((uint32_t)wn >> 3) + bNg;
    const uint32_t bCk1  = bCk0 + 2;

    const int nt = K / GBK;

    auto issue = [&](int kt) {
        const uint32_t bu = smU + (kt % STG) * BUF_SZ;
        const size_t ka = (size_t)kt * 128;     // bytes along K
        const size_t kb = (size_t)kt * bStep;
        #pragma unroll
        for (int i = 0; i < 4; ++i)
            cp16(bu + sOff0 + i * 4096, pAh + ka + i * aRowStep32);
        #pragma unroll
        for (int i = 0; i < 4; ++i)
            cp16(bu + 16384 + sOff0 + i * 4096, pAl + ka + i * aRowStep32);
        #pragma unroll
        for (int i = 0; i < 2; ++i)
            cp16(bu + 32768 + sOff0 + i * 4096, pB + kb + i * bRowStep32);
        cp_commit();
    };

    issue(0);
    if (nt > 1) issue(1); else cp_commit();
    if (nt > 2) issue(2); else cp_commit();

    for (int kt = 0; kt < nt; ++kt) {
        cp_wait2();
        __syncthreads();
        if (kt + 3 < nt) issue(kt + 3);
        else cp_commit();

        const uint32_t bu = smU + (kt % STG) * BUF_SZ;
        const uint32_t aB = bu + aRowAddr;

        #pragma unroll
        for (int ks = 0; ks < 4; ++ks) {
            const uint32_t aOff = (((aCk0 + 2 * ks) ^ aSel) << 4);
            const uint32_t rowB = ks * 16 + bLane;
            const uint32_t rx = rowB & 7;
            const uint32_t bRow = rowB * 128;

            uint32_t ah[2][4], al[2][4], bh[2][4];
            ldsm4(ah[0], aB + aOff);
            ldsm4(ah[1], aB + 2048 + aOff);
            ldsm4(al[0], aB + 16384 + aOff);
            ldsm4(al[1], aB + 18432 + aOff);
            ldsm4t(bh[0], bu + 32768 + bRow + (((bCk0 ^ rx)) << 4));
            ldsm4t(bh[1], bu + 32768 + bRow + (((bCk1 ^ rx)) << 4));

            #pragma unroll
            for (int mb = 0; mb < 2; ++mb)
                #pragma unroll
                for (int nb = 0; nb < 4; ++nb)
                    mma16816(acc[mb][nb], ah[mb], &bh[nb >> 1][2 * (nb & 1)]);
            #pragma unroll
            for (int mb = 0; mb < 2; ++mb)
                #pragma unroll
                for (int nb = 0; nb < 4; ++nb)
                    mma16816(acc[mb][nb], al[mb], &bh[nb >> 1][2 * (nb & 1)]);
        }
    }

    // epilogue
    const int q = l >> 2, idx = l & 3;
    #pragma unroll
    for (int mb = 0; mb < 2; ++mb) {
        const int r0 = rowBase + wm + mb * 16 + q;
        const int r1 = r0 + 8;
        #pragma unroll
        for (int nb = 0; nb < 4; ++nb) {
            const int col = colBase + wn + nb * 8 + 2 * idx;
            if (mode == 0) {
                const float bs0 = bias[col], bs1 = bias[col + 1];
                float v00 = fmaxf(acc[mb][nb][0] + bs0, 0.0f);
                float v01 = fmaxf(acc[mb][nb][1] + bs1, 0.0f);
                float v10 = fmaxf(acc[mb][nb][2] + bs0, 0.0f);
                float v11 = fmaxf(acc[mb][nb][3] + bs1, 0.0f);
                fp16 h00, l00, h01, l01, h10, l10, h11, l11;
                split2h(v00, h00, l00); split2h(v01, h01, l01);
                split2h(v10, h10, l10); split2h(v11, h11, l11);
                *(__half2*)(outH + (size_t)r0 * outW + col) = __halves2half2(h00, h01);
                *(__half2*)(outL + (size_t)r0 * outW + col) = __halves2half2(l00, l01);
                *(__half2*)(outH + (size_t)r1 * outW + col) = __halves2half2(h10, h11);
                *(__half2*)(outL + (size_t)r1 * outW + col) = __halves2half2(l10, l11);
            } else {
                #pragma unroll
                for (int e = 0; e < 4; ++e) {
                    const int rr = (e < 2) ? r0 : r1;
                    const int cc = col + (e & 1);
                    if (rr < NROIS) {
                        const float v = acc[mb][nb][e] + bias[cc];
                        if (cc < 324)      outLoc[(size_t)rr * 324 + cc] = v;
                        else if (cc < 405) outSc[(size_t)rr * 81 + (cc - 324)] = v;
                    }
                }
            }
        }
    }
}

// ---------------- launch ------------------------------------------------------
extern "C" void kernel_launch(void* const* d_in, const int* in_sizes, int n_in,
                              void* d_out, int out_size)
{
    const float* f2   = (const float*)d_in[0];
    const float* f3   = (const float*)d_in[1];
    const float* f4   = (const float*)d_in[2];
    const float* f5   = (const float*)d_in[3];
    const float* rois = (const float*)d_in[4];
    const float* W1   = (const float*)d_in[6];
    const float* b1   = (const float*)d_in[7];
    const float* W2   = (const float*)d_in[8];
    const float* b2   = (const float*)d_in[9];
    const float* Wloc = (const float*)d_in[10];
    const float* bloc = (const float*)d_in[11];
    const float* Wsc  = (const float*)d_in[12];
    const float* bsc  = (const float*)d_in[13];

    float* out_loc = (float*)d_out;
    float* out_sc  = (float*)d_out + (size_t)NROIS * 324;

    fp16 *xh, *xl, *w1h, *w2h, *whh, *f1h, *f1l, *f2h_, *f2l_;
    float *bcomb, *ft2, *ft3, *ft4, *ft5;
    cudaGetSymbolAddress((void**)&xh,   g_xh);
    cudaGetSymbolAddress((void**)&xl,   g_xl);
    cudaGetSymbolAddress((void**)&w1h,  g_w1h);
    cudaGetSymbolAddress((void**)&w2h,  g_w2h);
    cudaGetSymbolAddress((void**)&whh,  g_whh);
    cudaGetSymbolAddress((void**)&f1h,  g_f1h);
    cudaGetSymbolAddress((void**)&f1l,  g_f1l);
    cudaGetSymbolAddress((void**)&f2h_, g_f2h);
    cudaGetSymbolAddress((void**)&f2l_, g_f2l);
    cudaGetSymbolAddress((void**)&bcomb, g_bcomb);
    cudaGetSymbolAddress((void**)&ft2,  g_ft2);
    cudaGetSymbolAddress((void**)&ft3,  g_ft3);
    cudaGetSymbolAddress((void**)&ft4,  g_ft4);
    cudaGetSymbolAddress((void**)&ft5,  g_ft5);

    cudaFuncSetAttribute(gemm_mma, cudaFuncAttributeMaxDynamicSharedMemorySize, GEMM_SMEM);
    cudaFuncSetAttribute(roi_align3, cudaFuncAttributeMaxDynamicSharedMemorySize, DFEAT * 4);

    // launch 1: fused prep
    prep_all<<<NB_W1 + NB_W2 + NB_HD + 1, 256>>>((const float4*)W1, (const float4*)W2,
                                                 Wloc, Wsc, bloc, bsc,
                                                 w1h, w2h, whh, bcomb);
    // launch 2: fused feature transpose
    ftrans_all<<<FT_NB2 + FT_NB3 + FT_NB4 + FT_NB5, dim3(32, 8)>>>(f2, f3, f4, f5,
                                                                   ft2, ft3, ft4, ft5);
    // launch 3: ROI align
    roi_align3<<<NROIS, 128, DFEAT * 4>>>(ft2, ft3, ft4, ft5, rois, xh, xl);

    // launch 4 (profiled): big GEMM
    gemm_mma<<<dim3(8, 16), 256, GEMM_SMEM>>>(xh, xl, w1h, b1, DFEAT, 1024, 0,
                                              f1h, f1l, nullptr, nullptr, 1024);
    // launch 5
    gemm_mma<<<dim3(8, 16), 256, GEMM_SMEM>>>(f1h, f1l, w2h, b2, 1024, 1024, 0,
                                              f2h_, f2l_, nullptr, nullptr, 1024);
    // launch 6
    gemm_mma<<<dim3(8, 7), 256, GEMM_SMEM>>>(f2h_, f2l_, whh, bcomb, 1024, 512, 1,
                                             nullptr, nullptr, out_loc, out_sc, 0);
}

// round 10
// speedup vs baseline: 8.5566x; 1.0938x over previous
#include <cuda_runtime.h>
#include <cuda_fp16.h>
#include <cstdint>

typedef __half fp16;

#define NROIS 1000
#define DFEAT 12544
#define MPAD  1024

// ---------------- persistent scratch (zero-init) -------------------------------
__device__ fp16 g_xh [MPAD * DFEAT];
__device__ fp16 g_xl [MPAD * DFEAT];
__device__ fp16 g_w1h[DFEAT * 1024];   // [K][N], single fp16
__device__ fp16 g_w2h[1024 * 1024];
__device__ fp16 g_whh[1024 * 512];     // combined heads [K=1024][N=512 padded]
__device__ fp16 g_f1h[MPAD * 1024];
__device__ fp16 g_f1l[MPAD * 1024];
__device__ fp16 g_f2h[MPAD * 1024];
__device__ fp16 g_f2l[MPAD * 1024];
__device__ float g_bcomb[512];
// transposed feature maps [H][W][C] fp16
__device__ fp16 g_ft2[256 * 256 * 256];
__device__ fp16 g_ft3[128 * 128 * 256];
__device__ fp16 g_ft4[64 * 64 * 256];
__device__ fp16 g_ft5[32 * 32 * 256];

// ---------------- helpers ------------------------------------------------------
__device__ __forceinline__ uint32_t s2u(const void* p) {
    uint32_t a;
    asm("{ .reg .u64 t; cvta.to.shared.u64 t, %1; cvt.u32.u64 %0, t; }" : "=r"(a) : "l"(p));
    return a;
}
__device__ __forceinline__ void cp16(uint32_t s, const void* g) {
    asm volatile("cp.async.cg.shared.global [%0], [%1], 16;" :: "r"(s), "l"(g) : "memory");
}
__device__ __forceinline__ void cp_commit() {
    asm volatile("cp.async.commit_group;" ::: "memory");
}
__device__ __forceinline__ void cp_wait2() {
    asm volatile("cp.async.wait_group 2;" ::: "memory");
}
__device__ __forceinline__ void ldsm4(uint32_t* r, uint32_t a) {
    asm volatile("ldmatrix.sync.aligned.m8n8.x4.shared.b16 {%0,%1,%2,%3}, [%4];"
                 : "=r"(r[0]), "=r"(r[1]), "=r"(r[2]), "=r"(r[3]) : "r"(a));
}
__device__ __forceinline__ void ldsm4t(uint32_t* r, uint32_t a) {
    asm volatile("ldmatrix.sync.aligned.m8n8.x4.trans.shared.b16 {%0,%1,%2,%3}, [%4];"
                 : "=r"(r[0]), "=r"(r[1]), "=r"(r[2]), "=r"(r[3]) : "r"(a));
}
__device__ __forceinline__ void mma16816(float* c, const uint32_t* a, const uint32_t* b) {
    asm volatile(
        "mma.sync.aligned.m16n8k16.row.col.f32.f16.f16.f32 "
        "{%0,%1,%2,%3}, {%4,%5,%6,%7}, {%8,%9}, {%0,%1,%2,%3};"
        : "+f"(c[0]), "+f"(c[1]), "+f"(c[2]), "+f"(c[3])
        : "r"(a[0]), "r"(a[1]), "r"(a[2]), "r"(a[3]), "r"(b[0]), "r"(b[1]));
}
__device__ __forceinline__ void split2h(float v, fp16& h, fp16& l) {
    h = __float2half_rn(v);
    l = __float2half_rn(v - __half2float(h));
}

// ---------------- fused prep: W1/W2 fp16 convert, heads pack, bias pack --------
#define NB_W1 12544
#define NB_W2 1024
#define NB_HD 2048
__global__ void prep_all(const float4* __restrict__ W1, const float4* __restrict__ W2,
                         const float* __restrict__ Wloc, const float* __restrict__ Wsc,
                         const float* __restrict__ bloc, const float* __restrict__ bsc,
                         fp16* __restrict__ w1h, fp16* __restrict__ w2h,
                         fp16* __restrict__ whh, float* __restrict__ bcomb)
{
    const int b = blockIdx.x;
    const int tid = threadIdx.x;
    if (b < NB_W1 + NB_W2) {
        const bool isW1 = (b < NB_W1);
        const int i = (isW1 ? b : b - NB_W1) * 256 + tid;
        const float4 v = isW1 ? W1[i] : W2[i];
        __half2* H2 = (__half2*)(isW1 ? w1h : w2h);
        H2[2 * i]     = __halves2half2(__float2half_rn(v.x), __float2half_rn(v.y));
        H2[2 * i + 1] = __halves2half2(__float2half_rn(v.z), __float2half_rn(v.w));
    } else if (b < NB_W1 + NB_W2 + NB_HD) {
        const int idx = (b - NB_W1 - NB_W2) * 256 + tid;
        const int k = idx >> 9, n = idx & 511;
        float v = 0.0f;
        if (n < 324)      v = Wloc[k * 324 + n];
        else if (n < 405) v = Wsc[k * 81 + (n - 324)];
        whh[idx] = __float2half_rn(v);
    } else {
        for (int i = tid; i < 512; i += 256)
            bcomb[i] = (i < 324) ? bloc[i] : ((i < 405) ? bsc[i - 324] : 0.0f);
    }
}

// ---------------- fused feature transpose [C][H][W] fp32 -> [H][W][C] fp16 -----
#define FT_NB2 16384
#define FT_NB3 4096
#define FT_NB4 1024
#define FT_NB5 256
__global__ void ftrans_all(const float* __restrict__ f2, const float* __restrict__ f3,
                           const float* __restrict__ f4, const float* __restrict__ f5,
                           fp16* __restrict__ t2o, fp16* __restrict__ t3o,
                           fp16* __restrict__ t4o, fp16* __restrict__ t5o)
{
    __shared__ float t[32][33];
    int b = blockIdx.x;
    const float* f; fp16* ft; int H;
    if (b < FT_NB2)                         { f = f2; ft = t2o; H = 256; }
    else if (b < FT_NB2 + FT_NB3)           { b -= FT_NB2; f = f3; ft = t3o; H = 128; }
    else if (b < FT_NB2 + FT_NB3 + FT_NB4)  { b -= FT_NB2 + FT_NB3; f = f4; ft = t4o; H = 64; }
    else                                    { b -= FT_NB2 + FT_NB3 + FT_NB4; f = f5; ft = t5o; H = 32; }
    const int W = H;
    const int wT = H >> 5;
    const int w0 = (b % wT) * 32;
    const int h  = (b / wT) % H;
    const int c0 = (b / (wT * H)) * 32;
    const int tx = threadIdx.x, ty = threadIdx.y;
    #pragma unroll
    for (int r = 0; r < 4; ++r) {
        const int c = c0 + ty + r * 8;
        t[ty + r * 8][tx] = f[((size_t)c * H + h) * W + w0 + tx];
    }
    __syncthreads();
    #pragma unroll
    for (int r = 0; r < 4; ++r) {
        const int w = w0 + ty + r * 8;
        ft[((size_t)h * W + w) * 256 + c0 + tx] = __float2half_rn(t[tx][ty + r * 8]);
    }
}

// ---------------- ROI align, fp16 uint2 gather (4 channels/thread) -------------
__global__ void roi_align3(const fp16* __restrict__ ft2, const fp16* __restrict__ ft3,
                           const fp16* __restrict__ ft4, const fp16* __restrict__ ft5,
                           const float* __restrict__ rois,
                           fp16* __restrict__ xh, fp16* __restrict__ xl)
{
    extern __shared__ float s[];   // 12544 floats
    const int r = blockIdx.x;
    const int tid = threadIdx.x;
    const int cg = tid & 63;
    const int half = tid >> 6;

    __shared__ int   s_y0[14], s_y1[14], s_x0[14], s_x1[14];
    __shared__ float s_ly[14], s_lx[14];

    const float ry1 = rois[r * 4 + 0];
    const float rx1 = rois[r * 4 + 1];
    const float ry2 = rois[r * 4 + 2];
    const float rx2 = rois[r * 4 + 3];

    const float hh = ry2 - ry1 + 1.0f;
    const float ww = rx2 - rx1 + 1.0f;
    float lv = floorf(logf(sqrtf(hh * ww) / 224.0f) / 0.693147f + 4.0f);
    lv = fminf(fmaxf(lv, 2.0f), 5.0f);
    const int lvl = (int)lv;

    int H; const fp16* ft;
    if (lvl == 2)      { H = 256; ft = ft2; }
    else if (lvl == 3) { H = 128; ft = ft3; }
    else if (lvl == 4) { H = 64;  ft = ft4; }
    else               { H = 32;  ft = ft5; }
    const int W = H;

    const float fm = (float)(H - 1);
    const float gy1 = ry1 * fm / 1023.0f;
    const float gx1 = rx1 * fm / 1023.0f;
    const float gy2 = ry2 * fm / 1023.0f;
    const float gx2 = rx2 * fm / 1023.0f;
    const float hs = (gy2 - gy1) / 14.0f;
    const float ws = (gx2 - gx1) / 14.0f;

    if (tid < 14) {
        const float cy = ((float)tid + 0.5f) * hs + gy1;
        const float fl = floorf(cy);
        s_y0[tid] = (int)fl;
        s_y1[tid] = (int)ceilf(cy);
        s_ly[tid] = cy - fl;
    } else if (tid < 28) {
        const int j = tid - 14;
        const float cx = ((float)j + 0.5f) * ws + gx1;
        const float fl = floorf(cx);
        s_x0[j] = (int)fl;
        s_x1[j] = (int)ceilf(cx);
        s_lx[j] = cx - fl;
    }
    __syncthreads();

    const fp16* __restrict__ fb = ft + 4 * cg;   // channels 4cg..4cg+3

    const int pyBeg = half ? 4 : 0;
    const int pyEnd = half ? 7 : 4;

    for (int py = pyBeg; py < pyEnd; ++py) {
        float4 m[7];
        #pragma unroll
        for (int i = 0; i < 7; ++i) m[i] = make_float4(-3.0e38f, -3.0e38f, -3.0e38f, -3.0e38f);
        #pragma unroll
        for (int a = 0; a < 2; ++a) {
            const int sy = 2 * py + a;
            const float ly = s_ly[sy];
            const float oly = 1.0f - ly;
            const fp16* __restrict__ r0 = fb + (size_t)(s_y0[sy] * W) * 256;
            const fp16* __restrict__ r1 = fb + (size_t)(s_y1[sy] * W) * 256;
            #pragma unroll
            for (int sx = 0; sx < 14; ++sx) {
                const int x0 = s_x0[sx] * 256;
                const int x1 = s_x1[sx] * 256;
                const float lx = s_lx[sx];
                const float olx = 1.0f - lx;
                const float w00 = oly * olx, w01 = oly * lx;
                const float w10 = ly * olx,  w11 = ly * lx;
                const uint2 u00 = *(const uint2*)(r0 + x0);
                const uint2 u01 = *(const uint2*)(r0 + x1);
                const uint2 u10 = *(const uint2*)(r1 + x0);
                const uint2 u11 = *(const uint2*)(r1 + x1);
                const float2 a00 = __half22float2(*(const __half2*)&u00.x);
                const float2 b00 = __half22float2(*(const __half2*)&u00.y);
                const float2 a01 = __half22float2(*(const __half2*)&u01.x);
                const float2 b01 = __half22float2(*(const __half2*)&u01.y);
                const float2 a10 = __half22float2(*(const __half2*)&u10.x);
                const float2 b10 = __half22float2(*(const __half2*)&u10.y);
                const float2 a11 = __half22float2(*(const __half2*)&u11.x);
                const float2 b11 = __half22float2(*(const __half2*)&u11.y);
                float4& mm = m[sx >> 1];
                mm.x = fmaxf(mm.x, a00.x * w00 + a10.x * w10 + a01.x * w01 + a11.x * w11);
                mm.y = fmaxf(mm.y, a00.y * w00 + a10.y * w10 + a01.y * w01 + a11.y * w11);
                mm.z = fmaxf(mm.z, b00.x * w00 + b10.x * w10 + b01.x * w01 + b11.x * w11);
                mm.w = fmaxf(mm.w, b00.y * w00 + b10.y * w10 + b01.y * w01 + b11.y * w11);
            }
        }
        #pragma unroll
        for (int px = 0; px < 7; ++px) {
            const int cell = py * 7 + px;
            s[(4 * cg + 0) * 49 + cell] = m[px].x;
            s[(4 * cg + 1) * 49 + cell] = m[px].y;
            s[(4 * cg + 2) * 49 + cell] = m[px].z;
            s[(4 * cg + 3) * 49 + cell] = m[px].w;
        }
    }
    __syncthreads();

    const size_t ob = (size_t)r * DFEAT;
    for (int i = tid * 2; i < DFEAT; i += 256) {
        const float v0 = s[i], v1 = s[i + 1];
        fp16 h0, l0, h1, l1;
        split2h(v0, h0, l0);
        split2h(v1, h1, l1);
        *(__half2*)(xh + ob + i) = __halves2half2(h0, h1);
        *(__half2*)(xl + ob + i) = __halves2half2(l0, l1);
    }
}

// ---------------- HMMA GEMM, 2-term fp16, GBK=64, fragment double-buffering ----
// A: [M][K] fp16 hi/lo (K-major). B: [K][N] fp16 (N-major, single).
// Stage 40KB: Ah[128][64]@0, Al@16384, Bh[64][64]@32768. 128B rows, chunk ^= row&7.
#define GBK 64
#define BUF_SZ 40960
#define STG 4
#define GEMM_SMEM (STG * BUF_SZ)

__global__ __launch_bounds__(256) void gemm_mma(
    const fp16* __restrict__ Ah, const fp16* __restrict__ Al,
    const fp16* __restrict__ Bh,
    const float* __restrict__ bias, int K, int N, int mode,
    fp16* __restrict__ outH, fp16* __restrict__ outL,
    float* __restrict__ outLoc, float* __restrict__ outSc, int outW)
{
    extern __shared__ char smem[];
    const uint32_t smU = s2u(smem);
    const int t   = threadIdx.x;
    const int l   = t & 31;
    const int wid = t >> 5;                 // 0..7
    const int wm  = (wid & 3) * 32;         // 4 warps over M=128
    const int wn  = (wid >> 2) * 32;        // 2 warps over N=64
    const int rowBase = blockIdx.x * 128;
    const int colBase = blockIdx.y * 64;
    const size_t K2 = (size_t)K * 2;

    // loader geometry
    const int ldRow = t >> 3;
    const int ldC   = t & 7;
    const uint32_t ldSel  = (uint32_t)(ldRow & 7);
    const uint32_t sOff0  = ldRow * 128 + (((uint32_t)ldC ^ ldSel) << 4);

    const char* pAh = (const char*)(Ah + (size_t)(rowBase + ldRow) * K) + ldC * 16;
    const char* pAl = (const char*)(Al + (size_t)(rowBase + ldRow) * K) + ldC * 16;
    const char* pB  = (const char*)(Bh + (size_t)ldRow * N + colBase) + ldC * 16;
    const size_t bStep = (size_t)GBK * N * 2;
    const size_t aRowStep32 = 32 * K2;
    const size_t bRowStep32 = 32 * (size_t)N * 2;

    float acc[2][4][4];
    #pragma unroll
    for (int mb = 0; mb < 2; ++mb)
        #pragma unroll
        for (int nb = 0; nb < 4; ++nb)
            #pragma unroll
            for (int i = 0; i < 4; ++i) acc[mb][nb][i] = 0.0f;

    // ldmatrix geometry
    const uint32_t aRowAddr = (wm + (l & 15)) * 128;
    const uint32_t aSel = (uint32_t)((l & 15) & 7);
    const uint32_t aCk0 = (l >> 4);
    const uint32_t bLane = l & 15;
    const uint32_t bNg   = (uint32_t)(l >> 4);
    const uint32_t bCk0  = ((uint32_t)wn >> 3) + bNg;
    const uint32_t bCk1  = bCk0 + 2;

    const int nt = K / GBK;

    auto issue = [&](int kt) {
        const uint32_t bu = smU + (kt % STG) * BUF_SZ;
        const size_t ka = (size_t)kt * 128;
        const size_t kb = (size_t)kt * bStep;
        #pragma unroll
        for (int i = 0; i < 4; ++i)
            cp16(bu + sOff0 + i * 4096, pAh + ka + i * aRowStep32);
        #pragma unroll
        for (int i = 0; i < 4; ++i)
            cp16(bu + 16384 + sOff0 + i * 4096, pAl + ka + i * aRowStep32);
        #pragma unroll
        for (int i = 0; i < 2; ++i)
            cp16(bu + 32768 + sOff0 + i * 4096, pB + kb + i * bRowStep32);
        cp_commit();
    };

    issue(0);
    if (nt > 1) issue(1); else cp_commit();
    if (nt > 2) issue(2); else cp_commit();

    // double-buffered fragments
    uint32_t ah[2][2][4], al[2][2][4], bh[2][2][4];

    for (int kt = 0; kt < nt; ++kt) {
        cp_wait2();
        __syncthreads();
        if (kt + 3 < nt) issue(kt + 3);
        else cp_commit();

        const uint32_t bu = smU + (kt % STG) * BUF_SZ;
        const uint32_t aB = bu + aRowAddr;
        const uint32_t bB = bu + 32768;

        // prologue: fragments for ks=0
        {
            const uint32_t aOff = ((aCk0 ^ aSel) << 4);
            const uint32_t rowB = bLane;
            const uint32_t rx = rowB & 7;
            const uint32_t bRow = rowB * 128;
            ldsm4(ah[0][0], aB + aOff);
            ldsm4(ah[0][1], aB + 2048 + aOff);
            ldsm4(al[0][0], aB + 16384 + aOff);
            ldsm4(al[0][1], aB + 18432 + aOff);
            ldsm4t(bh[0][0], bB + bRow + (((bCk0 ^ rx)) << 4));
            ldsm4t(bh[0][1], bB + bRow + (((bCk1 ^ rx)) << 4));
        }

        #pragma unroll
        for (int ks = 0; ks < 4; ++ks) {
            const int cur = ks & 1;
            const int nxt = cur ^ 1;
            if (ks < 3) {
                const uint32_t aOff = (((aCk0 + 2 * (ks + 1)) ^ aSel) << 4);
                const uint32_t rowB = (ks + 1) * 16 + bLane;
                const uint32_t rx = rowB & 7;
                const uint32_t bRow = rowB * 128;
                ldsm4(ah[nxt][0], aB + aOff);
                ldsm4(ah[nxt][1], aB + 2048 + aOff);
                ldsm4(al[nxt][0], aB + 16384 + aOff);
                ldsm4(al[nxt][1], aB + 18432 + aOff);
                ldsm4t(bh[nxt][0], bB + bRow + (((bCk0 ^ rx)) << 4));
                ldsm4t(bh[nxt][1], bB + bRow + (((bCk1 ^ rx)) << 4));
            }
            #pragma unroll
            for (int mb = 0; mb < 2; ++mb)
                #pragma unroll
                for (int nb = 0; nb < 4; ++nb)
                    mma16816(acc[mb][nb], ah[cur][mb], &bh[cur][nb >> 1][2 * (nb & 1)]);
            #pragma unroll
            for (int mb = 0; mb < 2; ++mb)
                #pragma unroll
                for (int nb = 0; nb < 4; ++nb)
                    mma16816(acc[mb][nb], al[cur][mb], &bh[cur][nb >> 1][2 * (nb & 1)]);
        }
    }

    // epilogue
    const int q = l >> 2, idx = l & 3;
    #pragma unroll
    for (int mb = 0; mb < 2; ++mb) {
        const int r0 = rowBase + wm + mb * 16 + q;
        const int r1 = r0 + 8;
        #pragma unroll
        for (int nb = 0; nb < 4; ++nb) {
            const int col = colBase + wn + nb * 8 + 2 * idx;
            if (mode == 0) {
                const float bs0 = bias[col], bs1 = bias[col + 1];
                float v00 = fmaxf(acc[mb][nb][0] + bs0, 0.0f);
                float v01 = fmaxf(acc[mb][nb][1] + bs1, 0.0f);
                float v10 = fmaxf(acc[mb][nb][2] + bs0, 0.0f);
                float v11 = fmaxf(acc[mb][nb][3] + bs1, 0.0f);
                fp16 h00, l00, h01, l01, h10, l10, h11, l11;
                split2h(v00, h00, l00); split2h(v01, h01, l01);
                split2h(v10, h10, l10); split2h(v11, h11, l11);
                *(__half2*)(outH + (size_t)r0 * outW + col) = __halves2half2(h00, h01);
                *(__half2*)(outL + (size_t)r0 * outW + col) = __halves2half2(l00, l01);
                *(__half2*)(outH + (size_t)r1 * outW + col) = __halves2half2(h10, h11);
                *(__half2*)(outL + (size_t)r1 * outW + col) = __halves2half2(l10, l11);
            } else {
                #pragma unroll
                for (int e = 0; e < 4; ++e) {
                    const int rr = (e < 2) ? r0 : r1;
                    const int cc = col + (e & 1);
                    if (rr < NROIS) {
                        const float v = acc[mb][nb][e] + bias[cc];
                        if (cc < 324)      outLoc[(size_t)rr * 324 + cc] = v;
                        else if (cc < 405) outSc[(size_t)rr * 81 + (cc - 324)] = v;
                    }
                }
            }
        }
    }
}

// ---------------- launch ------------------------------------------------------
extern "C" void kernel_launch(void* const* d_in, const int* in_sizes, int n_in,
                              void* d_out, int out_size)
{
    const float* f2   = (const float*)d_in[0];
    const float* f3   = (const float*)d_in[1];
    const float* f4   = (const float*)d_in[2];
    const float* f5   = (const float*)d_in[3];
    const float* rois = (const float*)d_in[4];
    const float* W1   = (const float*)d_in[6];
    const float* b1   = (const float*)d_in[7];
    const float* W2   = (const float*)d_in[8];
    const float* b2   = (const float*)d_in[9];
    const float* Wloc = (const float*)d_in[10];
    const float* bloc = (const float*)d_in[11];
    const float* Wsc  = (const float*)d_in[12];
    const float* bsc  = (const float*)d_in[13];

    float* out_loc = (float*)d_out;
    float* out_sc  = (float*)d_out + (size_t)NROIS * 324;

    fp16 *xh, *xl, *w1h, *w2h, *whh, *f1h, *f1l, *f2h_, *f2l_;
    fp16 *ft2, *ft3, *ft4, *ft5;
    float *bcomb;
    cudaGetSymbolAddress((void**)&xh,   g_xh);
    cudaGetSymbolAddress((void**)&xl,   g_xl);
    cudaGetSymbolAddress((void**)&w1h,  g_w1h);
    cudaGetSymbolAddress((void**)&w2h,  g_w2h);
    cudaGetSymbolAddress((void**)&whh,  g_whh);
    cudaGetSymbolAddress((void**)&f1h,  g_f1h);
    cudaGetSymbolAddress((void**)&f1l,  g_f1l);
    cudaGetSymbolAddress((void**)&f2h_, g_f2h);
    cudaGetSymbolAddress((void**)&f2l_, g_f2l);
    cudaGetSymbolAddress((void**)&bcomb, g_bcomb);
    cudaGetSymbolAddress((void**)&ft2,  g_ft2);
    cudaGetSymbolAddress((void**)&ft3,  g_ft3);
    cudaGetSymbolAddress((void**)&ft4,  g_ft4);
    cudaGetSymbolAddress((void**)&ft5,  g_ft5);

    cudaFuncSetAttribute(gemm_mma, cudaFuncAttributeMaxDynamicSharedMemorySize, GEMM_SMEM);
    cudaFuncSetAttribute(roi_align3, cudaFuncAttributeMaxDynamicSharedMemorySize, DFEAT * 4);

    // launch 1: fused prep
    prep_all<<<NB_W1 + NB_W2 + NB_HD + 1, 256>>>((const float4*)W1, (const float4*)W2,
                                                 Wloc, Wsc, bloc, bsc,
                                                 w1h, w2h, whh, bcomb);
    // launch 2: fused feature transpose (fp32 -> fp16 channel-last)
    ftrans_all<<<FT_NB2 + FT_NB3 + FT_NB4 + FT_NB5, dim3(32, 8)>>>(f2, f3, f4, f5,
                                                                   ft2, ft3, ft4, ft5);
    // launch 3: ROI align
    roi_align3<<<NROIS, 128, DFEAT * 4>>>(ft2, ft3, ft4, ft5, rois, xh, xl);

    // launch 4 (profiled): big GEMM
    gemm_mma<<<dim3(8, 16), 256, GEMM_SMEM>>>(xh, xl, w1h, b1, DFEAT, 1024, 0,
                                              f1h, f1l, nullptr, nullptr, 1024);
    // launch 5
    gemm_mma<<<dim3(8, 16), 256, GEMM_SMEM>>>(f1h, f1l, w2h, b2, 1024, 1024, 0,
                                              f2h_, f2l_, nullptr, nullptr, 1024);
    // launch 6
    gemm_mma<<<dim3(8, 7), 256, GEMM_SMEM>>>(f2h_, f2l_, whh, bcomb, 1024, 512, 1,
                                             nullptr, nullptr, out_loc, out_sc, 0);
}

// round 11
// speedup vs baseline: 11.3220x; 1.3232x over previous
#include <cuda_runtime.h>
#include <cuda_fp16.h>
#include <cstdint>

typedef __half fp16;

#define NROIS 1000
#define DFEAT 12544
#define MPAD  1024

// ---------------- persistent scratch (zero-init) -------------------------------
__device__ fp16 g_xh [MPAD * DFEAT];
__device__ fp16 g_w1h[DFEAT * 1024];   // [K][N], single fp16
__device__ fp16 g_w2h[1024 * 1024];
__device__ fp16 g_whh[1024 * 512];     // combined heads [K=1024][N=512 padded]
__device__ fp16 g_f1h[MPAD * 1024];
__device__ fp16 g_f1l[MPAD * 1024];
__device__ fp16 g_f2h[MPAD * 1024];
__device__ fp16 g_f2l[MPAD * 1024];
__device__ float g_bcomb[512];
// transposed feature maps [H][W][C] fp16
__device__ fp16 g_ft2[256 * 256 * 256];
__device__ fp16 g_ft3[128 * 128 * 256];
__device__ fp16 g_ft4[64 * 64 * 256];
__device__ fp16 g_ft5[32 * 32 * 256];

// ---------------- helpers ------------------------------------------------------
__device__ __forceinline__ uint32_t s2u(const void* p) {
    uint32_t a;
    asm("{ .reg .u64 t; cvta.to.shared.u64 t, %1; cvt.u32.u64 %0, t; }" : "=r"(a) : "l"(p));
    return a;
}
__device__ __forceinline__ void cp16(uint32_t s, const void* g) {
    asm volatile("cp.async.cg.shared.global [%0], [%1], 16;" :: "r"(s), "l"(g) : "memory");
}
__device__ __forceinline__ void cp_commit() {
    asm volatile("cp.async.commit_group;" ::: "memory");
}
__device__ __forceinline__ void cp_wait2() {
    asm volatile("cp.async.wait_group 2;" ::: "memory");
}
__device__ __forceinline__ void ldsm4(uint32_t* r, uint32_t a) {
    asm volatile("ldmatrix.sync.aligned.m8n8.x4.shared.b16 {%0,%1,%2,%3}, [%4];"
                 : "=r"(r[0]), "=r"(r[1]), "=r"(r[2]), "=r"(r[3]) : "r"(a));
}
__device__ __forceinline__ void ldsm4t(uint32_t* r, uint32_t a) {
    asm volatile("ldmatrix.sync.aligned.m8n8.x4.trans.shared.b16 {%0,%1,%2,%3}, [%4];"
                 : "=r"(r[0]), "=r"(r[1]), "=r"(r[2]), "=r"(r[3]) : "r"(a));
}
__device__ __forceinline__ void mma16816(float* c, const uint32_t* a, const uint32_t* b) {
    asm volatile(
        "mma.sync.aligned.m16n8k16.row.col.f32.f16.f16.f32 "
        "{%0,%1,%2,%3}, {%4,%5,%6,%7}, {%8,%9}, {%0,%1,%2,%3};"
        : "+f"(c[0]), "+f"(c[1]), "+f"(c[2]), "+f"(c[3])
        : "r"(a[0]), "r"(a[1]), "r"(a[2]), "r"(a[3]), "r"(b[0]), "r"(b[1]));
}
__device__ __forceinline__ void split2h(float v, fp16& h, fp16& l) {
    h = __float2half_rn(v);
    l = __float2half_rn(v - __half2float(h));
}

// ---------------- fused prep: W1/W2 fp16 convert, heads pack, bias pack --------
#define NB_W1 12544
#define NB_W2 1024
#define NB_HD 2048
__global__ void prep_all(const float4* __restrict__ W1, const float4* __restrict__ W2,
                         const float* __restrict__ Wloc, const float* __restrict__ Wsc,
                         const float* __restrict__ bloc, const float* __restrict__ bsc,
                         fp16* __restrict__ w1h, fp16* __restrict__ w2h,
                         fp16* __restrict__ whh, float* __restrict__ bcomb)
{
    const int b = blockIdx.x;
    const int tid = threadIdx.x;
    if (b < NB_W1 + NB_W2) {
        const bool isW1 = (b < NB_W1);
        const int i = (isW1 ? b : b - NB_W1) * 256 + tid;
        const float4 v = isW1 ? W1[i] : W2[i];
        __half2* H2 = (__half2*)(isW1 ? w1h : w2h);
        H2[2 * i]     = __halves2half2(__float2half_rn(v.x), __float2half_rn(v.y));
        H2[2 * i + 1] = __halves2half2(__float2half_rn(v.z), __float2half_rn(v.w));
    } else if (b < NB_W1 + NB_W2 + NB_HD) {
        const int idx = (b - NB_W1 - NB_W2) * 256 + tid;
        const int k = idx >> 9, n = idx & 511;
        float v = 0.0f;
        if (n < 324)      v = Wloc[k * 324 + n];
        else if (n < 405) v = Wsc[k * 81 + (n - 324)];
        whh[idx] = __float2half_rn(v);
    } else {
        for (int i = tid; i < 512; i += 256)
            bcomb[i] = (i < 324) ? bloc[i] : ((i < 405) ? bsc[i - 324] : 0.0f);
    }
}

// ---------------- fused feature transpose [C][H][W] fp32 -> [H][W][C] fp16 -----
#define FT_NB2 16384
#define FT_NB3 4096
#define FT_NB4 1024
#define FT_NB5 256
__global__ void ftrans_all(const float* __restrict__ f2, const float* __restrict__ f3,
                           const float* __restrict__ f4, const float* __restrict__ f5,
                           fp16* __restrict__ t2o, fp16* __restrict__ t3o,
                           fp16* __restrict__ t4o, fp16* __restrict__ t5o)
{
    __shared__ float t[32][33];
    int b = blockIdx.x;
    const float* f; fp16* ft; int H;
    if (b < FT_NB2)                         { f = f2; ft = t2o; H = 256; }
    else if (b < FT_NB2 + FT_NB3)           { b -= FT_NB2; f = f3; ft = t3o; H = 128; }
    else if (b < FT_NB2 + FT_NB3 + FT_NB4)  { b -= FT_NB2 + FT_NB3; f = f4; ft = t4o; H = 64; }
    else                                    { b -= FT_NB2 + FT_NB3 + FT_NB4; f = f5; ft = t5o; H = 32; }
    const int W = H;
    const int wT = H >> 5;
    const int w0 = (b % wT) * 32;
    const int h  = (b / wT) % H;
    const int c0 = (b / (wT * H)) * 32;
    const int tx = threadIdx.x, ty = threadIdx.y;
    #pragma unroll
    for (int r = 0; r < 4; ++r) {
        const int c = c0 + ty + r * 8;
        t[ty + r * 8][tx] = f[((size_t)c * H + h) * W + w0 + tx];
    }
    __syncthreads();
    #pragma unroll
    for (int r = 0; r < 4; ++r) {
        const int w = w0 + ty + r * 8;
        ft[((size_t)h * W + w) * 256 + c0 + tx] = __float2half_rn(t[tx][ty + r * 8]);
    }
}

// ---------------- ROI align, fp16 uint2 gather (4 channels/thread) -------------
__global__ void roi_align3(const fp16* __restrict__ ft2, const fp16* __restrict__ ft3,
                           const fp16* __restrict__ ft4, const fp16* __restrict__ ft5,
                           const float* __restrict__ rois,
                           fp16* __restrict__ xh)
{
    extern __shared__ float s[];   // 12544 floats
    const int r = blockIdx.x;
    const int tid = threadIdx.x;
    const int cg = tid & 63;
    const int half = tid >> 6;

    __shared__ int   s_y0[14], s_y1[14], s_x0[14], s_x1[14];
    __shared__ float s_ly[14], s_lx[14];

    const float ry1 = rois[r * 4 + 0];
    const float rx1 = rois[r * 4 + 1];
    const float ry2 = rois[r * 4 + 2];
    const float rx2 = rois[r * 4 + 3];

    const float hh = ry2 - ry1 + 1.0f;
    const float ww = rx2 - rx1 + 1.0f;
    float lv = floorf(logf(sqrtf(hh * ww) / 224.0f) / 0.693147f + 4.0f);
    lv = fminf(fmaxf(lv, 2.0f), 5.0f);
    const int lvl = (int)lv;

    int H; const fp16* ft;
    if (lvl == 2)      { H = 256; ft = ft2; }
    else if (lvl == 3) { H = 128; ft = ft3; }
    else if (lvl == 4) { H = 64;  ft = ft4; }
    else               { H = 32;  ft = ft5; }
    const int W = H;

    const float fm = (float)(H - 1);
    const float gy1 = ry1 * fm / 1023.0f;
    const float gx1 = rx1 * fm / 1023.0f;
    const float gy2 = ry2 * fm / 1023.0f;
    const float gx2 = rx2 * fm / 1023.0f;
    const float hs = (gy2 - gy1) / 14.0f;
    const float ws = (gx2 - gx1) / 14.0f;

    if (tid < 14) {
        const float cy = ((float)tid + 0.5f) * hs + gy1;
        const float fl = floorf(cy);
        s_y0[tid] = (int)fl;
        s_y1[tid] = (int)ceilf(cy);
        s_ly[tid] = cy - fl;
    } else if (tid < 28) {
        const int j = tid - 14;
        const float cx = ((float)j + 0.5f) * ws + gx1;
        const float fl = floorf(cx);
        s_x0[j] = (int)fl;
        s_x1[j] = (int)ceilf(cx);
        s_lx[j] = cx - fl;
    }
    __syncthreads();

    const fp16* __restrict__ fb = ft + 4 * cg;   // channels 4cg..4cg+3

    const int pyBeg = half ? 4 : 0;
    const int pyEnd = half ? 7 : 4;

    for (int py = pyBeg; py < pyEnd; ++py) {
        float4 m[7];
        #pragma unroll
        for (int i = 0; i < 7; ++i) m[i] = make_float4(-3.0e38f, -3.0e38f, -3.0e38f, -3.0e38f);
        #pragma unroll
        for (int a = 0; a < 2; ++a) {
            const int sy = 2 * py + a;
            const float ly = s_ly[sy];
            const float oly = 1.0f - ly;
            const fp16* __restrict__ r0 = fb + (size_t)(s_y0[sy] * W) * 256;
            const fp16* __restrict__ r1 = fb + (size_t)(s_y1[sy] * W) * 256;
            #pragma unroll
            for (int sx = 0; sx < 14; ++sx) {
                const int x0 = s_x0[sx] * 256;
                const int x1 = s_x1[sx] * 256;
                const float lx = s_lx[sx];
                const float olx = 1.0f - lx;
                const float w00 = oly * olx, w01 = oly * lx;
                const float w10 = ly * olx,  w11 = ly * lx;
                const uint2 u00 = *(const uint2*)(r0 + x0);
                const uint2 u01 = *(const uint2*)(r0 + x1);
                const uint2 u10 = *(const uint2*)(r1 + x0);
                const uint2 u11 = *(const uint2*)(r1 + x1);
                const float2 a00 = __half22float2(*(const __half2*)&u00.x);
                const float2 b00 = __half22float2(*(const __half2*)&u00.y);
                const float2 a01 = __half22float2(*(const __half2*)&u01.x);
                const float2 b01 = __half22float2(*(const __half2*)&u01.y);
                const float2 a10 = __half22float2(*(const __half2*)&u10.x);
                const float2 b10 = __half22float2(*(const __half2*)&u10.y);
                const float2 a11 = __half22float2(*(const __half2*)&u11.x);
                const float2 b11 = __half22float2(*(const __half2*)&u11.y);
                float4& mm = m[sx >> 1];
                mm.x = fmaxf(mm.x, a00.x * w00 + a10.x * w10 + a01.x * w01 + a11.x * w11);
                mm.y = fmaxf(mm.y, a00.y * w00 + a10.y * w10 + a01.y * w01 + a11.y * w11);
                mm.z = fmaxf(mm.z, b00.x * w00 + b10.x * w10 + b01.x * w01 + b11.x * w11);
                mm.w = fmaxf(mm.w, b00.y * w00 + b10.y * w10 + b01.y * w01 + b11.y * w11);
            }
        }
        #pragma unroll
        for (int px = 0; px < 7; ++px) {
            const int cell = py * 7 + px;
            s[(4 * cg + 0) * 49 + cell] = m[px].x;
            s[(4 * cg + 1) * 49 + cell] = m[px].y;
            s[(4 * cg + 2) * 49 + cell] = m[px].z;
            s[(4 * cg + 3) * 49 + cell] = m[px].w;
        }
    }
    __syncthreads();

    const size_t ob = (size_t)r * DFEAT;
    for (int i = tid * 2; i < DFEAT; i += 256) {
        *(__half2*)(xh + ob + i) =
            __halves2half2(__float2half_rn(s[i]), __float2half_rn(s[i + 1]));
    }
}

// ---------------- HMMA GEMM, templated A-term count, GBK=64, 256 threads -------
// A: [M][K] fp16 (hi, + lo if NA==2). B: [K][N] fp16 (N-major, single).
// Stage: Ah 16KB (+Al 16KB if NA==2) + B 8KB. 128B rows, chunk ^= row&7.
#define GBK 64
#define STG 4

template<int NA>
__global__ __launch_bounds__(256) void gemm_mma(
    const fp16* __restrict__ Ah, const fp16* __restrict__ Al,
    const fp16* __restrict__ Bh,
    const float* __restrict__ bias, int K, int N, int mode,
    fp16* __restrict__ outH, fp16* __restrict__ outL,
    float* __restrict__ outLoc, float* __restrict__ outSc, int outW)
{
    constexpr uint32_t B_OFF  = NA * 16384u;
    constexpr uint32_t BUF_SZ = NA * 16384u + 8192u;

    extern __shared__ char smem[];
    const uint32_t smU = s2u(smem);
    const int t   = threadIdx.x;
    const int l   = t & 31;
    const int wid = t >> 5;                 // 0..7
    const int wm  = (wid & 3) * 32;         // 4 warps over M=128
    const int wn  = (wid >> 2) * 32;        // 2 warps over N=64
    const int rowBase = blockIdx.x * 128;
    const int colBase = blockIdx.y * 64;
    const size_t K2 = (size_t)K * 2;

    // loader geometry
    const int ldRow = t >> 3;
    const int ldC   = t & 7;
    const uint32_t ldSel  = (uint32_t)(ldRow & 7);
    const uint32_t sOff0  = ldRow * 128 + (((uint32_t)ldC ^ ldSel) << 4);

    const char* pAh = (const char*)(Ah + (size_t)(rowBase + ldRow) * K) + ldC * 16;
    const char* pAl = (NA == 2)
        ? (const char*)(Al + (size_t)(rowBase + ldRow) * K) + ldC * 16 : nullptr;
    const char* pB  = (const char*)(Bh + (size_t)ldRow * N + colBase) + ldC * 16;
    const size_t bStep = (size_t)GBK * N * 2;
    const size_t aRowStep32 = 32 * K2;
    const size_t bRowStep32 = 32 * (size_t)N * 2;

    float acc[2][4][4];
    #pragma unroll
    for (int mb = 0; mb < 2; ++mb)
        #pragma unroll
        for (int nb = 0; nb < 4; ++nb)
            #pragma unroll
            for (int i = 0; i < 4; ++i) acc[mb][nb][i] = 0.0f;

    // ldmatrix geometry
    const uint32_t aRowAddr = (wm + (l & 15)) * 128;
    const uint32_t aSel = (uint32_t)((l & 15) & 7);
    const uint32_t aCk0 = (l >> 4);
    const uint32_t bLane = l & 15;
    const uint32_t bNg   = (uint32_t)(l >> 4);
    const uint32_t bCk0  = ((uint32_t)wn >> 3) + bNg;
    const uint32_t bCk1  = bCk0 + 2;

    const int nt = K / GBK;

    auto issue = [&](int kt) {
        const uint32_t bu = smU + (kt % STG) * BUF_SZ;
        const size_t ka = (size_t)kt * 128;
        const size_t kb = (size_t)kt * bStep;
        #pragma unroll
        for (int i = 0; i < 4; ++i)
            cp16(bu + sOff0 + i * 4096, pAh + ka + i * aRowStep32);
        if (NA == 2) {
            #pragma unroll
            for (int i = 0; i < 4; ++i)
                cp16(bu + 16384 + sOff0 + i * 4096, pAl + ka + i * aRowStep32);
        }
        #pragma unroll
        for (int i = 0; i < 2; ++i)
            cp16(bu + B_OFF + sOff0 + i * 4096, pB + kb + i * bRowStep32);
        cp_commit();
    };

    issue(0);
    if (nt > 1) issue(1); else cp_commit();
    if (nt > 2) issue(2); else cp_commit();

    for (int kt = 0; kt < nt; ++kt) {
        cp_wait2();
        __syncthreads();
        if (kt + 3 < nt) issue(kt + 3);
        else cp_commit();

        const uint32_t bu = smU + (kt % STG) * BUF_SZ;
        const uint32_t aB = bu + aRowAddr;
        const uint32_t bB = bu + B_OFF;

        #pragma unroll
        for (int ks = 0; ks < 4; ++ks) {
            const uint32_t aOff = (((aCk0 + 2 * ks) ^ aSel) << 4);
            const uint32_t rowB = ks * 16 + bLane;
            const uint32_t rx = rowB & 7;
            const uint32_t bRow = rowB * 128;

            uint32_t af[2][2][4], bh[2][4];
            ldsm4(af[0][0], aB + aOff);
            ldsm4(af[0][1], aB + 2048 + aOff);
            if (NA == 2) {
                ldsm4(af[1][0], aB + 16384 + aOff);
                ldsm4(af[1][1], aB + 18432 + aOff);
            }
            ldsm4t(bh[0], bB + bRow + (((bCk0 ^ rx)) << 4));
            ldsm4t(bh[1], bB + bRow + (((bCk1 ^ rx)) << 4));

            #pragma unroll
            for (int term = 0; term < NA; ++term)
                #pragma unroll
                for (int mb = 0; mb < 2; ++mb)
                    #pragma unroll
                    for (int nb = 0; nb < 4; ++nb)
                        mma16816(acc[mb][nb], af[term][mb], &bh[nb >> 1][2 * (nb & 1)]);
        }
    }

    // epilogue
    const int q = l >> 2, idx = l & 3;
    #pragma unroll
    for (int mb = 0; mb < 2; ++mb) {
        const int r0 = rowBase + wm + mb * 16 + q;
        const int r1 = r0 + 8;
        #pragma unroll
        for (int nb = 0; nb < 4; ++nb) {
            const int col = colBase + wn + nb * 8 + 2 * idx;
            if (mode == 0) {
                const float bs0 = bias[col], bs1 = bias[col + 1];
                float v00 = fmaxf(acc[mb][nb][0] + bs0, 0.0f);
                float v01 = fmaxf(acc[mb][nb][1] + bs1, 0.0f);
                float v10 = fmaxf(acc[mb][nb][2] + bs0, 0.0f);
                float v11 = fmaxf(acc[mb][nb][3] + bs1, 0.0f);
                fp16 h00, l00, h01, l01, h10, l10, h11, l11;
                split2h(v00, h00, l00); split2h(v01, h01, l01);
                split2h(v10, h10, l10); split2h(v11, h11, l11);
                *(__half2*)(outH + (size_t)r0 * outW + col) = __halves2half2(h00, h01);
                *(__half2*)(outL + (size_t)r0 * outW + col) = __halves2half2(l00, l01);
                *(__half2*)(outH + (size_t)r1 * outW + col) = __halves2half2(h10, h11);
                *(__half2*)(outL + (size_t)r1 * outW + col) = __halves2half2(l10, l11);
            } else {
                #pragma unroll
                for (int e = 0; e < 4; ++e) {
                    const int rr = (e < 2) ? r0 : r1;
                    const int cc = col + (e & 1);
                    if (rr < NROIS) {
                        const float v = acc[mb][nb][e] + bias[cc];
                        if (cc < 324)      outLoc[(size_t)rr * 324 + cc] = v;
                        else if (cc < 405) outSc[(size_t)rr * 81 + (cc - 324)] = v;
                    }
                }
            }
        }
    }
}

// ---------------- launch ------------------------------------------------------
extern "C" void kernel_launch(void* const* d_in, const int* in_sizes, int n_in,
                              void* d_out, int out_size)
{
    const float* f2   = (const float*)d_in[0];
    const float* f3   = (const float*)d_in[1];
    const float* f4   = (const float*)d_in[2];
    const float* f5   = (const float*)d_in[3];
    const float* rois = (const float*)d_in[4];
    const float* W1   = (const float*)d_in[6];
    const float* b1   = (const float*)d_in[7];
    const float* W2   = (const float*)d_in[8];
    const float* b2   = (const float*)d_in[9];
    const float* Wloc = (const float*)d_in[10];
    const float* bloc = (const float*)d_in[11];
    const float* Wsc  = (const float*)d_in[12];
    const float* bsc  = (const float*)d_in[13];

    float* out_loc = (float*)d_out;
    float* out_sc  = (float*)d_out + (size_t)NROIS * 324;

    fp16 *xh, *w1h, *w2h, *whh, *f1h, *f1l, *f2h_, *f2l_;
    fp16 *ft2, *ft3, *ft4, *ft5;
    float *bcomb;
    cudaGetSymbolAddress((void**)&xh,   g_xh);
    cudaGetSymbolAddress((void**)&w1h,  g_w1h);
    cudaGetSymbolAddress((void**)&w2h,  g_w2h);
    cudaGetSymbolAddress((void**)&whh,  g_whh);
    cudaGetSymbolAddress((void**)&f1h,  g_f1h);
    cudaGetSymbolAddress((void**)&f1l,  g_f1l);
    cudaGetSymbolAddress((void**)&f2h_, g_f2h);
    cudaGetSymbolAddress((void**)&f2l_, g_f2l);
    cudaGetSymbolAddress((void**)&bcomb, g_bcomb);
    cudaGetSymbolAddress((void**)&ft2,  g_ft2);
    cudaGetSymbolAddress((void**)&ft3,  g_ft3);
    cudaGetSymbolAddress((void**)&ft4,  g_ft4);
    cudaGetSymbolAddress((void**)&ft5,  g_ft5);

    const int SMEM1 = STG * (1 * 16384 + 8192);   // 98304
    const int SMEM2 = STG * (2 * 16384 + 8192);   // 163840
    cudaFuncSetAttribute(gemm_mma<1>, cudaFuncAttributeMaxDynamicSharedMemorySize, SMEM1);
    cudaFuncSetAttribute(gemm_mma<2>, cudaFuncAttributeMaxDynamicSharedMemorySize, SMEM2);
    cudaFuncSetAttribute(roi_align3, cudaFuncAttributeMaxDynamicSharedMemorySize, DFEAT * 4);

    // launch 1: fused prep
    prep_all<<<NB_W1 + NB_W2 + NB_HD + 1, 256>>>((const float4*)W1, (const float4*)W2,
                                                 Wloc, Wsc, bloc, bsc,
                                                 w1h, w2h, whh, bcomb);
    // launch 2: fused feature transpose (fp32 -> fp16 channel-last)
    ftrans_all<<<FT_NB2 + FT_NB3 + FT_NB4 + FT_NB5, dim3(32, 8)>>>(f2, f3, f4, f5,
                                                                   ft2, ft3, ft4, ft5);
    // launch 3: ROI align (fp16 out, hi only)
    roi_align3<<<NROIS, 128, DFEAT * 4>>>(ft2, ft3, ft4, ft5, rois, xh);

    // launch 4 (profiled): big GEMM, single A term
    gemm_mma<1><<<dim3(8, 16), 256, SMEM1>>>(xh, nullptr, w1h, b1, DFEAT, 1024, 0,
                                             f1h, f1l, nullptr, nullptr, 1024);
    // launch 5: 2-term A
    gemm_mma<2><<<dim3(8, 16), 256, SMEM2>>>(f1h, f1l, w2h, b2, 1024, 1024, 0,
                                             f2h_, f2l_, nullptr, nullptr, 1024);
    // launch 6: heads, 2-term A
    gemm_mma<2><<<dim3(8, 7), 256, SMEM2>>>(f2h_, f2l_, whh, bcomb, 1024, 512, 1,
                                            nullptr, nullptr, out_loc, out_sc, 0);
}

// round 12
// speedup vs baseline: 11.7884x; 1.0412x over previous
#include <cuda_runtime.h>
#include <cuda_fp16.h>
#include <cstdint>

typedef __half fp16;

#define NROIS 1000
#define DFEAT 12544
#define MPAD  1024

// ---------------- persistent scratch (zero-init) -------------------------------
__device__ fp16 g_xh [MPAD * DFEAT];
__device__ fp16 g_w1h[DFEAT * 1024];   // [K][N], single fp16
__device__ fp16 g_w2h[1024 * 1024];
__device__ fp16 g_whh[1024 * 512];     // combined heads [K=1024][N=512 padded]
__device__ fp16 g_f1h[MPAD * 1024];
__device__ fp16 g_f2h[MPAD * 1024];
__device__ float g_bcomb[512];
// transposed feature maps [H][W][C] fp16
__device__ fp16 g_ft2[256 * 256 * 256];
__device__ fp16 g_ft3[128 * 128 * 256];
__device__ fp16 g_ft4[64 * 64 * 256];
__device__ fp16 g_ft5[32 * 32 * 256];

// ---------------- helpers ------------------------------------------------------
__device__ __forceinline__ uint32_t s2u(const void* p) {
    uint32_t a;
    asm("{ .reg .u64 t; cvta.to.shared.u64 t, %1; cvt.u32.u64 %0, t; }" : "=r"(a) : "l"(p));
    return a;
}
__device__ __forceinline__ void cp16(uint32_t s, const void* g) {
    asm volatile("cp.async.cg.shared.global [%0], [%1], 16;" :: "r"(s), "l"(g) : "memory");
}
__device__ __forceinline__ void cp_commit() {
    asm volatile("cp.async.commit_group;" ::: "memory");
}
__device__ __forceinline__ void cp_wait2() {
    asm volatile("cp.async.wait_group 2;" ::: "memory");
}
__device__ __forceinline__ void ldsm4(uint32_t* r, uint32_t a) {
    asm volatile("ldmatrix.sync.aligned.m8n8.x4.shared.b16 {%0,%1,%2,%3}, [%4];"
                 : "=r"(r[0]), "=r"(r[1]), "=r"(r[2]), "=r"(r[3]) : "r"(a));
}
__device__ __forceinline__ void ldsm4t(uint32_t* r, uint32_t a) {
    asm volatile("ldmatrix.sync.aligned.m8n8.x4.trans.shared.b16 {%0,%1,%2,%3}, [%4];"
                 : "=r"(r[0]), "=r"(r[1]), "=r"(r[2]), "=r"(r[3]) : "r"(a));
}
__device__ __forceinline__ void mma16816(float* c, const uint32_t* a, const uint32_t* b) {
    asm volatile(
        "mma.sync.aligned.m16n8k16.row.col.f32.f16.f16.f32 "
        "{%0,%1,%2,%3}, {%4,%5,%6,%7}, {%8,%9}, {%0,%1,%2,%3};"
        : "+f"(c[0]), "+f"(c[1]), "+f"(c[2]), "+f"(c[3])
        : "r"(a[0]), "r"(a[1]), "r"(a[2]), "r"(a[3]), "r"(b[0]), "r"(b[1]));
}

// ---------------- fused prep: W1/W2 fp16 convert, heads pack, bias pack --------
#define NB_W1 12544
#define NB_W2 1024
#define NB_HD 2048
__global__ void prep_all(const float4* __restrict__ W1, const float4* __restrict__ W2,
                         const float* __restrict__ Wloc, const float* __restrict__ Wsc,
                         const float* __restrict__ bloc, const float* __restrict__ bsc,
                         fp16* __restrict__ w1h, fp16* __restrict__ w2h,
                         fp16* __restrict__ whh, float* __restrict__ bcomb)
{
    const int b = blockIdx.x;
    const int tid = threadIdx.x;
    if (b < NB_W1 + NB_W2) {
        const bool isW1 = (b < NB_W1);
        const int i = (isW1 ? b : b - NB_W1) * 256 + tid;
        const float4 v = isW1 ? W1[i] : W2[i];
        __half2* H2 = (__half2*)(isW1 ? w1h : w2h);
        H2[2 * i]     = __halves2half2(__float2half_rn(v.x), __float2half_rn(v.y));
        H2[2 * i + 1] = __halves2half2(__float2half_rn(v.z), __float2half_rn(v.w));
    } else if (b < NB_W1 + NB_W2 + NB_HD) {
        const int idx = (b - NB_W1 - NB_W2) * 256 + tid;
        const int k = idx >> 9, n = idx & 511;
        float v = 0.0f;
        if (n < 324)      v = Wloc[k * 324 + n];
        else if (n < 405) v = Wsc[k * 81 + (n - 324)];
        whh[idx] = __float2half_rn(v);
    } else {
        for (int i = tid; i < 512; i += 256)
            bcomb[i] = (i < 324) ? bloc[i] : ((i < 405) ? bsc[i - 324] : 0.0f);
    }
}

// ---------------- fused feature transpose [C][H][W] fp32 -> [H][W][C] fp16 -----
#define FT_NB2 16384
#define FT_NB3 4096
#define FT_NB4 1024
#define FT_NB5 256
__global__ void ftrans_all(const float* __restrict__ f2, const float* __restrict__ f3,
                           const float* __restrict__ f4, const float* __restrict__ f5,
                           fp16* __restrict__ t2o, fp16* __restrict__ t3o,
                           fp16* __restrict__ t4o, fp16* __restrict__ t5o)
{
    __shared__ float t[32][33];
    int b = blockIdx.x;
    const float* f; fp16* ft; int H;
    if (b < FT_NB2)                         { f = f2; ft = t2o; H = 256; }
    else if (b < FT_NB2 + FT_NB3)           { b -= FT_NB2; f = f3; ft = t3o; H = 128; }
    else if (b < FT_NB2 + FT_NB3 + FT_NB4)  { b -= FT_NB2 + FT_NB3; f = f4; ft = t4o; H = 64; }
    else                                    { b -= FT_NB2 + FT_NB3 + FT_NB4; f = f5; ft = t5o; H = 32; }
    const int W = H;
    const int wT = H >> 5;
    const int w0 = (b % wT) * 32;
    const int h  = (b / wT) % H;
    const int c0 = (b / (wT * H)) * 32;
    const int tx = threadIdx.x, ty = threadIdx.y;
    #pragma unroll
    for (int r = 0; r < 4; ++r) {
        const int c = c0 + ty + r * 8;
        t[ty + r * 8][tx] = f[((size_t)c * H + h) * W + w0 + tx];
    }
    __syncthreads();
    #pragma unroll
    for (int r = 0; r < 4; ++r) {
        const int w = w0 + ty + r * 8;
        ft[((size_t)h * W + w) * 256 + c0 + tx] = __float2half_rn(t[tx][ty + r * 8]);
    }
}

// ---------------- ROI align, fp16 uint2 gather (4 channels/thread) -------------
__global__ void roi_align3(const fp16* __restrict__ ft2, const fp16* __restrict__ ft3,
                           const fp16* __restrict__ ft4, const fp16* __restrict__ ft5,
                           const float* __restrict__ rois,
                           fp16* __restrict__ xh)
{
    extern __shared__ float s[];   // 12544 floats
    const int r = blockIdx.x;
    const int tid = threadIdx.x;
    const int cg = tid & 63;
    const int half = tid >> 6;

    __shared__ int   s_y0[14], s_y1[14], s_x0[14], s_x1[14];
    __shared__ float s_ly[14], s_lx[14];

    const float ry1 = rois[r * 4 + 0];
    const float rx1 = rois[r * 4 + 1];
    const float ry2 = rois[r * 4 + 2];
    const float rx2 = rois[r * 4 + 3];

    const float hh = ry2 - ry1 + 1.0f;
    const float ww = rx2 - rx1 + 1.0f;
    float lv = floorf(logf(sqrtf(hh * ww) / 224.0f) / 0.693147f + 4.0f);
    lv = fminf(fmaxf(lv, 2.0f), 5.0f);
    const int lvl = (int)lv;

    int H; const fp16* ft;
    if (lvl == 2)      { H = 256; ft = ft2; }
    else if (lvl == 3) { H = 128; ft = ft3; }
    else if (lvl == 4) { H = 64;  ft = ft4; }
    else               { H = 32;  ft = ft5; }
    const int W = H;

    const float fm = (float)(H - 1);
    const float gy1 = ry1 * fm / 1023.0f;
    const float gx1 = rx1 * fm / 1023.0f;
    const float gy2 = ry2 * fm / 1023.0f;
    const float gx2 = rx2 * fm / 1023.0f;
    const float hs = (gy2 - gy1) / 14.0f;
    const float ws = (gx2 - gx1) / 14.0f;

    if (tid < 14) {
        const float cy = ((float)tid + 0.5f) * hs + gy1;
        const float fl = floorf(cy);
        s_y0[tid] = (int)fl;
        s_y1[tid] = (int)ceilf(cy);
        s_ly[tid] = cy - fl;
    } else if (tid < 28) {
        const int j = tid - 14;
        const float cx = ((float)j + 0.5f) * ws + gx1;
        const float fl = floorf(cx);
        s_x0[j] = (int)fl;
        s_x1[j] = (int)ceilf(cx);
        s_lx[j] = cx - fl;
    }
    __syncthreads();

    const fp16* __restrict__ fb = ft + 4 * cg;   // channels 4cg..4cg+3

    const int pyBeg = half ? 4 : 0;
    const int pyEnd = half ? 7 : 4;

    for (int py = pyBeg; py < pyEnd; ++py) {
        float4 m[7];
        #pragma unroll
        for (int i = 0; i < 7; ++i) m[i] = make_float4(-3.0e38f, -3.0e38f, -3.0e38f, -3.0e38f);
        #pragma unroll
        for (int a = 0; a < 2; ++a) {
            const int sy = 2 * py + a;
            const float ly = s_ly[sy];
            const float oly = 1.0f - ly;
            const fp16* __restrict__ r0 = fb + (size_t)(s_y0[sy] * W) * 256;
            const fp16* __restrict__ r1 = fb + (size_t)(s_y1[sy] * W) * 256;
            #pragma unroll
            for (int sx = 0; sx < 14; ++sx) {
                const int x0 = s_x0[sx] * 256;
                const int x1 = s_x1[sx] * 256;
                const float lx = s_lx[sx];
                const float olx = 1.0f - lx;
                const float w00 = oly * olx, w01 = oly * lx;
                const float w10 = ly * olx,  w11 = ly * lx;
                const uint2 u00 = *(const uint2*)(r0 + x0);
                const uint2 u01 = *(const uint2*)(r0 + x1);
                const uint2 u10 = *(const uint2*)(r1 + x0);
                const uint2 u11 = *(const uint2*)(r1 + x1);
                const float2 a00 = __half22float2(*(const __half2*)&u00.x);
                const float2 b00 = __half22float2(*(const __half2*)&u00.y);
                const float2 a01 = __half22float2(*(const __half2*)&u01.x);
                const float2 b01 = __half22float2(*(const __half2*)&u01.y);
                const float2 a10 = __half22float2(*(const __half2*)&u10.x);
                const float2 b10 = __half22float2(*(const __half2*)&u10.y);
                const float2 a11 = __half22float2(*(const __half2*)&u11.x);
                const float2 b11 = __half22float2(*(const __half2*)&u11.y);
                float4& mm = m[sx >> 1];
                mm.x = fmaxf(mm.x, a00.x * w00 + a10.x * w10 + a01.x * w01 + a11.x * w11);
                mm.y = fmaxf(mm.y, a00.y * w00 + a10.y * w10 + a01.y * w01 + a11.y * w11);
                mm.z = fmaxf(mm.z, b00.x * w00 + b10.x * w10 + b01.x * w01 + b11.x * w11);
                mm.w = fmaxf(mm.w, b00.y * w00 + b10.y * w10 + b01.y * w01 + b11.y * w11);
            }
        }
        #pragma unroll
        for (int px = 0; px < 7; ++px) {
            const int cell = py * 7 + px;
            s[(4 * cg + 0) * 49 + cell] = m[px].x;
            s[(4 * cg + 1) * 49 + cell] = m[px].y;
            s[(4 * cg + 2) * 49 + cell] = m[px].z;
            s[(4 * cg + 3) * 49 + cell] = m[px].w;
        }
    }
    __syncthreads();

    const size_t ob = (size_t)r * DFEAT;
    for (int i = tid * 2; i < DFEAT; i += 256) {
        *(__half2*)(xh + ob + i) =
            __halves2half2(__float2half_rn(s[i]), __float2half_rn(s[i + 1]));
    }
}

// ---------------- HMMA GEMM, single-term fp16, GBK=64, 256 threads -------------
// A: [M][K] fp16 (K-major). B: [K][N] fp16 (N-major).
// Stage 24KB: Ah[128][64]@0, B[64][64]@16384. 128B rows, chunk ^= row&7.
#define GBK 64
#define STG 4
#define BUF_SZ 24576
#define GEMM_SMEM (STG * BUF_SZ)

__global__ __launch_bounds__(256) void gemm_mma(
    const fp16* __restrict__ Ah, const fp16* __restrict__ Bh,
    const float* __restrict__ bias, int K, int N, int mode,
    fp16* __restrict__ outH,
    float* __restrict__ outLoc, float* __restrict__ outSc, int outW)
{
    extern __shared__ char smem[];
    const uint32_t smU = s2u(smem);
    const int t   = threadIdx.x;
    const int l   = t & 31;
    const int wid = t >> 5;                 // 0..7
    const int wm  = (wid & 3) * 32;         // 4 warps over M=128
    const int wn  = (wid >> 2) * 32;        // 2 warps over N=64
    const int rowBase = blockIdx.x * 128;
    const int colBase = blockIdx.y * 64;
    const size_t K2 = (size_t)K * 2;

    // loader geometry
    const int ldRow = t >> 3;
    const int ldC   = t & 7;
    const uint32_t ldSel  = (uint32_t)(ldRow & 7);
    const uint32_t sOff0  = ldRow * 128 + (((uint32_t)ldC ^ ldSel) << 4);

    const char* pAh = (const char*)(Ah + (size_t)(rowBase + ldRow) * K) + ldC * 16;
    const char* pB  = (const char*)(Bh + (size_t)ldRow * N + colBase) + ldC * 16;
    const size_t bStep = (size_t)GBK * N * 2;
    const size_t aRowStep32 = 32 * K2;
    const size_t bRowStep32 = 32 * (size_t)N * 2;

    float acc[2][4][4];
    #pragma unroll
    for (int mb = 0; mb < 2; ++mb)
        #pragma unroll
        for (int nb = 0; nb < 4; ++nb)
            #pragma unroll
            for (int i = 0; i < 4; ++i) acc[mb][nb][i] = 0.0f;

    // ldmatrix geometry
    const uint32_t aRowAddr = (wm + (l & 15)) * 128;
    const uint32_t aSel = (uint32_t)((l & 15) & 7);
    const uint32_t aCk0 = (l >> 4);
    const uint32_t bLane = l & 15;
    const uint32_t bNg   = (uint32_t)(l >> 4);
    const uint32_t bCk0  = ((uint32_t)wn >> 3) + bNg;
    const uint32_t bCk1  = bCk0 + 2;

    const int nt = K / GBK;

    auto issue = [&](int kt) {
        const uint32_t bu = smU + (kt % STG) * BUF_SZ;
        const size_t ka = (size_t)kt * 128;
        const size_t kb = (size_t)kt * bStep;
        #pragma unroll
        for (int i = 0; i < 4; ++i)
            cp16(bu + sOff0 + i * 4096, pAh + ka + i * aRowStep32);
        #pragma unroll
        for (int i = 0; i < 2; ++i)
            cp16(bu + 16384 + sOff0 + i * 4096, pB + kb + i * bRowStep32);
        cp_commit();
    };

    issue(0);
    if (nt > 1) issue(1); else cp_commit();
    if (nt > 2) issue(2); else cp_commit();

    for (int kt = 0; kt < nt; ++kt) {
        cp_wait2();
        __syncthreads();
        if (kt + 3 < nt) issue(kt + 3);
        else cp_commit();

        const uint32_t bu = smU + (kt % STG) * BUF_SZ;
        const uint32_t aB = bu + aRowAddr;
        const uint32_t bB = bu + 16384;

        #pragma unroll
        for (int ks = 0; ks < 4; ++ks) {
            const uint32_t aOff = (((aCk0 + 2 * ks) ^ aSel) << 4);
            const uint32_t rowB = ks * 16 + bLane;
            const uint32_t rx = rowB & 7;
            const uint32_t bRow = rowB * 128;

            uint32_t af[2][4], bh[2][4];
            ldsm4(af[0], aB + aOff);
            ldsm4(af[1], aB + 2048 + aOff);
            ldsm4t(bh[0], bB + bRow + (((bCk0 ^ rx)) << 4));
            ldsm4t(bh[1], bB + bRow + (((bCk1 ^ rx)) << 4));

            #pragma unroll
            for (int mb = 0; mb < 2; ++mb)
                #pragma unroll
                for (int nb = 0; nb < 4; ++nb)
                    mma16816(acc[mb][nb], af[mb], &bh[nb >> 1][2 * (nb & 1)]);
        }
    }

    // epilogue
    const int q = l >> 2, idx = l & 3;
    #pragma unroll
    for (int mb = 0; mb < 2; ++mb) {
        const int r0 = rowBase + wm + mb * 16 + q;
        const int r1 = r0 + 8;
        #pragma unroll
        for (int nb = 0; nb < 4; ++nb) {
            const int col = colBase + wn + nb * 8 + 2 * idx;
            if (mode == 0) {
                const float bs0 = bias[col], bs1 = bias[col + 1];
                const float v00 = fmaxf(acc[mb][nb][0] + bs0, 0.0f);
                const float v01 = fmaxf(acc[mb][nb][1] + bs1, 0.0f);
                const float v10 = fmaxf(acc[mb][nb][2] + bs0, 0.0f);
                const float v11 = fmaxf(acc[mb][nb][3] + bs1, 0.0f);
                *(__half2*)(outH + (size_t)r0 * outW + col) =
                    __halves2half2(__float2half_rn(v00), __float2half_rn(v01));
                *(__half2*)(outH + (size_t)r1 * outW + col) =
                    __halves2half2(__float2half_rn(v10), __float2half_rn(v11));
            } else {
                #pragma unroll
                for (int e = 0; e < 4; ++e) {
                    const int rr = (e < 2) ? r0 : r1;
                    const int cc = col + (e & 1);
                    if (rr < NROIS) {
                        const float v = acc[mb][nb][e] + bias[cc];
                        if (cc < 324)      outLoc[(size_t)rr * 324 + cc] = v;
                        else if (cc < 405) outSc[(size_t)rr * 81 + (cc - 324)] = v;
                    }
                }
            }
        }
    }
}

// ---------------- launch ------------------------------------------------------
extern "C" void kernel_launch(void* const* d_in, const int* in_sizes, int n_in,
                              void* d_out, int out_size)
{
    const float* f2   = (const float*)d_in[0];
    const float* f3   = (const float*)d_in[1];
    const float* f4   = (const float*)d_in[2];
    const float* f5   = (const float*)d_in[3];
    const float* rois = (const float*)d_in[4];
    const float* W1   = (const float*)d_in[6];
    const float* b1   = (const float*)d_in[7];
    const float* W2   = (const float*)d_in[8];
    const float* b2   = (const float*)d_in[9];
    const float* Wloc = (const float*)d_in[10];
    const float* bloc = (const float*)d_in[11];
    const float* Wsc  = (const float*)d_in[12];
    const float* bsc  = (const float*)d_in[13];

    float* out_loc = (float*)d_out;
    float* out_sc  = (float*)d_out + (size_t)NROIS * 324;

    fp16 *xh, *w1h, *w2h, *whh, *f1h, *f2h_;
    fp16 *ft2, *ft3, *ft4, *ft5;
    float *bcomb;
    cudaGetSymbolAddress((void**)&xh,   g_xh);
    cudaGetSymbolAddress((void**)&w1h,  g_w1h);
    cudaGetSymbolAddress((void**)&w2h,  g_w2h);
    cudaGetSymbolAddress((void**)&whh,  g_whh);
    cudaGetSymbolAddress((void**)&f1h,  g_f1h);
    cudaGetSymbolAddress((void**)&f2h_, g_f2h);
    cudaGetSymbolAddress((void**)&bcomb, g_bcomb);
    cudaGetSymbolAddress((void**)&ft2,  g_ft2);
    cudaGetSymbolAddress((void**)&ft3,  g_ft3);
    cudaGetSymbolAddress((void**)&ft4,  g_ft4);
    cudaGetSymbolAddress((void**)&ft5,  g_ft5);

    cudaFuncSetAttribute(gemm_mma, cudaFuncAttributeMaxDynamicSharedMemorySize, GEMM_SMEM);
    cudaFuncSetAttribute(roi_align3, cudaFuncAttributeMaxDynamicSharedMemorySize, DFEAT * 4);

    // launch 1: fused prep
    prep_all<<<NB_W1 + NB_W2 + NB_HD + 1, 256>>>((const float4*)W1, (const float4*)W2,
                                                 Wloc, Wsc, bloc, bsc,
                                                 w1h, w2h, whh, bcomb);
    // launch 2: fused feature transpose (fp32 -> fp16 channel-last)
    ftrans_all<<<FT_NB2 + FT_NB3 + FT_NB4 + FT_NB5, dim3(32, 8)>>>(f2, f3, f4, f5,
                                                                   ft2, ft3, ft4, ft5);
    // launch 3: ROI align (fp16 out)
    roi_align3<<<NROIS, 128, DFEAT * 4>>>(ft2, ft3, ft4, ft5, rois, xh);

    // launch 4 (profiled): big GEMM
    gemm_mma<<<dim3(8, 16), 256, GEMM_SMEM>>>(xh, w1h, b1, DFEAT, 1024, 0,
                                              f1h, nullptr, nullptr, 1024);
    // launch 5
    gemm_mma<<<dim3(8, 16), 256, GEMM_SMEM>>>(f1h, w2h, b2, 1024, 1024, 0,
                                              f2h_, nullptr, nullptr, 1024);
    // launch 6: heads
    gemm_mma<<<dim3(8, 7), 256, GEMM_SMEM>>>(f2h_, whh, bcomb, 1024, 512, 1,
                                             nullptr, out_loc, out_sc, 0);
}